// round 6
// baseline (speedup 1.0000x reference)
#include <cuda_runtime.h>
#include <cuda_bf16.h>
#include <math.h>
#include <stdint.h>

typedef __nv_bfloat16 bf16;

// ---------------- problem constants ----------------
#define L_   6
#define D_   768
#define NH_  12
#define DH_  64
#define T_   512
#define B_   16
#define BT_  (B_ * T_)       // 8192
#define D3_  (3 * D_)        // 2304
#define D4_  (4 * D_)        // 3072

// ---------------- scratch (static device globals; no allocs allowed) ----------------
__device__ __align__(128) float g_x  [BT_ * D_];
__device__ __align__(128) float g_xn [BT_ * D_];
__device__ __align__(128) float g_qkv[BT_ * D3_];
__device__ __align__(128) bf16  g_xh [BT_ * D_];
__device__ __align__(128) bf16  g_xl [BT_ * D_];
__device__ __align__(128) bf16  g_yh [BT_ * D_];
__device__ __align__(128) bf16  g_yl [BT_ * D_];
__device__ __align__(128) bf16  g_hh [BT_ * D4_];
__device__ __align__(128) bf16  g_hl [BT_ * D4_];
__device__ __align__(128) float g_dm [B_ * D_];
__device__ char  g_mask[B_ * T_];
__device__ int   g_lastidx[B_];

// transposed+split weights: [N, K] bf16 hi/lo
__device__ __align__(128) bf16 g_qkvT_h[L_ * D3_ * D_];
__device__ __align__(128) bf16 g_qkvT_l[L_ * D3_ * D_];
__device__ __align__(128) bf16 g_projT_h[L_ * D_ * D_];
__device__ __align__(128) bf16 g_projT_l[L_ * D_ * D_];
__device__ __align__(128) bf16 g_fc1T_h[L_ * D4_ * D_];
__device__ __align__(128) bf16 g_fc1T_l[L_ * D4_ * D_];
__device__ __align__(128) bf16 g_fc2T_h[L_ * D_ * D4_];
__device__ __align__(128) bf16 g_fc2T_l[L_ * D_ * D4_];

// ---------------- PTX helpers ----------------
__device__ __forceinline__ uint32_t smem_u32(const void* p) {
    uint32_t a;
    asm("{ .reg .u64 t; cvta.to.shared.u64 t, %1; cvt.u32.u64 %0, t; }" : "=r"(a) : "l"(p));
    return a;
}
__device__ __forceinline__ void cp16(uint32_t s, const void* g) {
    asm volatile("cp.async.cg.shared.global [%0], [%1], 16;" :: "r"(s), "l"(g) : "memory");
}
__device__ __forceinline__ void ldsm4(uint32_t* r, uint32_t addr) {
    asm volatile("ldmatrix.sync.aligned.m8n8.x4.shared.b16 {%0,%1,%2,%3}, [%4];"
                 : "=r"(r[0]), "=r"(r[1]), "=r"(r[2]), "=r"(r[3]) : "r"(addr));
}
__device__ __forceinline__ void mma16816(float* c, const uint32_t* a, const uint32_t* b) {
    asm volatile(
        "mma.sync.aligned.m16n8k16.row.col.f32.bf16.bf16.f32 "
        "{%0,%1,%2,%3}, {%4,%5,%6,%7}, {%8,%9}, {%0,%1,%2,%3};"
        : "+f"(c[0]), "+f"(c[1]), "+f"(c[2]), "+f"(c[3])
        : "r"(a[0]), "r"(a[1]), "r"(a[2]), "r"(a[3]), "r"(b[0]), "r"(b[1]));
}
__device__ __forceinline__ float gelu_exact(float v) {
    return 0.5f * v * (1.0f + erff(v * 0.70710678118654752440f));
}
__device__ __forceinline__ void split_bf16(float v, bf16& h, bf16& l) {
    h = __float2bfloat16(v);
    l = __float2bfloat16(v - __bfloat162float(h));
}

// ---------------- mask + last_idx ----------------
__global__ void mask_kernel(const int* __restrict__ cards,
                            char* __restrict__ mask, int* __restrict__ lastidx) {
    int b = blockIdx.x;
    int t = threadIdx.x;
    bool valid = cards[b * T_ + t] != 0;
    bool any = __syncthreads_or(valid);
    bool m = valid || (t == 0 && !any);
    mask[b * T_ + t] = m ? 1 : 0;
    int cnt = __syncthreads_count(m);
    if (t == 0) lastidx[b] = (cnt - 1) > 0 ? (cnt - 1) : 0;
}

// ---------------- deck means ----------------
__global__ void deckmean_kernel(const int* __restrict__ deck, const int* __restrict__ opp,
                                const float* __restrict__ tok, float* __restrict__ dm) {
    int b = blockIdx.x;
    int d = threadIdx.x;
    float s = 0.f;
    #pragma unroll
    for (int i = 0; i < 8; i++) {
        s += tok[(size_t)deck[b * 8 + i] * D_ + d];
        s += tok[(size_t)opp [b * 8 + i] * D_ + d];
    }
    dm[b * D_ + d] = s * 0.125f;
}

// ---------------- embedding sum ----------------
__global__ void embed_kernel(const int* __restrict__ cards, const int* __restrict__ players,
                             const float* __restrict__ tok, const float* __restrict__ pemb,
                             const float* __restrict__ pos, const float* __restrict__ dm,
                             float* __restrict__ x) {
    int bt = blockIdx.x;
    int b = bt >> 9;
    int t = bt & 511;
    int card = cards[bt];
    int pl = players[bt]; pl = pl < 0 ? 0 : (pl > 1 ? 1 : pl);
    const float* tr = tok  + (size_t)card * D_;
    const float* pr = pemb + (size_t)pl * D_;
    const float* qr = pos  + (size_t)t * D_;
    const float* mr = dm   + (size_t)b * D_;
    float* xr = x + (size_t)bt * D_;
    for (int d = threadIdx.x; d < D_; d += 256)
        xr[d] = tr[d] + pr[d] + mr[d] + qr[d];
}

// ---------------- layernorm -> bf16 hi/lo (or fp32 for final) ----------------
template<bool TOBF>
__global__ void ln_kernel(const float* __restrict__ x, const float* __restrict__ g,
                          const float* __restrict__ be, float* __restrict__ of,
                          bf16* __restrict__ oh, bf16* __restrict__ ol) {
    __shared__ float sh1[8], sh2[8];
    int r = blockIdx.x;
    size_t base = (size_t)r * D_;
    int t = threadIdx.x;
    float v0 = x[base + t], v1 = x[base + t + 256], v2 = x[base + t + 512];
    float s = v0 + v1 + v2;
    float q = v0 * v0 + v1 * v1 + v2 * v2;
    #pragma unroll
    for (int o2 = 16; o2; o2 >>= 1) {
        s += __shfl_xor_sync(0xffffffffu, s, o2);
        q += __shfl_xor_sync(0xffffffffu, q, o2);
    }
    if ((t & 31) == 0) { sh1[t >> 5] = s; sh2[t >> 5] = q; }
    __syncthreads();
    s = sh1[t & 7]; q = sh2[t & 7];
    #pragma unroll
    for (int o2 = 4; o2; o2 >>= 1) {
        s += __shfl_xor_sync(0xffffffffu, s, o2);
        q += __shfl_xor_sync(0xffffffffu, q, o2);
    }
    float mean = s * (1.0f / D_);
    float var  = q * (1.0f / D_) - mean * mean;
    float rstd = rsqrtf(var + 1e-5f);
    #pragma unroll
    for (int u = 0; u < 3; u++) {
        int d = t + u * 256;
        float v = (u == 0 ? v0 : (u == 1 ? v1 : v2));
        float o = (v - mean) * rstd * g[d] + be[d];
        if (TOBF) {
            bf16 hi, lo; split_bf16(o, hi, lo);
            oh[base + d] = hi; ol[base + d] = lo;
        } else {
            of[base + d] = o;
        }
    }
}

// ---------------- fused weight transpose + bf16 split (single launch) --------------
// tiles per layer: qkv 24x72=1728, proj 24x24=576, fc1 24x96=2304, fc2 96x24=2304
#define TQKV (L_ * 1728)                 // 10368
#define TPROJ (TQKV + L_ * 576)          // 13824
#define TFC1 (TPROJ + L_ * 2304)         // 27648
#define TFC2 (TFC1 + L_ * 2304)          // 41472

__global__ void transpose_all(const float* __restrict__ qkvw, const float* __restrict__ projw,
                              const float* __restrict__ fc1w, const float* __restrict__ fc2w,
                              bf16* __restrict__ qTh, bf16* __restrict__ qTl,
                              bf16* __restrict__ pTh, bf16* __restrict__ pTl,
                              bf16* __restrict__ f1Th, bf16* __restrict__ f1Tl,
                              bf16* __restrict__ f2Th, bf16* __restrict__ f2Tl) {
    __shared__ float tile[32][33];
    int idx = blockIdx.x;
    const float* W; bf16 *Th, *Tl; int K, N, rem;
    if (idx < TQKV) {
        int layer = idx / 1728; rem = idx % 1728;
        K = D_; N = D3_;
        W = qkvw + (size_t)layer * D_ * D3_;
        Th = qTh + (size_t)layer * D3_ * D_; Tl = qTl + (size_t)layer * D3_ * D_;
    } else if (idx < TPROJ) {
        idx -= TQKV;
        int layer = idx / 576; rem = idx % 576;
        K = D_; N = D_;
        W = projw + (size_t)layer * D_ * D_;
        Th = pTh + (size_t)layer * D_ * D_; Tl = pTl + (size_t)layer * D_ * D_;
    } else if (idx < TFC1) {
        idx -= TPROJ;
        int layer = idx / 2304; rem = idx % 2304;
        K = D_; N = D4_;
        W = fc1w + (size_t)layer * D_ * D4_;
        Th = f1Th + (size_t)layer * D4_ * D_; Tl = f1Tl + (size_t)layer * D4_ * D_;
    } else {
        idx -= TFC1;
        int layer = idx / 2304; rem = idx % 2304;
        K = D4_; N = D_;
        W = fc2w + (size_t)layer * D4_ * D_;
        Th = f2Th + (size_t)layer * D_ * D4_; Tl = f2Tl + (size_t)layer * D_ * D4_;
    }
    int tilesN = N >> 5;
    int n0 = (rem % tilesN) << 5;
    int k0 = (rem / tilesN) << 5;
    int tx = threadIdx.x, ty = threadIdx.y;   // 32x8
    #pragma unroll
    for (int i = 0; i < 32; i += 8)
        tile[ty + i][tx] = W[(size_t)(k0 + ty + i) * N + n0 + tx];
    __syncthreads();
    #pragma unroll
    for (int i = 0; i < 32; i += 8) {
        float v = tile[tx][ty + i];
        bf16 h, l; split_bf16(v, h, l);
        size_t o = (size_t)(n0 + ty + i) * K + k0 + tx;
        Th[o] = h; Tl[o] = l;
    }
}

// ---------------- mma.sync bf16x3 GEMM, 128x256 tiles (R3 config) ----------------
#define ROWB 80
#define A_HI_OFF 0
#define A_LO_OFF (128 * ROWB)              // 10240
#define B_HI_OFF (2 * 128 * ROWB)          // 20480
#define B_LO_OFF (B_HI_OFF + 256 * ROWB)   // 40960
#define STAGE_BYTES (B_LO_OFF + 256 * ROWB) // 61440
#define GEMM_SMEM (2 * STAGE_BYTES)         // 122880

template<int EPI>
__global__ __launch_bounds__(256, 1)
void gemm_mma(const bf16* __restrict__ Ah, const bf16* __restrict__ Al,
              const bf16* __restrict__ Bh, const bf16* __restrict__ Bl,
              const float* __restrict__ bias, const float* __restrict__ res,
              float* __restrict__ outf, bf16* __restrict__ outh, bf16* __restrict__ outl,
              int K, int Nfull) {
    extern __shared__ char dsm[];
    uint32_t tiles = smem_u32(dsm);

    int tid = threadIdx.x;
    int wid = tid >> 5;
    int lane = tid & 31;
    int warp_m = wid & 1;        // 2 warps in M (64 rows each)
    int warp_n = wid >> 1;       // 4 warps in N (64 cols each)
    int m0 = blockIdx.y * 128;
    int n0 = blockIdx.x * 256;
    int nt = K >> 5;

    int aRow  = lane & 15;
    int aColB = (lane >> 4) << 4;
    int bRow  = (lane & 7) + ((lane & 16) >> 1);
    int bColB = (lane & 8) << 1;

    float acc[4][8][4];
    #pragma unroll
    for (int mt = 0; mt < 4; mt++)
        #pragma unroll
        for (int ntl = 0; ntl < 8; ntl++)
            #pragma unroll
            for (int r = 0; r < 4; r++) acc[mt][ntl][r] = 0.f;

    auto load_stage = [&](int kt, int st) {
        uint32_t sb = tiles + st * STAGE_BYTES;
        int k0 = kt << 5;
        #pragma unroll
        for (int i = 0; i < 2; i++) {                    // A: 128 rows x 4 chunks
            int id = tid + (i << 8);
            int r = id >> 2, c = id & 3;
            size_t go = (size_t)(m0 + r) * K + k0 + (c << 3);
            uint32_t so = r * ROWB + (c << 4);
            cp16(sb + A_HI_OFF + so, Ah + go);
            cp16(sb + A_LO_OFF + so, Al + go);
        }
        #pragma unroll
        for (int i = 0; i < 4; i++) {                    // B: 256 rows x 4 chunks
            int id = tid + (i << 8);
            int r = id >> 2, c = id & 3;
            size_t go = (size_t)(n0 + r) * K + k0 + (c << 3);
            uint32_t so = r * ROWB + (c << 4);
            cp16(sb + B_HI_OFF + so, Bh + go);
            cp16(sb + B_LO_OFF + so, Bl + go);
        }
        asm volatile("cp.async.commit_group;" ::: "memory");
    };

    load_stage(0, 0);

    uint32_t aFrag[16], bH[16], bL[16];

    for (int kt = 0; kt < nt; kt++) {
        int cur = kt & 1;
        if (kt + 1 < nt) {
            load_stage(kt + 1, cur ^ 1);
            asm volatile("cp.async.wait_group 1;" ::: "memory");
        } else {
            asm volatile("cp.async.wait_group 0;" ::: "memory");
        }
        __syncthreads();

        uint32_t sb = tiles + cur * STAGE_BYTES;
        uint32_t aBase = sb + (warp_m * 64 + aRow) * ROWB + aColB;
        uint32_t bBase = sb + B_HI_OFF + (warp_n * 64 + bRow) * ROWB + bColB;

        #pragma unroll
        for (int ks = 0; ks < 2; ks++) {
            uint32_t kb = ks << 5;
            #pragma unroll
            for (int mt = 0; mt < 4; mt++)
                ldsm4(&aFrag[4 * mt], aBase + A_HI_OFF + mt * (16 * ROWB) + kb);
            #pragma unroll
            for (int p = 0; p < 4; p++) {
                ldsm4(&bH[4 * p], bBase + p * (16 * ROWB) + kb);
                ldsm4(&bL[4 * p], bBase + (B_LO_OFF - B_HI_OFF) + p * (16 * ROWB) + kb);
            }
            #pragma unroll
            for (int mt = 0; mt < 4; mt++)
                #pragma unroll
                for (int ntl = 0; ntl < 8; ntl++) {
                    mma16816(acc[mt][ntl], &aFrag[4 * mt], &bH[2 * ntl]);
                    mma16816(acc[mt][ntl], &aFrag[4 * mt], &bL[2 * ntl]);
                }
            #pragma unroll
            for (int mt = 0; mt < 4; mt++)
                ldsm4(&aFrag[4 * mt], aBase + A_LO_OFF + mt * (16 * ROWB) + kb);
            #pragma unroll
            for (int mt = 0; mt < 4; mt++)
                #pragma unroll
                for (int ntl = 0; ntl < 8; ntl++)
                    mma16816(acc[mt][ntl], &aFrag[4 * mt], &bH[2 * ntl]);
        }
        __syncthreads();
    }

    int m_base = m0 + warp_m * 64 + (lane >> 2);
    int n_base = n0 + warp_n * 64 + ((lane & 3) << 1);
    #pragma unroll
    for (int mt = 0; mt < 4; mt++) {
        #pragma unroll
        for (int ntl = 0; ntl < 8; ntl++) {
            int n = n_base + ntl * 8;
            float b0 = bias[n], b1 = bias[n + 1];
            #pragma unroll
            for (int rr = 0; rr < 2; rr++) {
                int m = m_base + mt * 16 + rr * 8;
                size_t ob = (size_t)m * Nfull + n;
                float v0 = acc[mt][ntl][2 * rr]     + b0;
                float v1 = acc[mt][ntl][2 * rr + 1] + b1;
                if (EPI == 0) {
                    *(float2*)(outf + ob) = make_float2(v0, v1);
                } else if (EPI == 2) {
                    float2 rv = *(const float2*)(res + ob);
                    *(float2*)(outf + ob) = make_float2(v0 + rv.x, v1 + rv.y);
                } else {
                    float g0 = gelu_exact(v0), g1 = gelu_exact(v1);
                    bf16 h0, l0, h1, l1;
                    split_bf16(g0, h0, l0); split_bf16(g1, h1, l1);
                    __nv_bfloat162 ph; ph.x = h0; ph.y = h1;
                    __nv_bfloat162 pl; pl.x = l0; pl.y = l1;
                    *(__nv_bfloat162*)(outh + ob) = ph;
                    *(__nv_bfloat162*)(outl + ob) = pl;
                }
            }
        }
    }
}

// ---------------- flash attention (fp32), 64 q x 64 k tiles, dynamic smem ----------
#define APAD 68
#define AQ_OFF 0
#define AK_OFF (64 * APAD * 4)                 // 17408
#define AV_OFF (2 * 64 * APAD * 4)             // 34816
#define AP_OFF (3 * 64 * APAD * 4)             // 52224
#define AM_OFF (4 * 64 * APAD * 4)             // 69632
#define ATTN_SMEM (AM_OFF + 64)

__global__ __launch_bounds__(256)
void attn_kernel(const float* __restrict__ qkv, const char* __restrict__ mask,
                 bf16* __restrict__ outh, bf16* __restrict__ outl) {
    extern __shared__ char asm_[];
    float* Qs  = (float*)(asm_ + AQ_OFF);      // [64][APAD]
    float* Kst = (float*)(asm_ + AK_OFF);      // [k][j]  [64][APAD]
    float* Vs  = (float*)(asm_ + AV_OFF);      // [j][d]  [64][APAD]
    float* Ps  = (float*)(asm_ + AP_OFF);      // [i][j]  [64][APAD]
    char*  Ms  = (char*)(asm_ + AM_OFF);

    int qt = blockIdx.x, h = blockIdx.y, b = blockIdx.z;
    int tid = threadIdx.x;
    int i  = tid >> 2;            // query row
    int jq = tid & 3;
    int c0 = jq * 16;
    int gq = qt * 64 + i;
    const float scale = 0.125f;

    // load Q tile (row = tid>>2, 16 floats)
    {
        int row = tid >> 2;
        int cc  = (tid & 3) * 16;
        const float* g = qkv + ((size_t)(b * T_ + qt * 64 + row)) * D3_ + h * DH_ + cc;
        #pragma unroll
        for (int u = 0; u < 4; u++)
            *(float4*)&Qs[row * APAD + cc + u * 4] = *(const float4*)(g + u * 4);
    }

    float O[16];
    #pragma unroll
    for (int cc = 0; cc < 16; cc++) O[cc] = 0.f;
    float m_prev = -INFINITY, l = 0.f;

    int ktmax = qt + 1;
    for (int kt = 0; kt < ktmax; kt++) {
        __syncthreads();
        {
            int j  = tid >> 2;               // 0..63
            int d0 = (tid & 3) * 16;         // 0..48
            const float* gk = qkv + ((size_t)(b * T_ + kt * 64 + j)) * D3_ + D_     + h * DH_ + d0;
            const float* gv = qkv + ((size_t)(b * T_ + kt * 64 + j)) * D3_ + 2 * D_ + h * DH_ + d0;
            #pragma unroll
            for (int u4 = 0; u4 < 4; u4++) {
                float4 kv = *(const float4*)(gk + u4 * 4);
                Kst[(d0 + u4 * 4 + 0) * APAD + j] = kv.x;
                Kst[(d0 + u4 * 4 + 1) * APAD + j] = kv.y;
                Kst[(d0 + u4 * 4 + 2) * APAD + j] = kv.z;
                Kst[(d0 + u4 * 4 + 3) * APAD + j] = kv.w;
                *(float4*)&Vs[j * APAD + d0 + u4 * 4] = *(const float4*)(gv + u4 * 4);
            }
            if (tid < 64) Ms[tid] = mask[b * T_ + kt * 64 + tid];
        }
        __syncthreads();

        // S = Q K^T for 16 keys per thread
        float s[16];
        #pragma unroll
        for (int jj = 0; jj < 16; jj++) s[jj] = 0.f;
        #pragma unroll 16
        for (int k = 0; k < 64; k++) {
            float qv = Qs[i * APAD + k];
            const float* kr = &Kst[k * APAD + c0];
            float4 ka = *(const float4*)(kr);
            float4 kb = *(const float4*)(kr + 4);
            float4 kc = *(const float4*)(kr + 8);
            float4 kd = *(const float4*)(kr + 12);
            s[0]  += qv * ka.x; s[1]  += qv * ka.y; s[2]  += qv * ka.z; s[3]  += qv * ka.w;
            s[4]  += qv * kb.x; s[5]  += qv * kb.y; s[6]  += qv * kb.z; s[7]  += qv * kb.w;
            s[8]  += qv * kc.x; s[9]  += qv * kc.y; s[10] += qv * kc.z; s[11] += qv * kc.w;
            s[12] += qv * kd.x; s[13] += qv * kd.y; s[14] += qv * kd.z; s[15] += qv * kd.w;
        }
        // mask + scale
        float mt = -INFINITY;
        #pragma unroll
        for (int jj = 0; jj < 16; jj++) {
            int gk = kt * 64 + c0 + jj;
            bool ok = (gk <= gq) && (Ms[c0 + jj] != 0);
            s[jj] = ok ? s[jj] * scale : -INFINITY;
            mt = fmaxf(mt, s[jj]);
        }
        mt = fmaxf(mt, __shfl_xor_sync(0xffffffffu, mt, 1));
        mt = fmaxf(mt, __shfl_xor_sync(0xffffffffu, mt, 2));
        float m_new = fmaxf(m_prev, mt);
        float alpha, psum = 0.f;
        float p[16];
        if (m_new == -INFINITY) {
            alpha = 1.0f;
            #pragma unroll
            for (int jj = 0; jj < 16; jj++) p[jj] = 0.f;
        } else {
            alpha = expf(m_prev - m_new);
            #pragma unroll
            for (int jj = 0; jj < 16; jj++) {
                p[jj] = expf(s[jj] - m_new);
                psum += p[jj];
            }
        }
        psum += __shfl_xor_sync(0xffffffffu, psum, 1);
        psum += __shfl_xor_sync(0xffffffffu, psum, 2);
        l = l * alpha + psum;
        m_prev = m_new;
        #pragma unroll
        for (int cc = 0; cc < 16; cc++) O[cc] *= alpha;
        #pragma unroll
        for (int jj = 0; jj < 16; jj++) Ps[i * APAD + c0 + jj] = p[jj];
        __syncthreads();

        // O += P @ V
        #pragma unroll 8
        for (int j = 0; j < 64; j++) {
            float pv = Ps[i * APAD + j];
            const float* vr = &Vs[j * APAD + c0];
            float4 v0 = *(const float4*)(vr);
            float4 v1 = *(const float4*)(vr + 4);
            float4 v2 = *(const float4*)(vr + 8);
            float4 v3 = *(const float4*)(vr + 12);
            O[0]  += pv * v0.x; O[1]  += pv * v0.y; O[2]  += pv * v0.z; O[3]  += pv * v0.w;
            O[4]  += pv * v1.x; O[5]  += pv * v1.y; O[6]  += pv * v1.z; O[7]  += pv * v1.w;
            O[8]  += pv * v2.x; O[9]  += pv * v2.y; O[10] += pv * v2.z; O[11] += pv * v2.w;
            O[12] += pv * v3.x; O[13] += pv * v3.y; O[14] += pv * v3.z; O[15] += pv * v3.w;
        }
    }

    float rl = (l > 0.f) ? (1.0f / l) : 0.f;
    size_t ob = ((size_t)(b * T_ + qt * 64 + i)) * D_ + h * DH_ + c0;
    #pragma unroll
    for (int cc = 0; cc < 16; cc++) {
        float v = O[cc] * rl;
        bf16 hi, lo; split_bf16(v, hi, lo);
        outh[ob + cc] = hi; outl[ob + cc] = lo;
    }
}

// ---------------- head ----------------
__global__ void head_kernel(const float* __restrict__ xn, const int* __restrict__ lastidx,
                            const float* __restrict__ hw, const float* __restrict__ hb,
                            float* __restrict__ out) {
    int b = blockIdx.x;
    int w = threadIdx.x >> 5;
    int lane = threadIdx.x & 31;
    const float* h = xn + ((size_t)(b * T_ + lastidx[b])) * D_;
    float s = 0.f;
    for (int d = lane; d < D_; d += 32) s += h[d] * hw[d * 9 + w];
    #pragma unroll
    for (int o = 16; o; o >>= 1) s += __shfl_down_sync(0xffffffffu, s, o);
    if (lane == 0) out[b * 9 + w] = s + hb[w];
}

// ---------------- orchestration ----------------
extern "C" void kernel_launch(void* const* d_in, const int* in_sizes, int n_in,
                              void* d_out, int out_size) {
    const int*   cards   = (const int*)  d_in[0];
    const int*   players = (const int*)  d_in[1];
    const int*   deck    = (const int*)  d_in[2];
    const int*   opp     = (const int*)  d_in[3];
    const float* tok     = (const float*)d_in[4];
    const float* pemb    = (const float*)d_in[5];
    const float* pos     = (const float*)d_in[6];
    const float* ln1s = (const float*)d_in[9];
    const float* ln1b = (const float*)d_in[10];
    const float* qkvw = (const float*)d_in[11];
    const float* qkvb = (const float*)d_in[12];
    const float* projw = (const float*)d_in[13];
    const float* projb = (const float*)d_in[14];
    const float* ln2s = (const float*)d_in[15];
    const float* ln2b = (const float*)d_in[16];
    const float* fc1w = (const float*)d_in[17];
    const float* fc1b = (const float*)d_in[18];
    const float* fc2w = (const float*)d_in[19];
    const float* fc2b = (const float*)d_in[20];
    const float* lnfs = (const float*)d_in[21];
    const float* lnfb = (const float*)d_in[22];
    const float* headw = (const float*)d_in[23];
    const float* headb = (const float*)d_in[24];

    float *x, *xn, *qkv, *dm;
    bf16 *xh, *xl, *yh, *yl, *hh, *hl;
    bf16 *qT_h, *qT_l, *pT_h, *pT_l, *f1T_h, *f1T_l, *f2T_h, *f2T_l;
    char* mask; int* lastidx;
    cudaGetSymbolAddress((void**)&x,    g_x);
    cudaGetSymbolAddress((void**)&xn,   g_xn);
    cudaGetSymbolAddress((void**)&qkv,  g_qkv);
    cudaGetSymbolAddress((void**)&dm,   g_dm);
    cudaGetSymbolAddress((void**)&xh,   g_xh);
    cudaGetSymbolAddress((void**)&xl,   g_xl);
    cudaGetSymbolAddress((void**)&yh,   g_yh);
    cudaGetSymbolAddress((void**)&yl,   g_yl);
    cudaGetSymbolAddress((void**)&hh,   g_hh);
    cudaGetSymbolAddress((void**)&hl,   g_hl);
    cudaGetSymbolAddress((void**)&qT_h, g_qkvT_h);
    cudaGetSymbolAddress((void**)&qT_l, g_qkvT_l);
    cudaGetSymbolAddress((void**)&pT_h, g_projT_h);
    cudaGetSymbolAddress((void**)&pT_l, g_projT_l);
    cudaGetSymbolAddress((void**)&f1T_h, g_fc1T_h);
    cudaGetSymbolAddress((void**)&f1T_l, g_fc1T_l);
    cudaGetSymbolAddress((void**)&f2T_h, g_fc2T_h);
    cudaGetSymbolAddress((void**)&f2T_l, g_fc2T_l);
    cudaGetSymbolAddress((void**)&mask, g_mask);
    cudaGetSymbolAddress((void**)&lastidx, g_lastidx);

    cudaFuncSetAttribute(gemm_mma<0>, cudaFuncAttributeMaxDynamicSharedMemorySize, GEMM_SMEM);
    cudaFuncSetAttribute(gemm_mma<1>, cudaFuncAttributeMaxDynamicSharedMemorySize, GEMM_SMEM);
    cudaFuncSetAttribute(gemm_mma<2>, cudaFuncAttributeMaxDynamicSharedMemorySize, GEMM_SMEM);
    cudaFuncSetAttribute(attn_kernel, cudaFuncAttributeMaxDynamicSharedMemorySize, ATTN_SMEM);

    mask_kernel<<<B_, T_>>>(cards, mask, lastidx);
    deckmean_kernel<<<B_, D_>>>(deck, opp, tok, dm);
    embed_kernel<<<BT_, 256>>>(cards, players, tok, pemb, pos, dm, x);

    dim3 tb(32, 8);
    transpose_all<<<TFC2, tb>>>(qkvw, projw, fc1w, fc2w,
                                qT_h, qT_l, pT_h, pT_l, f1T_h, f1T_l, f2T_h, f2T_l);

    for (int i = 0; i < L_; i++) {
        ln_kernel<true><<<BT_, 256>>>(x, ln1s + i * D_, ln1b + i * D_, nullptr, xh, xl);
        gemm_mma<0><<<dim3(D3_ / 256, BT_ / 128), 256, GEMM_SMEM>>>(
            xh, xl, qT_h + (size_t)i * D3_ * D_, qT_l + (size_t)i * D3_ * D_,
            qkvb + i * D3_, nullptr, qkv, nullptr, nullptr, D_, D3_);
        attn_kernel<<<dim3(T_ / 64, NH_, B_), 256, ATTN_SMEM>>>(qkv, mask, yh, yl);
        gemm_mma<2><<<dim3(D_ / 256, BT_ / 128), 256, GEMM_SMEM>>>(
            yh, yl, pT_h + (size_t)i * D_ * D_, pT_l + (size_t)i * D_ * D_,
            projb + i * D_, x, x, nullptr, nullptr, D_, D_);
        ln_kernel<true><<<BT_, 256>>>(x, ln2s + i * D_, ln2b + i * D_, nullptr, xh, xl);
        gemm_mma<1><<<dim3(D4_ / 256, BT_ / 128), 256, GEMM_SMEM>>>(
            xh, xl, f1T_h + (size_t)i * D4_ * D_, f1T_l + (size_t)i * D4_ * D_,
            fc1b + i * D4_, nullptr, nullptr, hh, hl, D_, D4_);
        gemm_mma<2><<<dim3(D_ / 256, BT_ / 128), 256, GEMM_SMEM>>>(
            hh, hl, f2T_h + (size_t)i * D_ * D4_, f2T_l + (size_t)i * D_ * D4_,
            fc2b + i * D_, x, x, nullptr, nullptr, D4_, D_);
    }

    ln_kernel<false><<<BT_, 256>>>(x, lnfs, lnfb, xn, nullptr, nullptr);
    head_kernel<<<B_, 288>>>(xn, lastidx, headw, headb, (float*)d_out);
}

// round 7
// speedup vs baseline: 1.0714x; 1.0714x over previous
#include <cuda_runtime.h>
#include <cuda_bf16.h>
#include <math.h>
#include <stdint.h>

typedef __nv_bfloat16 bf16;

// ---------------- problem constants ----------------
#define L_   6
#define D_   768
#define NH_  12
#define DH_  64
#define T_   512
#define B_   16
#define BT_  (B_ * T_)       // 8192
#define D3_  (3 * D_)        // 2304
#define D4_  (4 * D_)        // 3072

// ---------------- scratch (static device globals; no allocs allowed) ----------------
__device__ __align__(128) float g_x  [BT_ * D_];
__device__ __align__(128) float g_xn [BT_ * D_];
__device__ __align__(128) float g_qkv[BT_ * D3_];
__device__ __align__(128) bf16  g_xh [BT_ * D_];
__device__ __align__(128) bf16  g_xl [BT_ * D_];
__device__ __align__(128) bf16  g_yh [BT_ * D_];
__device__ __align__(128) bf16  g_yl [BT_ * D_];
__device__ __align__(128) bf16  g_hh [BT_ * D4_];
__device__ __align__(128) bf16  g_hl [BT_ * D4_];
__device__ __align__(128) float g_dm [B_ * D_];
__device__ char  g_mask[B_ * T_];
__device__ int   g_lastidx[B_];

// transposed+split weights: [N, K] bf16 hi/lo
__device__ __align__(128) bf16 g_qkvT_h[L_ * D3_ * D_];
__device__ __align__(128) bf16 g_qkvT_l[L_ * D3_ * D_];
__device__ __align__(128) bf16 g_projT_h[L_ * D_ * D_];
__device__ __align__(128) bf16 g_projT_l[L_ * D_ * D_];
__device__ __align__(128) bf16 g_fc1T_h[L_ * D4_ * D_];
__device__ __align__(128) bf16 g_fc1T_l[L_ * D4_ * D_];
__device__ __align__(128) bf16 g_fc2T_h[L_ * D_ * D4_];
__device__ __align__(128) bf16 g_fc2T_l[L_ * D_ * D4_];

// ---------------- PTX helpers ----------------
__device__ __forceinline__ uint32_t smem_u32(const void* p) {
    uint32_t a;
    asm("{ .reg .u64 t; cvta.to.shared.u64 t, %1; cvt.u32.u64 %0, t; }" : "=r"(a) : "l"(p));
    return a;
}
__device__ __forceinline__ void cp16(uint32_t s, const void* g) {
    asm volatile("cp.async.cg.shared.global [%0], [%1], 16;" :: "r"(s), "l"(g) : "memory");
}
__device__ __forceinline__ void ldsm4(uint32_t* r, uint32_t addr) {
    asm volatile("ldmatrix.sync.aligned.m8n8.x4.shared.b16 {%0,%1,%2,%3}, [%4];"
                 : "=r"(r[0]), "=r"(r[1]), "=r"(r[2]), "=r"(r[3]) : "r"(addr));
}
__device__ __forceinline__ void mma16816(float* c, const uint32_t* a, const uint32_t* b) {
    asm volatile(
        "mma.sync.aligned.m16n8k16.row.col.f32.bf16.bf16.f32 "
        "{%0,%1,%2,%3}, {%4,%5,%6,%7}, {%8,%9}, {%0,%1,%2,%3};"
        : "+f"(c[0]), "+f"(c[1]), "+f"(c[2]), "+f"(c[3])
        : "r"(a[0]), "r"(a[1]), "r"(a[2]), "r"(a[3]), "r"(b[0]), "r"(b[1]));
}
__device__ __forceinline__ float gelu_exact(float v) {
    return 0.5f * v * (1.0f + erff(v * 0.70710678118654752440f));
}
__device__ __forceinline__ void split_bf16(float v, bf16& h, bf16& l) {
    h = __float2bfloat16(v);
    l = __float2bfloat16(v - __bfloat162float(h));
}

// ---------------- fused weight transpose + bf16 split (single launch) --------------
#define TQKV (L_ * 1728)                 // 10368
#define TPROJ (TQKV + L_ * 576)          // 13824
#define TFC1 (TPROJ + L_ * 2304)         // 27648
#define TFC2 (TFC1 + L_ * 2304)          // 41472

__global__ void transpose_all(const float* __restrict__ qkvw, const float* __restrict__ projw,
                              const float* __restrict__ fc1w, const float* __restrict__ fc2w,
                              bf16* __restrict__ qTh, bf16* __restrict__ qTl,
                              bf16* __restrict__ pTh, bf16* __restrict__ pTl,
                              bf16* __restrict__ f1Th, bf16* __restrict__ f1Tl,
                              bf16* __restrict__ f2Th, bf16* __restrict__ f2Tl) {
    __shared__ float tile[32][33];
    int idx = blockIdx.x;
    const float* W; bf16 *Th, *Tl; int K, N, rem;
    if (idx < TQKV) {
        int layer = idx / 1728; rem = idx % 1728;
        K = D_; N = D3_;
        W = qkvw + (size_t)layer * D_ * D3_;
        Th = qTh + (size_t)layer * D3_ * D_; Tl = qTl + (size_t)layer * D3_ * D_;
    } else if (idx < TPROJ) {
        idx -= TQKV;
        int layer = idx / 576; rem = idx % 576;
        K = D_; N = D_;
        W = projw + (size_t)layer * D_ * D_;
        Th = pTh + (size_t)layer * D_ * D_; Tl = pTl + (size_t)layer * D_ * D_;
    } else if (idx < TFC1) {
        idx -= TPROJ;
        int layer = idx / 2304; rem = idx % 2304;
        K = D_; N = D4_;
        W = fc1w + (size_t)layer * D_ * D4_;
        Th = f1Th + (size_t)layer * D4_ * D_; Tl = f1Tl + (size_t)layer * D4_ * D_;
    } else {
        idx -= TFC1;
        int layer = idx / 2304; rem = idx % 2304;
        K = D4_; N = D_;
        W = fc2w + (size_t)layer * D4_ * D_;
        Th = f2Th + (size_t)layer * D_ * D4_; Tl = f2Tl + (size_t)layer * D_ * D4_;
    }
    int tilesN = N >> 5;
    int n0 = (rem % tilesN) << 5;
    int k0 = (rem / tilesN) << 5;
    int tx = threadIdx.x, ty = threadIdx.y;   // 32x8
    #pragma unroll
    for (int i = 0; i < 32; i += 8)
        tile[ty + i][tx] = W[(size_t)(k0 + ty + i) * N + n0 + tx];
    __syncthreads();
    #pragma unroll
    for (int i = 0; i < 32; i += 8) {
        float v = tile[tx][ty + i];
        bf16 h, l; split_bf16(v, h, l);
        size_t o = (size_t)(n0 + ty + i) * K + k0 + tx;
        Th[o] = h; Tl[o] = l;
    }
}

// ---------------- mask + last_idx ----------------
__global__ void mask_kernel(const int* __restrict__ cards,
                            char* __restrict__ mask, int* __restrict__ lastidx) {
    int b = blockIdx.x;
    int t = threadIdx.x;
    bool valid = cards[b * T_ + t] != 0;
    bool any = __syncthreads_or(valid);
    bool m = valid || (t == 0 && !any);
    mask[b * T_ + t] = m ? 1 : 0;
    int cnt = __syncthreads_count(m);
    if (t == 0) lastidx[b] = (cnt - 1) > 0 ? (cnt - 1) : 0;
}

// ---------------- deck means ----------------
__global__ void deckmean_kernel(const int* __restrict__ deck, const int* __restrict__ opp,
                                const float* __restrict__ tok, float* __restrict__ dm) {
    int b = blockIdx.x;
    int d = threadIdx.x;
    float s = 0.f;
    #pragma unroll
    for (int i = 0; i < 8; i++) {
        s += tok[(size_t)deck[b * 8 + i] * D_ + d];
        s += tok[(size_t)opp [b * 8 + i] * D_ + d];
    }
    dm[b * D_ + d] = s * 0.125f;
}

// ---------------- embedding sum ----------------
__global__ void embed_kernel(const int* __restrict__ cards, const int* __restrict__ players,
                             const float* __restrict__ tok, const float* __restrict__ pemb,
                             const float* __restrict__ pos, const float* __restrict__ dm,
                             float* __restrict__ x) {
    int bt = blockIdx.x;
    int b = bt >> 9;
    int t = bt & 511;
    int card = cards[bt];
    int pl = players[bt]; pl = pl < 0 ? 0 : (pl > 1 ? 1 : pl);
    const float* tr = tok  + (size_t)card * D_;
    const float* pr = pemb + (size_t)pl * D_;
    const float* qr = pos  + (size_t)t * D_;
    const float* mr = dm   + (size_t)b * D_;
    float* xr = x + (size_t)bt * D_;
    for (int d = threadIdx.x; d < D_; d += 256)
        xr[d] = tr[d] + pr[d] + mr[d] + qr[d];
}

// ---------------- layernorm -> bf16 hi/lo (or fp32 for final) ----------------
template<bool TOBF>
__global__ void ln_kernel(const float* __restrict__ x, const float* __restrict__ g,
                          const float* __restrict__ be, float* __restrict__ of,
                          bf16* __restrict__ oh, bf16* __restrict__ ol) {
    __shared__ float sh1[8], sh2[8];
    int r = blockIdx.x;
    size_t base = (size_t)r * D_;
    int t = threadIdx.x;
    float v0 = x[base + t], v1 = x[base + t + 256], v2 = x[base + t + 512];
    float s = v0 + v1 + v2;
    float q = v0 * v0 + v1 * v1 + v2 * v2;
    #pragma unroll
    for (int o2 = 16; o2; o2 >>= 1) {
        s += __shfl_xor_sync(0xffffffffu, s, o2);
        q += __shfl_xor_sync(0xffffffffu, q, o2);
    }
    if ((t & 31) == 0) { sh1[t >> 5] = s; sh2[t >> 5] = q; }
    __syncthreads();
    s = sh1[t & 7]; q = sh2[t & 7];
    #pragma unroll
    for (int o2 = 4; o2; o2 >>= 1) {
        s += __shfl_xor_sync(0xffffffffu, s, o2);
        q += __shfl_xor_sync(0xffffffffu, q, o2);
    }
    float mean = s * (1.0f / D_);
    float var  = q * (1.0f / D_) - mean * mean;
    float rstd = rsqrtf(var + 1e-5f);
    #pragma unroll
    for (int u = 0; u < 3; u++) {
        int d = t + u * 256;
        float v = (u == 0 ? v0 : (u == 1 ? v1 : v2));
        float o = (v - mean) * rstd * g[d] + be[d];
        if (TOBF) {
            bf16 hi, lo; split_bf16(o, hi, lo);
            oh[base + d] = hi; ol[base + d] = lo;
        } else {
            of[base + d] = o;
        }
    }
}

// ---------------- mma.sync bf16x3 GEMM, 128x256 tiles (R3 config) ----------------
#define ROWB 80
#define A_HI_OFF 0
#define A_LO_OFF (128 * ROWB)              // 10240
#define B_HI_OFF (2 * 128 * ROWB)          // 20480
#define B_LO_OFF (B_HI_OFF + 256 * ROWB)   // 40960
#define STAGE_BYTES (B_LO_OFF + 256 * ROWB) // 61440
#define GEMM_SMEM (2 * STAGE_BYTES)         // 122880

template<int EPI>
__global__ __launch_bounds__(256, 1)
void gemm_mma(const bf16* __restrict__ Ah, const bf16* __restrict__ Al,
              const bf16* __restrict__ Bh, const bf16* __restrict__ Bl,
              const float* __restrict__ bias, const float* __restrict__ res,
              float* __restrict__ outf, bf16* __restrict__ outh, bf16* __restrict__ outl,
              int K, int Nfull) {
    extern __shared__ char dsm[];
    uint32_t tiles = smem_u32(dsm);

    int tid = threadIdx.x;
    int wid = tid >> 5;
    int lane = tid & 31;
    int warp_m = wid & 1;        // 2 warps in M (64 rows each)
    int warp_n = wid >> 1;       // 4 warps in N (64 cols each)
    int m0 = blockIdx.y * 128;
    int n0 = blockIdx.x * 256;
    int nt = K >> 5;

    int aRow  = lane & 15;
    int aColB = (lane >> 4) << 4;
    int bRow  = (lane & 7) + ((lane & 16) >> 1);
    int bColB = (lane & 8) << 1;

    float acc[4][8][4];
    #pragma unroll
    for (int mt = 0; mt < 4; mt++)
        #pragma unroll
        for (int ntl = 0; ntl < 8; ntl++)
            #pragma unroll
            for (int r = 0; r < 4; r++) acc[mt][ntl][r] = 0.f;

    auto load_stage = [&](int kt, int st) {
        uint32_t sb = tiles + st * STAGE_BYTES;
        int k0 = kt << 5;
        #pragma unroll
        for (int i = 0; i < 2; i++) {                    // A: 128 rows x 4 chunks
            int id = tid + (i << 8);
            int r = id >> 2, c = id & 3;
            size_t go = (size_t)(m0 + r) * K + k0 + (c << 3);
            uint32_t so = r * ROWB + (c << 4);
            cp16(sb + A_HI_OFF + so, Ah + go);
            cp16(sb + A_LO_OFF + so, Al + go);
        }
        #pragma unroll
        for (int i = 0; i < 4; i++) {                    // B: 256 rows x 4 chunks
            int id = tid + (i << 8);
            int r = id >> 2, c = id & 3;
            size_t go = (size_t)(n0 + r) * K + k0 + (c << 3);
            uint32_t so = r * ROWB + (c << 4);
            cp16(sb + B_HI_OFF + so, Bh + go);
            cp16(sb + B_LO_OFF + so, Bl + go);
        }
        asm volatile("cp.async.commit_group;" ::: "memory");
    };

    load_stage(0, 0);

    uint32_t aFrag[16], bH[16], bL[16];

    for (int kt = 0; kt < nt; kt++) {
        int cur = kt & 1;
        if (kt + 1 < nt) {
            load_stage(kt + 1, cur ^ 1);
            asm volatile("cp.async.wait_group 1;" ::: "memory");
        } else {
            asm volatile("cp.async.wait_group 0;" ::: "memory");
        }
        __syncthreads();

        uint32_t sb = tiles + cur * STAGE_BYTES;
        uint32_t aBase = sb + (warp_m * 64 + aRow) * ROWB + aColB;
        uint32_t bBase = sb + B_HI_OFF + (warp_n * 64 + bRow) * ROWB + bColB;

        #pragma unroll
        for (int ks = 0; ks < 2; ks++) {
            uint32_t kb = ks << 5;
            #pragma unroll
            for (int mt = 0; mt < 4; mt++)
                ldsm4(&aFrag[4 * mt], aBase + A_HI_OFF + mt * (16 * ROWB) + kb);
            #pragma unroll
            for (int p = 0; p < 4; p++) {
                ldsm4(&bH[4 * p], bBase + p * (16 * ROWB) + kb);
                ldsm4(&bL[4 * p], bBase + (B_LO_OFF - B_HI_OFF) + p * (16 * ROWB) + kb);
            }
            #pragma unroll
            for (int mt = 0; mt < 4; mt++)
                #pragma unroll
                for (int ntl = 0; ntl < 8; ntl++) {
                    mma16816(acc[mt][ntl], &aFrag[4 * mt], &bH[2 * ntl]);
                    mma16816(acc[mt][ntl], &aFrag[4 * mt], &bL[2 * ntl]);
                }
            #pragma unroll
            for (int mt = 0; mt < 4; mt++)
                ldsm4(&aFrag[4 * mt], aBase + A_LO_OFF + mt * (16 * ROWB) + kb);
            #pragma unroll
            for (int mt = 0; mt < 4; mt++)
                #pragma unroll
                for (int ntl = 0; ntl < 8; ntl++)
                    mma16816(acc[mt][ntl], &aFrag[4 * mt], &bH[2 * ntl]);
        }
        __syncthreads();
    }

    int m_base = m0 + warp_m * 64 + (lane >> 2);
    int n_base = n0 + warp_n * 64 + ((lane & 3) << 1);
    #pragma unroll
    for (int mt = 0; mt < 4; mt++) {
        #pragma unroll
        for (int ntl = 0; ntl < 8; ntl++) {
            int n = n_base + ntl * 8;
            float b0 = bias[n], b1 = bias[n + 1];
            #pragma unroll
            for (int rr = 0; rr < 2; rr++) {
                int m = m_base + mt * 16 + rr * 8;
                size_t ob = (size_t)m * Nfull + n;
                float v0 = acc[mt][ntl][2 * rr]     + b0;
                float v1 = acc[mt][ntl][2 * rr + 1] + b1;
                if (EPI == 0) {
                    *(float2*)(outf + ob) = make_float2(v0, v1);
                } else if (EPI == 2) {
                    float2 rv = *(const float2*)(res + ob);
                    *(float2*)(outf + ob) = make_float2(v0 + rv.x, v1 + rv.y);
                } else {
                    float g0 = gelu_exact(v0), g1 = gelu_exact(v1);
                    bf16 h0, l0, h1, l1;
                    split_bf16(g0, h0, l0); split_bf16(g1, h1, l1);
                    __nv_bfloat162 ph; ph.x = h0; ph.y = h1;
                    __nv_bfloat162 pl; pl.x = l0; pl.y = l1;
                    *(__nv_bfloat162*)(outh + ob) = ph;
                    *(__nv_bfloat162*)(outl + ob) = pl;
                }
            }
        }
    }
}

// ---------------- flash attention (fp32), 64 q x 32 k tiles (R3 config) ------------
__global__ __launch_bounds__(256)
void attn_kernel(const float* __restrict__ qkv, const char* __restrict__ mask,
                 bf16* __restrict__ outh, bf16* __restrict__ outl) {
    int qt = blockIdx.x, h = blockIdx.y, b = blockIdx.z;
    __shared__ float Qs[64][64];
    __shared__ float Kst[64][32];
    __shared__ float Vs[32][64];
    __shared__ float Ps[64][32];
    __shared__ char  Ms[32];

    int tid = threadIdx.x;
    int i = tid >> 2;
    int jq = tid & 3;
    int c0 = jq * 16;
    int gq = qt * 64 + i;
    const float scale = 0.125f;

    {
        int idx = tid * 16;
        int row = idx >> 6;
        int cc = idx & 63;
        const float* g = qkv + ((size_t)(b * T_ + qt * 64 + row)) * D3_ + h * DH_ + cc;
        #pragma unroll
        for (int u = 0; u < 4; u++)
            *(float4*)&Qs[row][cc + u * 4] = *(const float4*)(g + u * 4);
    }

    float O[16];
    #pragma unroll
    for (int cc = 0; cc < 16; cc++) O[cc] = 0.f;
    float m_prev = -INFINITY, l = 0.f;

    int ktmax = (qt + 1) * 2;
    for (int kt = 0; kt < ktmax; kt++) {
        __syncthreads();
        {
            int j = tid >> 3;
            int d0 = (tid & 7) * 8;
            const float* gk = qkv + ((size_t)(b * T_ + kt * 32 + j)) * D3_ + D_ + h * DH_ + d0;
            const float* gv = qkv + ((size_t)(b * T_ + kt * 32 + j)) * D3_ + 2 * D_ + h * DH_ + d0;
            float4 k0v = *(const float4*)gk;
            float4 k1v = *(const float4*)(gk + 4);
            Kst[d0 + 0][j] = k0v.x; Kst[d0 + 1][j] = k0v.y;
            Kst[d0 + 2][j] = k0v.z; Kst[d0 + 3][j] = k0v.w;
            Kst[d0 + 4][j] = k1v.x; Kst[d0 + 5][j] = k1v.y;
            Kst[d0 + 6][j] = k1v.z; Kst[d0 + 7][j] = k1v.w;
            *(float4*)&Vs[j][d0]     = *(const float4*)gv;
            *(float4*)&Vs[j][d0 + 4] = *(const float4*)(gv + 4);
            if (tid < 32) Ms[tid] = mask[b * T_ + kt * 32 + tid];
        }
        __syncthreads();

        float s[8];
        #pragma unroll
        for (int jj = 0; jj < 8; jj++) s[jj] = 0.f;
        #pragma unroll
        for (int k = 0; k < 64; k++) {
            float qv = Qs[i][k];
            float4 ka = *(const float4*)&Kst[k][jq * 8];
            float4 kb = *(const float4*)&Kst[k][jq * 8 + 4];
            s[0] += qv * ka.x; s[1] += qv * ka.y; s[2] += qv * ka.z; s[3] += qv * ka.w;
            s[4] += qv * kb.x; s[5] += qv * kb.y; s[6] += qv * kb.z; s[7] += qv * kb.w;
        }
        float mt = -INFINITY;
        #pragma unroll
        for (int jj = 0; jj < 8; jj++) {
            int gk = kt * 32 + jq * 8 + jj;
            bool ok = (gk <= gq) && (Ms[jq * 8 + jj] != 0);
            s[jj] = ok ? s[jj] * scale : -INFINITY;
            mt = fmaxf(mt, s[jj]);
        }
        mt = fmaxf(mt, __shfl_xor_sync(0xffffffffu, mt, 1));
        mt = fmaxf(mt, __shfl_xor_sync(0xffffffffu, mt, 2));
        float m_new = fmaxf(m_prev, mt);
        float alpha, psum = 0.f;
        float p[8];
        if (m_new == -INFINITY) {
            alpha = 1.0f;
            #pragma unroll
            for (int jj = 0; jj < 8; jj++) p[jj] = 0.f;
        } else {
            alpha = expf(m_prev - m_new);
            #pragma unroll
            for (int jj = 0; jj < 8; jj++) {
                p[jj] = expf(s[jj] - m_new);
                psum += p[jj];
            }
        }
        psum += __shfl_xor_sync(0xffffffffu, psum, 1);
        psum += __shfl_xor_sync(0xffffffffu, psum, 2);
        l = l * alpha + psum;
        m_prev = m_new;
        #pragma unroll
        for (int cc = 0; cc < 16; cc++) O[cc] *= alpha;
        #pragma unroll
        for (int jj = 0; jj < 8; jj++) Ps[i][jq * 8 + jj] = p[jj];
        __syncthreads();

        #pragma unroll 8
        for (int j = 0; j < 32; j++) {
            float pv = Ps[i][j];
            float4 v0 = *(const float4*)&Vs[j][c0];
            float4 v1 = *(const float4*)&Vs[j][c0 + 4];
            float4 v2 = *(const float4*)&Vs[j][c0 + 8];
            float4 v3 = *(const float4*)&Vs[j][c0 + 12];
            O[0]  += pv * v0.x; O[1]  += pv * v0.y; O[2]  += pv * v0.z; O[3]  += pv * v0.w;
            O[4]  += pv * v1.x; O[5]  += pv * v1.y; O[6]  += pv * v1.z; O[7]  += pv * v1.w;
            O[8]  += pv * v2.x; O[9]  += pv * v2.y; O[10] += pv * v2.z; O[11] += pv * v2.w;
            O[12] += pv * v3.x; O[13] += pv * v3.y; O[14] += pv * v3.z; O[15] += pv * v3.w;
        }
    }

    float rl = (l > 0.f) ? (1.0f / l) : 0.f;
    size_t ob = ((size_t)(b * T_ + qt * 64 + i)) * D_ + h * DH_ + c0;
    #pragma unroll
    for (int cc = 0; cc < 16; cc++) {
        float v = O[cc] * rl;
        bf16 hi, lo; split_bf16(v, hi, lo);
        outh[ob + cc] = hi; outl[ob + cc] = lo;
    }
}

// ---------------- head ----------------
__global__ void head_kernel(const float* __restrict__ xn, const int* __restrict__ lastidx,
                            const float* __restrict__ hw, const float* __restrict__ hb,
                            float* __restrict__ out) {
    int b = blockIdx.x;
    int w = threadIdx.x >> 5;
    int lane = threadIdx.x & 31;
    const float* h = xn + ((size_t)(b * T_ + lastidx[b])) * D_;
    float s = 0.f;
    for (int d = lane; d < D_; d += 32) s += h[d] * hw[d * 9 + w];
    #pragma unroll
    for (int o = 16; o; o >>= 1) s += __shfl_down_sync(0xffffffffu, s, o);
    if (lane == 0) out[b * 9 + w] = s + hb[w];
}

// ---------------- orchestration ----------------
extern "C" void kernel_launch(void* const* d_in, const int* in_sizes, int n_in,
                              void* d_out, int out_size) {
    const int*   cards   = (const int*)  d_in[0];
    const int*   players = (const int*)  d_in[1];
    const int*   deck    = (const int*)  d_in[2];
    const int*   opp     = (const int*)  d_in[3];
    const float* tok     = (const float*)d_in[4];
    const float* pemb    = (const float*)d_in[5];
    const float* pos     = (const float*)d_in[6];
    const float* ln1s = (const float*)d_in[9];
    const float* ln1b = (const float*)d_in[10];
    const float* qkvw = (const float*)d_in[11];
    const float* qkvb = (const float*)d_in[12];
    const float* projw = (const float*)d_in[13];
    const float* projb = (const float*)d_in[14];
    const float* ln2s = (const float*)d_in[15];
    const float* ln2b = (const float*)d_in[16];
    const float* fc1w = (const float*)d_in[17];
    const float* fc1b = (const float*)d_in[18];
    const float* fc2w = (const float*)d_in[19];
    const float* fc2b = (const float*)d_in[20];
    const float* lnfs = (const float*)d_in[21];
    const float* lnfb = (const float*)d_in[22];
    const float* headw = (const float*)d_in[23];
    const float* headb = (const float*)d_in[24];

    float *x, *xn, *qkv, *dm;
    bf16 *xh, *xl, *yh, *yl, *hh, *hl;
    bf16 *qT_h, *qT_l, *pT_h, *pT_l, *f1T_h, *f1T_l, *f2T_h, *f2T_l;
    char* mask; int* lastidx;
    cudaGetSymbolAddress((void**)&x,    g_x);
    cudaGetSymbolAddress((void**)&xn,   g_xn);
    cudaGetSymbolAddress((void**)&qkv,  g_qkv);
    cudaGetSymbolAddress((void**)&dm,   g_dm);
    cudaGetSymbolAddress((void**)&xh,   g_xh);
    cudaGetSymbolAddress((void**)&xl,   g_xl);
    cudaGetSymbolAddress((void**)&yh,   g_yh);
    cudaGetSymbolAddress((void**)&yl,   g_yl);
    cudaGetSymbolAddress((void**)&hh,   g_hh);
    cudaGetSymbolAddress((void**)&hl,   g_hl);
    cudaGetSymbolAddress((void**)&qT_h, g_qkvT_h);
    cudaGetSymbolAddress((void**)&qT_l, g_qkvT_l);
    cudaGetSymbolAddress((void**)&pT_h, g_projT_h);
    cudaGetSymbolAddress((void**)&pT_l, g_projT_l);
    cudaGetSymbolAddress((void**)&f1T_h, g_fc1T_h);
    cudaGetSymbolAddress((void**)&f1T_l, g_fc1T_l);
    cudaGetSymbolAddress((void**)&f2T_h, g_fc2T_h);
    cudaGetSymbolAddress((void**)&f2T_l, g_fc2T_l);
    cudaGetSymbolAddress((void**)&mask, g_mask);
    cudaGetSymbolAddress((void**)&lastidx, g_lastidx);

    cudaFuncSetAttribute(gemm_mma<0>, cudaFuncAttributeMaxDynamicSharedMemorySize, GEMM_SMEM);
    cudaFuncSetAttribute(gemm_mma<1>, cudaFuncAttributeMaxDynamicSharedMemorySize, GEMM_SMEM);
    cudaFuncSetAttribute(gemm_mma<2>, cudaFuncAttributeMaxDynamicSharedMemorySize, GEMM_SMEM);

    dim3 tb(32, 8);
    // transpose FIRST so ncu's skip-5 capture lands on gemm_mma<0>
    transpose_all<<<TFC2, tb>>>(qkvw, projw, fc1w, fc2w,
                                qT_h, qT_l, pT_h, pT_l, f1T_h, f1T_l, f2T_h, f2T_l);
    mask_kernel<<<B_, T_>>>(cards, mask, lastidx);
    deckmean_kernel<<<B_, D_>>>(deck, opp, tok, dm);
    embed_kernel<<<BT_, 256>>>(cards, players, tok, pemb, pos, dm, x);

    for (int i = 0; i < L_; i++) {
        ln_kernel<true><<<BT_, 256>>>(x, ln1s + i * D_, ln1b + i * D_, nullptr, xh, xl);
        gemm_mma<0><<<dim3(D3_ / 256, BT_ / 128), 256, GEMM_SMEM>>>(
            xh, xl, qT_h + (size_t)i * D3_ * D_, qT_l + (size_t)i * D3_ * D_,
            qkvb + i * D3_, nullptr, qkv, nullptr, nullptr, D_, D3_);
        attn_kernel<<<dim3(T_ / 64, NH_, B_), 256>>>(qkv, mask, yh, yl);
        gemm_mma<2><<<dim3(D_ / 256, BT_ / 128), 256, GEMM_SMEM>>>(
            yh, yl, pT_h + (size_t)i * D_ * D_, pT_l + (size_t)i * D_ * D_,
            projb + i * D_, x, x, nullptr, nullptr, D_, D_);
        ln_kernel<true><<<BT_, 256>>>(x, ln2s + i * D_, ln2b + i * D_, nullptr, xh, xl);
        gemm_mma<1><<<dim3(D4_ / 256, BT_ / 128), 256, GEMM_SMEM>>>(
            xh, xl, f1T_h + (size_t)i * D4_ * D_, f1T_l + (size_t)i * D4_ * D_,
            fc1b + i * D4_, nullptr, nullptr, hh, hl, D_, D4_);
        gemm_mma<2><<<dim3(D_ / 256, BT_ / 128), 256, GEMM_SMEM>>>(
            hh, hl, f2T_h + (size_t)i * D_ * D4_, f2T_l + (size_t)i * D_ * D4_,
            fc2b + i * D_, x, x, nullptr, nullptr, D4_, D_);
    }

    ln_kernel<false><<<BT_, 256>>>(x, lnfs, lnfb, xn, nullptr, nullptr);
    head_kernel<<<B_, 288>>>(xn, lastidx, headw, headb, (float*)d_out);
}

// round 8
// speedup vs baseline: 1.2813x; 1.1959x over previous
#include <cuda_runtime.h>
#include <cuda_fp16.h>
#include <cuda_bf16.h>
#include <math.h>
#include <stdint.h>

typedef __half f16;

// ---------------- problem constants ----------------
#define L_   6
#define D_   768
#define NH_  12
#define DH_  64
#define T_   512
#define B_   16
#define BT_  (B_ * T_)       // 8192
#define D3_  (3 * D_)        // 2304
#define D4_  (4 * D_)        // 3072

// ---------------- scratch (static device globals; no allocs allowed) ----------------
__device__ __align__(128) float g_x  [BT_ * D_];
__device__ __align__(128) float g_xn [BT_ * D_];
__device__ __align__(128) float g_qkv[BT_ * D3_];
__device__ __align__(128) f16   g_xh [BT_ * D_];
__device__ __align__(128) f16   g_xl [BT_ * D_];
__device__ __align__(128) f16   g_yh [BT_ * D_];
__device__ __align__(128) f16   g_yl [BT_ * D_];
__device__ __align__(128) f16   g_hh [BT_ * D4_];
__device__ __align__(128) f16   g_hl [BT_ * D4_];
__device__ __align__(128) float g_dm [B_ * D_];
__device__ char  g_mask[B_ * T_];
__device__ int   g_lastidx[B_];

// transposed fp16 weights: [N, K] (hi only — 2-pass scheme)
__device__ __align__(128) f16 g_qkvT [L_ * D3_ * D_];
__device__ __align__(128) f16 g_projT[L_ * D_ * D_];
__device__ __align__(128) f16 g_fc1T [L_ * D4_ * D_];
__device__ __align__(128) f16 g_fc2T [L_ * D_ * D4_];

// ---------------- PTX helpers ----------------
__device__ __forceinline__ uint32_t smem_u32(const void* p) {
    uint32_t a;
    asm("{ .reg .u64 t; cvta.to.shared.u64 t, %1; cvt.u32.u64 %0, t; }" : "=r"(a) : "l"(p));
    return a;
}
__device__ __forceinline__ void cp16(uint32_t s, const void* g) {
    asm volatile("cp.async.cg.shared.global [%0], [%1], 16;" :: "r"(s), "l"(g) : "memory");
}
__device__ __forceinline__ void ldsm4(uint32_t* r, uint32_t addr) {
    asm volatile("ldmatrix.sync.aligned.m8n8.x4.shared.b16 {%0,%1,%2,%3}, [%4];"
                 : "=r"(r[0]), "=r"(r[1]), "=r"(r[2]), "=r"(r[3]) : "r"(addr));
}
__device__ __forceinline__ void mma16816(float* c, const uint32_t* a, const uint32_t* b) {
    asm volatile(
        "mma.sync.aligned.m16n8k16.row.col.f32.f16.f16.f32 "
        "{%0,%1,%2,%3}, {%4,%5,%6,%7}, {%8,%9}, {%0,%1,%2,%3};"
        : "+f"(c[0]), "+f"(c[1]), "+f"(c[2]), "+f"(c[3])
        : "r"(a[0]), "r"(a[1]), "r"(a[2]), "r"(a[3]), "r"(b[0]), "r"(b[1]));
}
__device__ __forceinline__ float gelu_exact(float v) {
    return 0.5f * v * (1.0f + erff(v * 0.70710678118654752440f));
}
__device__ __forceinline__ void split_f16(float v, f16& h, f16& l) {
    h = __float2half_rn(v);
    l = __float2half_rn(v - __half2float(h));
}

// ---------------- fused weight transpose + fp16 round (single launch) --------------
#define TQKV (L_ * 1728)                 // 10368
#define TPROJ (TQKV + L_ * 576)          // 13824
#define TFC1 (TPROJ + L_ * 2304)         // 27648
#define TFC2 (TFC1 + L_ * 2304)          // 41472

__global__ void transpose_all(const float* __restrict__ qkvw, const float* __restrict__ projw,
                              const float* __restrict__ fc1w, const float* __restrict__ fc2w,
                              f16* __restrict__ qT, f16* __restrict__ pT,
                              f16* __restrict__ f1T, f16* __restrict__ f2T) {
    __shared__ float tile[32][33];
    int idx = blockIdx.x;
    const float* W; f16* Th; int K, N, rem;
    if (idx < TQKV) {
        int layer = idx / 1728; rem = idx % 1728;
        K = D_; N = D3_;
        W = qkvw + (size_t)layer * D_ * D3_;
        Th = qT + (size_t)layer * D3_ * D_;
    } else if (idx < TPROJ) {
        idx -= TQKV;
        int layer = idx / 576; rem = idx % 576;
        K = D_; N = D_;
        W = projw + (size_t)layer * D_ * D_;
        Th = pT + (size_t)layer * D_ * D_;
    } else if (idx < TFC1) {
        idx -= TPROJ;
        int layer = idx / 2304; rem = idx % 2304;
        K = D_; N = D4_;
        W = fc1w + (size_t)layer * D_ * D4_;
        Th = f1T + (size_t)layer * D4_ * D_;
    } else {
        idx -= TFC1;
        int layer = idx / 2304; rem = idx % 2304;
        K = D4_; N = D_;
        W = fc2w + (size_t)layer * D4_ * D_;
        Th = f2T + (size_t)layer * D_ * D4_;
    }
    int tilesN = N >> 5;
    int n0 = (rem % tilesN) << 5;
    int k0 = (rem / tilesN) << 5;
    int tx = threadIdx.x, ty = threadIdx.y;   // 32x8
    #pragma unroll
    for (int i = 0; i < 32; i += 8)
        tile[ty + i][tx] = W[(size_t)(k0 + ty + i) * N + n0 + tx];
    __syncthreads();
    #pragma unroll
    for (int i = 0; i < 32; i += 8) {
        float v = tile[tx][ty + i];
        Th[(size_t)(n0 + ty + i) * K + k0 + tx] = __float2half_rn(v);
    }
}

// ---------------- mask + last_idx ----------------
__global__ void mask_kernel(const int* __restrict__ cards,
                            char* __restrict__ mask, int* __restrict__ lastidx) {
    int b = blockIdx.x;
    int t = threadIdx.x;
    bool valid = cards[b * T_ + t] != 0;
    bool any = __syncthreads_or(valid);
    bool m = valid || (t == 0 && !any);
    mask[b * T_ + t] = m ? 1 : 0;
    int cnt = __syncthreads_count(m);
    if (t == 0) lastidx[b] = (cnt - 1) > 0 ? (cnt - 1) : 0;
}

// ---------------- deck means ----------------
__global__ void deckmean_kernel(const int* __restrict__ deck, const int* __restrict__ opp,
                                const float* __restrict__ tok, float* __restrict__ dm) {
    int b = blockIdx.x;
    int d = threadIdx.x;
    float s = 0.f;
    #pragma unroll
    for (int i = 0; i < 8; i++) {
        s += tok[(size_t)deck[b * 8 + i] * D_ + d];
        s += tok[(size_t)opp [b * 8 + i] * D_ + d];
    }
    dm[b * D_ + d] = s * 0.125f;
}

// ---------------- embedding sum ----------------
__global__ void embed_kernel(const int* __restrict__ cards, const int* __restrict__ players,
                             const float* __restrict__ tok, const float* __restrict__ pemb,
                             const float* __restrict__ pos, const float* __restrict__ dm,
                             float* __restrict__ x) {
    int bt = blockIdx.x;
    int b = bt >> 9;
    int t = bt & 511;
    int card = cards[bt];
    int pl = players[bt]; pl = pl < 0 ? 0 : (pl > 1 ? 1 : pl);
    const float* tr = tok  + (size_t)card * D_;
    const float* pr = pemb + (size_t)pl * D_;
    const float* qr = pos  + (size_t)t * D_;
    const float* mr = dm   + (size_t)b * D_;
    float* xr = x + (size_t)bt * D_;
    for (int d = threadIdx.x; d < D_; d += 256)
        xr[d] = tr[d] + pr[d] + mr[d] + qr[d];
}

// ---------------- layernorm -> fp16 hi/lo (or fp32 for final) ----------------
template<bool TOH>
__global__ void ln_kernel(const float* __restrict__ x, const float* __restrict__ g,
                          const float* __restrict__ be, float* __restrict__ of,
                          f16* __restrict__ oh, f16* __restrict__ ol) {
    __shared__ float sh1[8], sh2[8];
    int r = blockIdx.x;
    size_t base = (size_t)r * D_;
    int t = threadIdx.x;
    float v0 = x[base + t], v1 = x[base + t + 256], v2 = x[base + t + 512];
    float s = v0 + v1 + v2;
    float q = v0 * v0 + v1 * v1 + v2 * v2;
    #pragma unroll
    for (int o2 = 16; o2; o2 >>= 1) {
        s += __shfl_xor_sync(0xffffffffu, s, o2);
        q += __shfl_xor_sync(0xffffffffu, q, o2);
    }
    if ((t & 31) == 0) { sh1[t >> 5] = s; sh2[t >> 5] = q; }
    __syncthreads();
    s = sh1[t & 7]; q = sh2[t & 7];
    #pragma unroll
    for (int o2 = 4; o2; o2 >>= 1) {
        s += __shfl_xor_sync(0xffffffffu, s, o2);
        q += __shfl_xor_sync(0xffffffffu, q, o2);
    }
    float mean = s * (1.0f / D_);
    float var  = q * (1.0f / D_) - mean * mean;
    float rstd = rsqrtf(var + 1e-5f);
    #pragma unroll
    for (int u = 0; u < 3; u++) {
        int d = t + u * 256;
        float v = (u == 0 ? v0 : (u == 1 ? v1 : v2));
        float o = (v - mean) * rstd * g[d] + be[d];
        if (TOH) {
            f16 hi, lo; split_f16(o, hi, lo);
            oh[base + d] = hi; ol[base + d] = lo;
        } else {
            of[base + d] = o;
        }
    }
}

// ---------------- mma.sync fp16x2 GEMM, 128x256 tiles ----------------
// C = epi( (Ah+Al)[M,K] @ Bh[N,K]^T + bias )   (B rounded once; dropped term ~2^-11)
#define ROWB 80
#define A_HI_OFF 0
#define A_LO_OFF (128 * ROWB)              // 10240
#define B_HI_OFF (2 * 128 * ROWB)          // 20480
#define STAGE_BYTES (B_HI_OFF + 256 * ROWB) // 40960
#define GEMM_SMEM (2 * STAGE_BYTES)         // 81920

template<int EPI>
__global__ __launch_bounds__(256, 1)
void gemm_mma(const f16* __restrict__ Ah, const f16* __restrict__ Al,
              const f16* __restrict__ Bh,
              const float* __restrict__ bias, const float* __restrict__ res,
              float* __restrict__ outf, f16* __restrict__ outh, f16* __restrict__ outl,
              int K, int Nfull) {
    extern __shared__ char dsm[];
    uint32_t tiles = smem_u32(dsm);

    int tid = threadIdx.x;
    int wid = tid >> 5;
    int lane = tid & 31;
    int warp_m = wid & 1;        // 2 warps in M (64 rows each)
    int warp_n = wid >> 1;       // 4 warps in N (64 cols each)
    int m0 = blockIdx.y * 128;
    int n0 = blockIdx.x * 256;
    int nt = K >> 5;

    int aRow  = lane & 15;
    int aColB = (lane >> 4) << 4;
    int bRow  = (lane & 7) + ((lane & 16) >> 1);
    int bColB = (lane & 8) << 1;

    float acc[4][8][4];
    #pragma unroll
    for (int mt = 0; mt < 4; mt++)
        #pragma unroll
        for (int ntl = 0; ntl < 8; ntl++)
            #pragma unroll
            for (int r = 0; r < 4; r++) acc[mt][ntl][r] = 0.f;

    auto load_stage = [&](int kt, int st) {
        uint32_t sb = tiles + st * STAGE_BYTES;
        int k0 = kt << 5;
        #pragma unroll
        for (int i = 0; i < 2; i++) {                    // A: 128 rows x 4 chunks (hi+lo)
            int id = tid + (i << 8);
            int r = id >> 2, c = id & 3;
            size_t go = (size_t)(m0 + r) * K + k0 + (c << 3);
            uint32_t so = r * ROWB + (c << 4);
            cp16(sb + A_HI_OFF + so, Ah + go);
            cp16(sb + A_LO_OFF + so, Al + go);
        }
        #pragma unroll
        for (int i = 0; i < 4; i++) {                    // B: 256 rows x 4 chunks (hi only)
            int id = tid + (i << 8);
            int r = id >> 2, c = id & 3;
            size_t go = (size_t)(n0 + r) * K + k0 + (c << 3);
            uint32_t so = r * ROWB + (c << 4);
            cp16(sb + B_HI_OFF + so, Bh + go);
        }
        asm volatile("cp.async.commit_group;" ::: "memory");
    };

    load_stage(0, 0);

    uint32_t aH[16], aL[16], bH[16];

    for (int kt = 0; kt < nt; kt++) {
        int cur = kt & 1;
        if (kt + 1 < nt) {
            load_stage(kt + 1, cur ^ 1);
            asm volatile("cp.async.wait_group 1;" ::: "memory");
        } else {
            asm volatile("cp.async.wait_group 0;" ::: "memory");
        }
        __syncthreads();

        uint32_t sb = tiles + cur * STAGE_BYTES;
        uint32_t aBase = sb + (warp_m * 64 + aRow) * ROWB + aColB;
        uint32_t bBase = sb + B_HI_OFF + (warp_n * 64 + bRow) * ROWB + bColB;

        #pragma unroll
        for (int ks = 0; ks < 2; ks++) {
            uint32_t kb = ks << 5;
            #pragma unroll
            for (int mt = 0; mt < 4; mt++) {
                ldsm4(&aH[4 * mt], aBase + A_HI_OFF + mt * (16 * ROWB) + kb);
                ldsm4(&aL[4 * mt], aBase + (A_LO_OFF - A_HI_OFF) + mt * (16 * ROWB) + kb);
            }
            #pragma unroll
            for (int p = 0; p < 4; p++)
                ldsm4(&bH[4 * p], bBase + p * (16 * ROWB) + kb);
            // pass 1: Ah*Bh
            #pragma unroll
            for (int mt = 0; mt < 4; mt++)
                #pragma unroll
                for (int ntl = 0; ntl < 8; ntl++)
                    mma16816(acc[mt][ntl], &aH[4 * mt], &bH[2 * ntl]);
            // pass 2: Al*Bh
            #pragma unroll
            for (int mt = 0; mt < 4; mt++)
                #pragma unroll
                for (int ntl = 0; ntl < 8; ntl++)
                    mma16816(acc[mt][ntl], &aL[4 * mt], &bH[2 * ntl]);
        }
        __syncthreads();
    }

    int m_base = m0 + warp_m * 64 + (lane >> 2);
    int n_base = n0 + warp_n * 64 + ((lane & 3) << 1);
    #pragma unroll
    for (int mt = 0; mt < 4; mt++) {
        #pragma unroll
        for (int ntl = 0; ntl < 8; ntl++) {
            int n = n_base + ntl * 8;
            float b0 = bias[n], b1 = bias[n + 1];
            #pragma unroll
            for (int rr = 0; rr < 2; rr++) {
                int m = m_base + mt * 16 + rr * 8;
                size_t ob = (size_t)m * Nfull + n;
                float v0 = acc[mt][ntl][2 * rr]     + b0;
                float v1 = acc[mt][ntl][2 * rr + 1] + b1;
                if (EPI == 0) {
                    *(float2*)(outf + ob) = make_float2(v0, v1);
                } else if (EPI == 2) {
                    float2 rv = *(const float2*)(res + ob);
                    *(float2*)(outf + ob) = make_float2(v0 + rv.x, v1 + rv.y);
                } else {
                    float g0 = gelu_exact(v0), g1 = gelu_exact(v1);
                    f16 h0, l0, h1, l1;
                    split_f16(g0, h0, l0); split_f16(g1, h1, l1);
                    *(__half2*)(outh + ob) = __halves2half2(h0, h1);
                    *(__half2*)(outl + ob) = __halves2half2(l0, l1);
                }
            }
        }
    }
}

// ---------------- flash attention (fp32), 64 q x 32 k tiles (R3 config) ------------
__global__ __launch_bounds__(256)
void attn_kernel(const float* __restrict__ qkv, const char* __restrict__ mask,
                 f16* __restrict__ outh, f16* __restrict__ outl) {
    int qt = blockIdx.x, h = blockIdx.y, b = blockIdx.z;
    __shared__ float Qs[64][64];
    __shared__ float Kst[64][32];
    __shared__ float Vs[32][64];
    __shared__ float Ps[64][32];
    __shared__ char  Ms[32];

    int tid = threadIdx.x;
    int i = tid >> 2;
    int jq = tid & 3;
    int c0 = jq * 16;
    int gq = qt * 64 + i;
    const float scale = 0.125f;

    {
        int idx = tid * 16;
        int row = idx >> 6;
        int cc = idx & 63;
        const float* g = qkv + ((size_t)(b * T_ + qt * 64 + row)) * D3_ + h * DH_ + cc;
        #pragma unroll
        for (int u = 0; u < 4; u++)
            *(float4*)&Qs[row][cc + u * 4] = *(const float4*)(g + u * 4);
    }

    float O[16];
    #pragma unroll
    for (int cc = 0; cc < 16; cc++) O[cc] = 0.f;
    float m_prev = -INFINITY, l = 0.f;

    int ktmax = (qt + 1) * 2;
    for (int kt = 0; kt < ktmax; kt++) {
        __syncthreads();
        {
            int j = tid >> 3;
            int d0 = (tid & 7) * 8;
            const float* gk = qkv + ((size_t)(b * T_ + kt * 32 + j)) * D3_ + D_ + h * DH_ + d0;
            const float* gv = qkv + ((size_t)(b * T_ + kt * 32 + j)) * D3_ + 2 * D_ + h * DH_ + d0;
            float4 k0v = *(const float4*)gk;
            float4 k1v = *(const float4*)(gk + 4);
            Kst[d0 + 0][j] = k0v.x; Kst[d0 + 1][j] = k0v.y;
            Kst[d0 + 2][j] = k0v.z; Kst[d0 + 3][j] = k0v.w;
            Kst[d0 + 4][j] = k1v.x; Kst[d0 + 5][j] = k1v.y;
            Kst[d0 + 6][j] = k1v.z; Kst[d0 + 7][j] = k1v.w;
            *(float4*)&Vs[j][d0]     = *(const float4*)gv;
            *(float4*)&Vs[j][d0 + 4] = *(const float4*)(gv + 4);
            if (tid < 32) Ms[tid] = mask[b * T_ + kt * 32 + tid];
        }
        __syncthreads();

        float s[8];
        #pragma unroll
        for (int jj = 0; jj < 8; jj++) s[jj] = 0.f;
        #pragma unroll
        for (int k = 0; k < 64; k++) {
            float qv = Qs[i][k];
            float4 ka = *(const float4*)&Kst[k][jq * 8];
            float4 kb = *(const float4*)&Kst[k][jq * 8 + 4];
            s[0] += qv * ka.x; s[1] += qv * ka.y; s[2] += qv * ka.z; s[3] += qv * ka.w;
            s[4] += qv * kb.x; s[5] += qv * kb.y; s[6] += qv * kb.z; s[7] += qv * kb.w;
        }
        float mt = -INFINITY;
        #pragma unroll
        for (int jj = 0; jj < 8; jj++) {
            int gk = kt * 32 + jq * 8 + jj;
            bool ok = (gk <= gq) && (Ms[jq * 8 + jj] != 0);
            s[jj] = ok ? s[jj] * scale : -INFINITY;
            mt = fmaxf(mt, s[jj]);
        }
        mt = fmaxf(mt, __shfl_xor_sync(0xffffffffu, mt, 1));
        mt = fmaxf(mt, __shfl_xor_sync(0xffffffffu, mt, 2));
        float m_new = fmaxf(m_prev, mt);
        float alpha, psum = 0.f;
        float p[8];
        if (m_new == -INFINITY) {
            alpha = 1.0f;
            #pragma unroll
            for (int jj = 0; jj < 8; jj++) p[jj] = 0.f;
        } else {
            alpha = expf(m_prev - m_new);
            #pragma unroll
            for (int jj = 0; jj < 8; jj++) {
                p[jj] = expf(s[jj] - m_new);
                psum += p[jj];
            }
        }
        psum += __shfl_xor_sync(0xffffffffu, psum, 1);
        psum += __shfl_xor_sync(0xffffffffu, psum, 2);
        l = l * alpha + psum;
        m_prev = m_new;
        #pragma unroll
        for (int cc = 0; cc < 16; cc++) O[cc] *= alpha;
        #pragma unroll
        for (int jj = 0; jj < 8; jj++) Ps[i][jq * 8 + jj] = p[jj];
        __syncthreads();

        #pragma unroll 8
        for (int j = 0; j < 32; j++) {
            float pv = Ps[i][j];
            float4 v0 = *(const float4*)&Vs[j][c0];
            float4 v1 = *(const float4*)&Vs[j][c0 + 4];
            float4 v2 = *(const float4*)&Vs[j][c0 + 8];
            float4 v3 = *(const float4*)&Vs[j][c0 + 12];
            O[0]  += pv * v0.x; O[1]  += pv * v0.y; O[2]  += pv * v0.z; O[3]  += pv * v0.w;
            O[4]  += pv * v1.x; O[5]  += pv * v1.y; O[6]  += pv * v1.z; O[7]  += pv * v1.w;
            O[8]  += pv * v2.x; O[9]  += pv * v2.y; O[10] += pv * v2.z; O[11] += pv * v2.w;
            O[12] += pv * v3.x; O[13] += pv * v3.y; O[14] += pv * v3.z; O[15] += pv * v3.w;
        }
    }

    float rl = (l > 0.f) ? (1.0f / l) : 0.f;
    size_t ob = ((size_t)(b * T_ + qt * 64 + i)) * D_ + h * DH_ + c0;
    #pragma unroll
    for (int cc = 0; cc < 16; cc++) {
        float v = O[cc] * rl;
        f16 hi, lo; split_f16(v, hi, lo);
        outh[ob + cc] = hi; outl[ob + cc] = lo;
    }
}

// ---------------- head ----------------
__global__ void head_kernel(const float* __restrict__ xn, const int* __restrict__ lastidx,
                            const float* __restrict__ hw, const float* __restrict__ hb,
                            float* __restrict__ out) {
    int b = blockIdx.x;
    int w = threadIdx.x >> 5;
    int lane = threadIdx.x & 31;
    const float* h = xn + ((size_t)(b * T_ + lastidx[b])) * D_;
    float s = 0.f;
    for (int d = lane; d < D_; d += 32) s += h[d] * hw[d * 9 + w];
    #pragma unroll
    for (int o = 16; o; o >>= 1) s += __shfl_down_sync(0xffffffffu, s, o);
    if (lane == 0) out[b * 9 + w] = s + hb[w];
}

// ---------------- orchestration ----------------
extern "C" void kernel_launch(void* const* d_in, const int* in_sizes, int n_in,
                              void* d_out, int out_size) {
    const int*   cards   = (const int*)  d_in[0];
    const int*   players = (const int*)  d_in[1];
    const int*   deck    = (const int*)  d_in[2];
    const int*   opp     = (const int*)  d_in[3];
    const float* tok     = (const float*)d_in[4];
    const float* pemb    = (const float*)d_in[5];
    const float* pos     = (const float*)d_in[6];
    const float* ln1s = (const float*)d_in[9];
    const float* ln1b = (const float*)d_in[10];
    const float* qkvw = (const float*)d_in[11];
    const float* qkvb = (const float*)d_in[12];
    const float* projw = (const float*)d_in[13];
    const float* projb = (const float*)d_in[14];
    const float* ln2s = (const float*)d_in[15];
    const float* ln2b = (const float*)d_in[16];
    const float* fc1w = (const float*)d_in[17];
    const float* fc1b = (const float*)d_in[18];
    const float* fc2w = (const float*)d_in[19];
    const float* fc2b = (const float*)d_in[20];
    const float* lnfs = (const float*)d_in[21];
    const float* lnfb = (const float*)d_in[22];
    const float* headw = (const float*)d_in[23];
    const float* headb = (const float*)d_in[24];

    float *x, *xn, *qkv, *dm;
    f16 *xh, *xl, *yh, *yl, *hh, *hl;
    f16 *qT, *pT, *f1T, *f2T;
    char* mask; int* lastidx;
    cudaGetSymbolAddress((void**)&x,    g_x);
    cudaGetSymbolAddress((void**)&xn,   g_xn);
    cudaGetSymbolAddress((void**)&qkv,  g_qkv);
    cudaGetSymbolAddress((void**)&dm,   g_dm);
    cudaGetSymbolAddress((void**)&xh,   g_xh);
    cudaGetSymbolAddress((void**)&xl,   g_xl);
    cudaGetSymbolAddress((void**)&yh,   g_yh);
    cudaGetSymbolAddress((void**)&yl,   g_yl);
    cudaGetSymbolAddress((void**)&hh,   g_hh);
    cudaGetSymbolAddress((void**)&hl,   g_hl);
    cudaGetSymbolAddress((void**)&qT,   g_qkvT);
    cudaGetSymbolAddress((void**)&pT,   g_projT);
    cudaGetSymbolAddress((void**)&f1T,  g_fc1T);
    cudaGetSymbolAddress((void**)&f2T,  g_fc2T);
    cudaGetSymbolAddress((void**)&mask, g_mask);
    cudaGetSymbolAddress((void**)&lastidx, g_lastidx);

    cudaFuncSetAttribute(gemm_mma<0>, cudaFuncAttributeMaxDynamicSharedMemorySize, GEMM_SMEM);
    cudaFuncSetAttribute(gemm_mma<1>, cudaFuncAttributeMaxDynamicSharedMemorySize, GEMM_SMEM);
    cudaFuncSetAttribute(gemm_mma<2>, cudaFuncAttributeMaxDynamicSharedMemorySize, GEMM_SMEM);

    dim3 tb(32, 8);
    transpose_all<<<TFC2, tb>>>(qkvw, projw, fc1w, fc2w, qT, pT, f1T, f2T);
    mask_kernel<<<B_, T_>>>(cards, mask, lastidx);
    deckmean_kernel<<<B_, D_>>>(deck, opp, tok, dm);
    embed_kernel<<<BT_, 256>>>(cards, players, tok, pemb, pos, dm, x);

    for (int i = 0; i < L_; i++) {
        ln_kernel<true><<<BT_, 256>>>(x, ln1s + i * D_, ln1b + i * D_, nullptr, xh, xl);
        gemm_mma<0><<<dim3(D3_ / 256, BT_ / 128), 256, GEMM_SMEM>>>(
            xh, xl, qT + (size_t)i * D3_ * D_,
            qkvb + i * D3_, nullptr, qkv, nullptr, nullptr, D_, D3_);
        attn_kernel<<<dim3(T_ / 64, NH_, B_), 256>>>(qkv, mask, yh, yl);
        gemm_mma<2><<<dim3(D_ / 256, BT_ / 128), 256, GEMM_SMEM>>>(
            yh, yl, pT + (size_t)i * D_ * D_,
            projb + i * D_, x, x, nullptr, nullptr, D_, D_);
        ln_kernel<true><<<BT_, 256>>>(x, ln2s + i * D_, ln2b + i * D_, nullptr, xh, xl);
        gemm_mma<1><<<dim3(D4_ / 256, BT_ / 128), 256, GEMM_SMEM>>>(
            xh, xl, f1T + (size_t)i * D4_ * D_,
            fc1b + i * D4_, nullptr, nullptr, hh, hl, D_, D4_);
        gemm_mma<2><<<dim3(D_ / 256, BT_ / 128), 256, GEMM_SMEM>>>(
            hh, hl, f2T + (size_t)i * D_ * D4_,
            fc2b + i * D_, x, x, nullptr, nullptr, D4_, D_);
    }

    ln_kernel<false><<<BT_, 256>>>(x, lnfs, lnfb, xn, nullptr, nullptr);
    head_kernel<<<B_, 288>>>(xn, lastidx, headw, headb, (float*)d_out);
}

// round 9
// speedup vs baseline: 2.1286x; 1.6612x over previous
#include <cuda_runtime.h>
#include <cuda_fp16.h>
#include <math.h>
#include <stdint.h>

typedef __half f16;

// ---------------- problem constants ----------------
#define L_   6
#define D_   768
#define NH_  12
#define DH_  64
#define T_   512
#define B_   16
#define BT_  (B_ * T_)       // 8192
#define D3_  (3 * D_)        // 2304
#define D4_  (4 * D_)        // 3072

// ---------------- scratch ----------------
__device__ __align__(128) float g_x  [BT_ * D_];
__device__ __align__(128) float g_xn [BT_ * D_];
__device__ __align__(128) float g_qkv[BT_ * D3_];
__device__ __align__(128) f16   g_xh [BT_ * D_];
__device__ __align__(128) f16   g_xl [BT_ * D_];
__device__ __align__(128) f16   g_yh [BT_ * D_];
__device__ __align__(128) f16   g_yl [BT_ * D_];
__device__ __align__(128) f16   g_hh [BT_ * D4_];
__device__ __align__(128) f16   g_hl [BT_ * D4_];
__device__ __align__(128) float g_dm [B_ * D_];
__device__ char  g_mask[B_ * T_];
__device__ int   g_lastidx[B_];

__device__ __align__(128) f16 g_qkvT [L_ * D3_ * D_];
__device__ __align__(128) f16 g_projT[L_ * D_ * D_];
__device__ __align__(128) f16 g_fc1T [L_ * D4_ * D_];
__device__ __align__(128) f16 g_fc2T [L_ * D_ * D4_];

// ---------------- PTX helpers ----------------
__device__ __forceinline__ uint32_t smem_u32(const void* p) {
    uint32_t a;
    asm("{ .reg .u64 t; cvta.to.shared.u64 t, %1; cvt.u32.u64 %0, t; }" : "=r"(a) : "l"(p));
    return a;
}
__device__ __forceinline__ void cp16(uint32_t s, const void* g) {
    asm volatile("cp.async.cg.shared.global [%0], [%1], 16;" :: "r"(s), "l"(g) : "memory");
}
__device__ __forceinline__ void ldsm4(uint32_t* r, uint32_t addr) {
    asm volatile("ldmatrix.sync.aligned.m8n8.x4.shared.b16 {%0,%1,%2,%3}, [%4];"
                 : "=r"(r[0]), "=r"(r[1]), "=r"(r[2]), "=r"(r[3]) : "r"(addr));
}
__device__ __forceinline__ void mma16816(float* c, const uint32_t* a, const uint32_t* b) {
    asm volatile(
        "mma.sync.aligned.m16n8k16.row.col.f32.f16.f16.f32 "
        "{%0,%1,%2,%3}, {%4,%5,%6,%7}, {%8,%9}, {%0,%1,%2,%3};"
        : "+f"(c[0]), "+f"(c[1]), "+f"(c[2]), "+f"(c[3])
        : "r"(a[0]), "r"(a[1]), "r"(a[2]), "r"(a[3]), "r"(b[0]), "r"(b[1]));
}
__device__ __forceinline__ float gelu_exact(float v) {
    return 0.5f * v * (1.0f + erff(v * 0.70710678118654752440f));
}
__device__ __forceinline__ void split_f16(float v, f16& h, f16& l) {
    h = __float2half_rn(v);
    l = __float2half_rn(v - __half2float(h));
}
__device__ __forceinline__ uint32_t pack_h2(f16 a, f16 b) {
    __half2 t = __halves2half2(a, b);
    return *(uint32_t*)&t;
}

// ---------------- fused weight transpose + fp16 round ----------------
#define TQKV (L_ * 1728)
#define TPROJ (TQKV + L_ * 576)
#define TFC1 (TPROJ + L_ * 2304)
#define TFC2 (TFC1 + L_ * 2304)

__global__ void transpose_all(const float* __restrict__ qkvw, const float* __restrict__ projw,
                              const float* __restrict__ fc1w, const float* __restrict__ fc2w,
                              f16* __restrict__ qT, f16* __restrict__ pT,
                              f16* __restrict__ f1T, f16* __restrict__ f2T) {
    __shared__ float tile[32][33];
    int idx = blockIdx.x;
    const float* W; f16* Th; int K, N, rem;
    if (idx < TQKV) {
        int layer = idx / 1728; rem = idx % 1728;
        K = D_; N = D3_;
        W = qkvw + (size_t)layer * D_ * D3_;
        Th = qT + (size_t)layer * D3_ * D_;
    } else if (idx < TPROJ) {
        idx -= TQKV;
        int layer = idx / 576; rem = idx % 576;
        K = D_; N = D_;
        W = projw + (size_t)layer * D_ * D_;
        Th = pT + (size_t)layer * D_ * D_;
    } else if (idx < TFC1) {
        idx -= TPROJ;
        int layer = idx / 2304; rem = idx % 2304;
        K = D_; N = D4_;
        W = fc1w + (size_t)layer * D_ * D4_;
        Th = f1T + (size_t)layer * D4_ * D_;
    } else {
        idx -= TFC1;
        int layer = idx / 2304; rem = idx % 2304;
        K = D4_; N = D_;
        W = fc2w + (size_t)layer * D4_ * D_;
        Th = f2T + (size_t)layer * D_ * D4_;
    }
    int tilesN = N >> 5;
    int n0 = (rem % tilesN) << 5;
    int k0 = (rem / tilesN) << 5;
    int tx = threadIdx.x, ty = threadIdx.y;
    #pragma unroll
    for (int i = 0; i < 32; i += 8)
        tile[ty + i][tx] = W[(size_t)(k0 + ty + i) * N + n0 + tx];
    __syncthreads();
    #pragma unroll
    for (int i = 0; i < 32; i += 8) {
        float v = tile[tx][ty + i];
        Th[(size_t)(n0 + ty + i) * K + k0 + tx] = __float2half_rn(v);
    }
}

// ---------------- mask + last_idx ----------------
__global__ void mask_kernel(const int* __restrict__ cards,
                            char* __restrict__ mask, int* __restrict__ lastidx) {
    int b = blockIdx.x;
    int t = threadIdx.x;
    bool valid = cards[b * T_ + t] != 0;
    bool any = __syncthreads_or(valid);
    bool m = valid || (t == 0 && !any);
    mask[b * T_ + t] = m ? 1 : 0;
    int cnt = __syncthreads_count(m);
    if (t == 0) lastidx[b] = (cnt - 1) > 0 ? (cnt - 1) : 0;
}

// ---------------- deck means ----------------
__global__ void deckmean_kernel(const int* __restrict__ deck, const int* __restrict__ opp,
                                const float* __restrict__ tok, float* __restrict__ dm) {
    int b = blockIdx.x;
    int d = threadIdx.x;
    float s = 0.f;
    #pragma unroll
    for (int i = 0; i < 8; i++) {
        s += tok[(size_t)deck[b * 8 + i] * D_ + d];
        s += tok[(size_t)opp [b * 8 + i] * D_ + d];
    }
    dm[b * D_ + d] = s * 0.125f;
}

// ---------------- embedding sum ----------------
__global__ void embed_kernel(const int* __restrict__ cards, const int* __restrict__ players,
                             const float* __restrict__ tok, const float* __restrict__ pemb,
                             const float* __restrict__ pos, const float* __restrict__ dm,
                             float* __restrict__ x) {
    int bt = blockIdx.x;
    int b = bt >> 9;
    int t = bt & 511;
    int card = cards[bt];
    int pl = players[bt]; pl = pl < 0 ? 0 : (pl > 1 ? 1 : pl);
    const float* tr = tok  + (size_t)card * D_;
    const float* pr = pemb + (size_t)pl * D_;
    const float* qr = pos  + (size_t)t * D_;
    const float* mr = dm   + (size_t)b * D_;
    float* xr = x + (size_t)bt * D_;
    for (int d = threadIdx.x; d < D_; d += 256)
        xr[d] = tr[d] + pr[d] + mr[d] + qr[d];
}

// ---------------- layernorm -> fp16 hi/lo (or fp32 for final) ----------------
template<bool TOH>
__global__ void ln_kernel(const float* __restrict__ x, const float* __restrict__ g,
                          const float* __restrict__ be, float* __restrict__ of,
                          f16* __restrict__ oh, f16* __restrict__ ol) {
    __shared__ float sh1[8], sh2[8];
    int r = blockIdx.x;
    size_t base = (size_t)r * D_;
    int t = threadIdx.x;
    float v0 = x[base + t], v1 = x[base + t + 256], v2 = x[base + t + 512];
    float s = v0 + v1 + v2;
    float q = v0 * v0 + v1 * v1 + v2 * v2;
    #pragma unroll
    for (int o2 = 16; o2; o2 >>= 1) {
        s += __shfl_xor_sync(0xffffffffu, s, o2);
        q += __shfl_xor_sync(0xffffffffu, q, o2);
    }
    if ((t & 31) == 0) { sh1[t >> 5] = s; sh2[t >> 5] = q; }
    __syncthreads();
    s = sh1[t & 7]; q = sh2[t & 7];
    #pragma unroll
    for (int o2 = 4; o2; o2 >>= 1) {
        s += __shfl_xor_sync(0xffffffffu, s, o2);
        q += __shfl_xor_sync(0xffffffffu, q, o2);
    }
    float mean = s * (1.0f / D_);
    float var  = q * (1.0f / D_) - mean * mean;
    float rstd = rsqrtf(var + 1e-5f);
    #pragma unroll
    for (int u = 0; u < 3; u++) {
        int d = t + u * 256;
        float v = (u == 0 ? v0 : (u == 1 ? v1 : v2));
        float o = (v - mean) * rstd * g[d] + be[d];
        if (TOH) {
            f16 hi, lo; split_f16(o, hi, lo);
            oh[base + d] = hi; ol[base + d] = lo;
        } else {
            of[base + d] = o;
        }
    }
}

// ---------------- mma.sync fp16x2 GEMM, 128x256 tiles ----------------
#define ROWB 80
#define A_HI_OFF 0
#define A_LO_OFF (128 * ROWB)
#define B_HI_OFF (2 * 128 * ROWB)
#define STAGE_BYTES (B_HI_OFF + 256 * ROWB)
#define GEMM_SMEM (2 * STAGE_BYTES)

template<int EPI>
__global__ __launch_bounds__(256, 1)
void gemm_mma(const f16* __restrict__ Ah, const f16* __restrict__ Al,
              const f16* __restrict__ Bh,
              const float* __restrict__ bias, const float* __restrict__ res,
              float* __restrict__ outf, f16* __restrict__ outh, f16* __restrict__ outl,
              int K, int Nfull) {
    extern __shared__ char dsm[];
    uint32_t tiles = smem_u32(dsm);

    int tid = threadIdx.x;
    int wid = tid >> 5;
    int lane = tid & 31;
    int warp_m = wid & 1;
    int warp_n = wid >> 1;
    int m0 = blockIdx.y * 128;
    int n0 = blockIdx.x * 256;
    int nt = K >> 5;

    int aRow  = lane & 15;
    int aColB = (lane >> 4) << 4;
    int bRow  = (lane & 7) + ((lane & 16) >> 1);
    int bColB = (lane & 8) << 1;

    float acc[4][8][4];
    #pragma unroll
    for (int mt = 0; mt < 4; mt++)
        #pragma unroll
        for (int ntl = 0; ntl < 8; ntl++)
            #pragma unroll
            for (int r = 0; r < 4; r++) acc[mt][ntl][r] = 0.f;

    auto load_stage = [&](int kt, int st) {
        uint32_t sb = tiles + st * STAGE_BYTES;
        int k0 = kt << 5;
        #pragma unroll
        for (int i = 0; i < 2; i++) {
            int id = tid + (i << 8);
            int r = id >> 2, c = id & 3;
            size_t go = (size_t)(m0 + r) * K + k0 + (c << 3);
            uint32_t so = r * ROWB + (c << 4);
            cp16(sb + A_HI_OFF + so, Ah + go);
            cp16(sb + A_LO_OFF + so, Al + go);
        }
        #pragma unroll
        for (int i = 0; i < 4; i++) {
            int id = tid + (i << 8);
            int r = id >> 2, c = id & 3;
            size_t go = (size_t)(n0 + r) * K + k0 + (c << 3);
            uint32_t so = r * ROWB + (c << 4);
            cp16(sb + B_HI_OFF + so, Bh + go);
        }
        asm volatile("cp.async.commit_group;" ::: "memory");
    };

    load_stage(0, 0);

    uint32_t aH[16], aL[16], bH[16];

    for (int kt = 0; kt < nt; kt++) {
        int cur = kt & 1;
        if (kt + 1 < nt) {
            load_stage(kt + 1, cur ^ 1);
            asm volatile("cp.async.wait_group 1;" ::: "memory");
        } else {
            asm volatile("cp.async.wait_group 0;" ::: "memory");
        }
        __syncthreads();

        uint32_t sb = tiles + cur * STAGE_BYTES;
        uint32_t aBase = sb + (warp_m * 64 + aRow) * ROWB + aColB;
        uint32_t bBase = sb + B_HI_OFF + (warp_n * 64 + bRow) * ROWB + bColB;

        #pragma unroll
        for (int ks = 0; ks < 2; ks++) {
            uint32_t kb = ks << 5;
            #pragma unroll
            for (int mt = 0; mt < 4; mt++) {
                ldsm4(&aH[4 * mt], aBase + A_HI_OFF + mt * (16 * ROWB) + kb);
                ldsm4(&aL[4 * mt], aBase + (A_LO_OFF - A_HI_OFF) + mt * (16 * ROWB) + kb);
            }
            #pragma unroll
            for (int p = 0; p < 4; p++)
                ldsm4(&bH[4 * p], bBase + p * (16 * ROWB) + kb);
            #pragma unroll
            for (int mt = 0; mt < 4; mt++)
                #pragma unroll
                for (int ntl = 0; ntl < 8; ntl++)
                    mma16816(acc[mt][ntl], &aH[4 * mt], &bH[2 * ntl]);
            #pragma unroll
            for (int mt = 0; mt < 4; mt++)
                #pragma unroll
                for (int ntl = 0; ntl < 8; ntl++)
                    mma16816(acc[mt][ntl], &aL[4 * mt], &bH[2 * ntl]);
        }
        __syncthreads();
    }

    int m_base = m0 + warp_m * 64 + (lane >> 2);
    int n_base = n0 + warp_n * 64 + ((lane & 3) << 1);
    #pragma unroll
    for (int mt = 0; mt < 4; mt++) {
        #pragma unroll
        for (int ntl = 0; ntl < 8; ntl++) {
            int n = n_base + ntl * 8;
            float b0 = bias[n], b1 = bias[n + 1];
            #pragma unroll
            for (int rr = 0; rr < 2; rr++) {
                int m = m_base + mt * 16 + rr * 8;
                size_t ob = (size_t)m * Nfull + n;
                float v0 = acc[mt][ntl][2 * rr]     + b0;
                float v1 = acc[mt][ntl][2 * rr + 1] + b1;
                if (EPI == 0) {
                    *(float2*)(outf + ob) = make_float2(v0, v1);
                } else if (EPI == 2) {
                    float2 rv = *(const float2*)(res + ob);
                    *(float2*)(outf + ob) = make_float2(v0 + rv.x, v1 + rv.y);
                } else {
                    float g0 = gelu_exact(v0), g1 = gelu_exact(v1);
                    f16 h0, l0, h1, l1;
                    split_f16(g0, h0, l0); split_f16(g1, h1, l1);
                    *(__half2*)(outh + ob) = __halves2half2(h0, h1);
                    *(__half2*)(outl + ob) = __halves2half2(l0, l1);
                }
            }
        }
    }
}

// ---------------- tensor-core flash attention (fp16 hi/lo, fp32 softmax) -----------
// 128 threads = 4 warps; warp w owns query rows [qt*64 + w*16, +16).
// K tiles of 32 keys. Scores/P in registers; P->A-frag conversion in-register.
#define QSTR 72     // halves per Q/K row (64 + 8 pad) -> 144B stride
#define VSTR 40     // halves per V^T row (32 + 8 pad) -> 80B stride

__global__ __launch_bounds__(128)
void attn_kernel(const float* __restrict__ qkv, const char* __restrict__ mask,
                 f16* __restrict__ outh, f16* __restrict__ outl) {
    __shared__ f16 sQh[64 * QSTR], sQl[64 * QSTR];
    __shared__ f16 sKh[32 * QSTR], sKl[32 * QSTR];
    __shared__ f16 sVh[64 * VSTR], sVl[64 * VSTR];   // V^T: [dim][key]
    __shared__ char Ms[32];

    int qt = blockIdx.x, h = blockIdx.y, b = blockIdx.z;
    int tid = threadIdx.x;
    int wid = tid >> 5, lane = tid & 31;
    int grp = lane >> 2, qd = lane & 3;

    // ---- load Q (64x64), scale by 1/8, split hi/lo ----
    {
        int row = tid >> 1;
        int c0 = (tid & 1) * 32;
        const float* g = qkv + ((size_t)(b * T_ + qt * 64 + row)) * D3_ + h * DH_ + c0;
        #pragma unroll
        for (int u = 0; u < 8; u++) {
            float4 v = *(const float4*)(g + u * 4);
            v.x *= 0.125f; v.y *= 0.125f; v.z *= 0.125f; v.w *= 0.125f;
            f16 h0, l0, h1, l1, h2, l2, h3, l3;
            split_f16(v.x, h0, l0); split_f16(v.y, h1, l1);
            split_f16(v.z, h2, l2); split_f16(v.w, h3, l3);
            int o = row * QSTR + c0 + u * 4;
            *(__half2*)&sQh[o]     = __halves2half2(h0, h1);
            *(__half2*)&sQh[o + 2] = __halves2half2(h2, h3);
            *(__half2*)&sQl[o]     = __halves2half2(l0, l1);
            *(__half2*)&sQl[o + 2] = __halves2half2(l2, l3);
        }
    }

    float O[8][4];
    #pragma unroll
    for (int nf = 0; nf < 8; nf++)
        #pragma unroll
        for (int r = 0; r < 4; r++) O[nf][r] = 0.f;
    float m_a = -INFINITY, m_b = -INFINITY, l_a = 0.f, l_b = 0.f;

    uint32_t aAddrH = smem_u32(sQh) + (wid * 16 + (lane & 15)) * (QSTR * 2) + ((lane >> 4) << 4);
    uint32_t aAddrL = smem_u32(sQl) + (wid * 16 + (lane & 15)) * (QSTR * 2) + ((lane >> 4) << 4);
    int bRow  = (lane & 7) + ((lane & 16) >> 1);
    int bColB = (lane & 8) << 1;
    uint32_t kAddrH = smem_u32(sKh) + bRow * (QSTR * 2) + bColB;
    uint32_t kAddrL = smem_u32(sKl) + bRow * (QSTR * 2) + bColB;
    uint32_t vAddrH = smem_u32(sVh) + bRow * (VSTR * 2) + bColB;
    uint32_t vAddrL = smem_u32(sVl) + bRow * (VSTR * 2) + bColB;

    int q_a = qt * 64 + wid * 16 + grp;
    int q_b = q_a + 8;

    int ktmax = (qt + 1) * 2;
    for (int kt = 0; kt < ktmax; kt++) {
        __syncthreads();
        // ---- fill K (row-major) and V^T, fp16 hi/lo ----
        {
            int j  = tid >> 2;
            int d0 = (tid & 3) * 16;
            const float* gk = qkv + ((size_t)(b * T_ + kt * 32 + j)) * D3_ + D_ + h * DH_ + d0;
            const float* gv = gk + D_;
            #pragma unroll
            for (int u = 0; u < 4; u++) {
                float4 kv = *(const float4*)(gk + u * 4);
                f16 h0, l0, h1, l1, h2, l2, h3, l3;
                split_f16(kv.x, h0, l0); split_f16(kv.y, h1, l1);
                split_f16(kv.z, h2, l2); split_f16(kv.w, h3, l3);
                int o = j * QSTR + d0 + u * 4;
                *(__half2*)&sKh[o]     = __halves2half2(h0, h1);
                *(__half2*)&sKh[o + 2] = __halves2half2(h2, h3);
                *(__half2*)&sKl[o]     = __halves2half2(l0, l1);
                *(__half2*)&sKl[o + 2] = __halves2half2(l2, l3);
                float4 vv = *(const float4*)(gv + u * 4);
                f16 vh0, vl0, vh1, vl1, vh2, vl2, vh3, vl3;
                split_f16(vv.x, vh0, vl0); split_f16(vv.y, vh1, vl1);
                split_f16(vv.z, vh2, vl2); split_f16(vv.w, vh3, vl3);
                int d = d0 + u * 4;
                sVh[(d + 0) * VSTR + j] = vh0; sVl[(d + 0) * VSTR + j] = vl0;
                sVh[(d + 1) * VSTR + j] = vh1; sVl[(d + 1) * VSTR + j] = vl1;
                sVh[(d + 2) * VSTR + j] = vh2; sVl[(d + 2) * VSTR + j] = vl2;
                sVh[(d + 3) * VSTR + j] = vh3; sVl[(d + 3) * VSTR + j] = vl3;
            }
            if (tid < 32) Ms[tid] = mask[b * T_ + kt * 32 + tid];
        }
        __syncthreads();

        // ---- S = Q K^T (m16 x n32, k64) ----
        float S[4][4];
        #pragma unroll
        for (int f = 0; f < 4; f++)
            #pragma unroll
            for (int r = 0; r < 4; r++) S[f][r] = 0.f;
        #pragma unroll
        for (int kc = 0; kc < 4; kc++) {
            uint32_t qh[4], ql[4], kh[8], kl[8];
            ldsm4(qh, aAddrH + kc * 32);
            ldsm4(ql, aAddrL + kc * 32);
            ldsm4(&kh[0], kAddrH + kc * 32);
            ldsm4(&kh[4], kAddrH + 16 * (QSTR * 2) + kc * 32);
            ldsm4(&kl[0], kAddrL + kc * 32);
            ldsm4(&kl[4], kAddrL + 16 * (QSTR * 2) + kc * 32);
            #pragma unroll
            for (int f = 0; f < 4; f++) {
                mma16816(S[f], qh, &kh[2 * f]);
                mma16816(S[f], qh, &kl[2 * f]);
                mma16816(S[f], ql, &kh[2 * f]);
            }
        }

        // ---- mask + online softmax (rows a = grp, b = grp+8) ----
        float mt_a = -INFINITY, mt_b = -INFINITY;
        #pragma unroll
        for (int f = 0; f < 4; f++) {
            int ci = f * 8 + qd * 2;
            int gk0 = kt * 32 + ci, gk1 = gk0 + 1;
            bool ok0 = Ms[ci] != 0, ok1 = Ms[ci + 1] != 0;
            S[f][0] = (ok0 && gk0 <= q_a) ? S[f][0] : -INFINITY;
            S[f][1] = (ok1 && gk1 <= q_a) ? S[f][1] : -INFINITY;
            S[f][2] = (ok0 && gk0 <= q_b) ? S[f][2] : -INFINITY;
            S[f][3] = (ok1 && gk1 <= q_b) ? S[f][3] : -INFINITY;
            mt_a = fmaxf(mt_a, fmaxf(S[f][0], S[f][1]));
            mt_b = fmaxf(mt_b, fmaxf(S[f][2], S[f][3]));
        }
        mt_a = fmaxf(mt_a, __shfl_xor_sync(0xffffffffu, mt_a, 1));
        mt_a = fmaxf(mt_a, __shfl_xor_sync(0xffffffffu, mt_a, 2));
        mt_b = fmaxf(mt_b, __shfl_xor_sync(0xffffffffu, mt_b, 1));
        mt_b = fmaxf(mt_b, __shfl_xor_sync(0xffffffffu, mt_b, 2));
        float mn_a = fmaxf(m_a, mt_a), mn_b = fmaxf(m_b, mt_b);
        float al_a, al_b, ps_a = 0.f, ps_b = 0.f;
        if (mn_a == -INFINITY) {
            al_a = 1.f;
            #pragma unroll
            for (int f = 0; f < 4; f++) { S[f][0] = 0.f; S[f][1] = 0.f; }
        } else {
            al_a = expf(m_a - mn_a);
            #pragma unroll
            for (int f = 0; f < 4; f++) {
                S[f][0] = expf(S[f][0] - mn_a);
                S[f][1] = expf(S[f][1] - mn_a);
                ps_a += S[f][0] + S[f][1];
            }
        }
        if (mn_b == -INFINITY) {
            al_b = 1.f;
            #pragma unroll
            for (int f = 0; f < 4; f++) { S[f][2] = 0.f; S[f][3] = 0.f; }
        } else {
            al_b = expf(m_b - mn_b);
            #pragma unroll
            for (int f = 0; f < 4; f++) {
                S[f][2] = expf(S[f][2] - mn_b);
                S[f][3] = expf(S[f][3] - mn_b);
                ps_b += S[f][2] + S[f][3];
            }
        }
        ps_a += __shfl_xor_sync(0xffffffffu, ps_a, 1);
        ps_a += __shfl_xor_sync(0xffffffffu, ps_a, 2);
        ps_b += __shfl_xor_sync(0xffffffffu, ps_b, 1);
        ps_b += __shfl_xor_sync(0xffffffffu, ps_b, 2);
        l_a = l_a * al_a + ps_a;
        l_b = l_b * al_b + ps_b;
        m_a = mn_a; m_b = mn_b;
        #pragma unroll
        for (int nf = 0; nf < 8; nf++) {
            O[nf][0] *= al_a; O[nf][1] *= al_a;
            O[nf][2] *= al_b; O[nf][3] *= al_b;
        }

        // ---- O += P V  (P in registers -> A-frags) ----
        #pragma unroll
        for (int kc = 0; kc < 2; kc++) {
            int f0 = 2 * kc, f1 = 2 * kc + 1;
            f16 h00, l00, h01, l01, h02, l02, h03, l03;
            f16 h10, l10, h11, l11, h12, l12, h13, l13;
            split_f16(S[f0][0], h00, l00); split_f16(S[f0][1], h01, l01);
            split_f16(S[f0][2], h02, l02); split_f16(S[f0][3], h03, l03);
            split_f16(S[f1][0], h10, l10); split_f16(S[f1][1], h11, l11);
            split_f16(S[f1][2], h12, l12); split_f16(S[f1][3], h13, l13);
            uint32_t pah[4], pal[4];
            pah[0] = pack_h2(h00, h01); pal[0] = pack_h2(l00, l01);
            pah[1] = pack_h2(h02, h03); pal[1] = pack_h2(l02, l03);
            pah[2] = pack_h2(h10, h11); pal[2] = pack_h2(l10, l11);
            pah[3] = pack_h2(h12, h13); pal[3] = pack_h2(l12, l13);
            uint32_t vh[16], vl[16];
            #pragma unroll
            for (int p4 = 0; p4 < 4; p4++) {
                ldsm4(&vh[4 * p4], vAddrH + p4 * 16 * (VSTR * 2) + kc * 32);
                ldsm4(&vl[4 * p4], vAddrL + p4 * 16 * (VSTR * 2) + kc * 32);
            }
            #pragma unroll
            for (int nf = 0; nf < 8; nf++) {
                mma16816(O[nf], pah, &vh[2 * nf]);
                mma16816(O[nf], pah, &vl[2 * nf]);
                mma16816(O[nf], pal, &vh[2 * nf]);
            }
        }
    }

    // ---- normalize + write fp16 hi/lo ----
    float rl_a = (l_a > 0.f) ? (1.f / l_a) : 0.f;
    float rl_b = (l_b > 0.f) ? (1.f / l_b) : 0.f;
    size_t rowA = (size_t)(b * T_) + qt * 64 + wid * 16 + grp;
    size_t rowB = rowA + 8;
    #pragma unroll
    for (int nf = 0; nf < 8; nf++) {
        int col = h * DH_ + nf * 8 + qd * 2;
        float v0 = O[nf][0] * rl_a, v1 = O[nf][1] * rl_a;
        float v2 = O[nf][2] * rl_b, v3 = O[nf][3] * rl_b;
        f16 h0, l0, h1, l1, h2, l2, h3, l3;
        split_f16(v0, h0, l0); split_f16(v1, h1, l1);
        split_f16(v2, h2, l2); split_f16(v3, h3, l3);
        *(__half2*)(outh + rowA * D_ + col) = __halves2half2(h0, h1);
        *(__half2*)(outl + rowA * D_ + col) = __halves2half2(l0, l1);
        *(__half2*)(outh + rowB * D_ + col) = __halves2half2(h2, h3);
        *(__half2*)(outl + rowB * D_ + col) = __halves2half2(l2, l3);
    }
}

// ---------------- head ----------------
__global__ void head_kernel(const float* __restrict__ xn, const int* __restrict__ lastidx,
                            const float* __restrict__ hw, const float* __restrict__ hb,
                            float* __restrict__ out) {
    int b = blockIdx.x;
    int w = threadIdx.x >> 5;
    int lane = threadIdx.x & 31;
    const float* h = xn + ((size_t)(b * T_ + lastidx[b])) * D_;
    float s = 0.f;
    for (int d = lane; d < D_; d += 32) s += h[d] * hw[d * 9 + w];
    #pragma unroll
    for (int o = 16; o; o >>= 1) s += __shfl_down_sync(0xffffffffu, s, o);
    if (lane == 0) out[b * 9 + w] = s + hb[w];
}

// ---------------- orchestration ----------------
extern "C" void kernel_launch(void* const* d_in, const int* in_sizes, int n_in,
                              void* d_out, int out_size) {
    const int*   cards   = (const int*)  d_in[0];
    const int*   players = (const int*)  d_in[1];
    const int*   deck    = (const int*)  d_in[2];
    const int*   opp     = (const int*)  d_in[3];
    const float* tok     = (const float*)d_in[4];
    const float* pemb    = (const float*)d_in[5];
    const float* pos     = (const float*)d_in[6];
    const float* ln1s = (const float*)d_in[9];
    const float* ln1b = (const float*)d_in[10];
    const float* qkvw = (const float*)d_in[11];
    const float* qkvb = (const float*)d_in[12];
    const float* projw = (const float*)d_in[13];
    const float* projb = (const float*)d_in[14];
    const float* ln2s = (const float*)d_in[15];
    const float* ln2b = (const float*)d_in[16];
    const float* fc1w = (const float*)d_in[17];
    const float* fc1b = (const float*)d_in[18];
    const float* fc2w = (const float*)d_in[19];
    const float* fc2b = (const float*)d_in[20];
    const float* lnfs = (const float*)d_in[21];
    const float* lnfb = (const float*)d_in[22];
    const float* headw = (const float*)d_in[23];
    const float* headb = (const float*)d_in[24];

    float *x, *xn, *qkv, *dm;
    f16 *xh, *xl, *yh, *yl, *hh, *hl;
    f16 *qT, *pT, *f1T, *f2T;
    char* mask; int* lastidx;
    cudaGetSymbolAddress((void**)&x,    g_x);
    cudaGetSymbolAddress((void**)&xn,   g_xn);
    cudaGetSymbolAddress((void**)&qkv,  g_qkv);
    cudaGetSymbolAddress((void**)&dm,   g_dm);
    cudaGetSymbolAddress((void**)&xh,   g_xh);
    cudaGetSymbolAddress((void**)&xl,   g_xl);
    cudaGetSymbolAddress((void**)&yh,   g_yh);
    cudaGetSymbolAddress((void**)&yl,   g_yl);
    cudaGetSymbolAddress((void**)&hh,   g_hh);
    cudaGetSymbolAddress((void**)&hl,   g_hl);
    cudaGetSymbolAddress((void**)&qT,   g_qkvT);
    cudaGetSymbolAddress((void**)&pT,   g_projT);
    cudaGetSymbolAddress((void**)&f1T,  g_fc1T);
    cudaGetSymbolAddress((void**)&f2T,  g_fc2T);
    cudaGetSymbolAddress((void**)&mask, g_mask);
    cudaGetSymbolAddress((void**)&lastidx, g_lastidx);

    cudaFuncSetAttribute(gemm_mma<0>, cudaFuncAttributeMaxDynamicSharedMemorySize, GEMM_SMEM);
    cudaFuncSetAttribute(gemm_mma<1>, cudaFuncAttributeMaxDynamicSharedMemorySize, GEMM_SMEM);
    cudaFuncSetAttribute(gemm_mma<2>, cudaFuncAttributeMaxDynamicSharedMemorySize, GEMM_SMEM);

    dim3 tb(32, 8);
    transpose_all<<<TFC2, tb>>>(qkvw, projw, fc1w, fc2w, qT, pT, f1T, f2T);
    mask_kernel<<<B_, T_>>>(cards, mask, lastidx);
    deckmean_kernel<<<B_, D_>>>(deck, opp, tok, dm);
    embed_kernel<<<BT_, 256>>>(cards, players, tok, pemb, pos, dm, x);

    for (int i = 0; i < L_; i++) {
        ln_kernel<true><<<BT_, 256>>>(x, ln1s + i * D_, ln1b + i * D_, nullptr, xh, xl);
        gemm_mma<0><<<dim3(D3_ / 256, BT_ / 128), 256, GEMM_SMEM>>>(
            xh, xl, qT + (size_t)i * D3_ * D_,
            qkvb + i * D3_, nullptr, qkv, nullptr, nullptr, D_, D3_);
        attn_kernel<<<dim3(T_ / 64, NH_, B_), 128>>>(qkv, mask, yh, yl);
        gemm_mma<2><<<dim3(D_ / 256, BT_ / 128), 256, GEMM_SMEM>>>(
            yh, yl, pT + (size_t)i * D_ * D_,
            projb + i * D_, x, x, nullptr, nullptr, D_, D_);
        ln_kernel<true><<<BT_, 256>>>(x, ln2s + i * D_, ln2b + i * D_, nullptr, xh, xl);
        gemm_mma<1><<<dim3(D4_ / 256, BT_ / 128), 256, GEMM_SMEM>>>(
            xh, xl, f1T + (size_t)i * D4_ * D_,
            fc1b + i * D4_, nullptr, nullptr, hh, hl, D_, D4_);
        gemm_mma<2><<<dim3(D_ / 256, BT_ / 128), 256, GEMM_SMEM>>>(
            hh, hl, f2T + (size_t)i * D_ * D4_,
            fc2b + i * D_, x, x, nullptr, nullptr, D4_, D_);
    }

    ln_kernel<false><<<BT_, 256>>>(x, lnfs, lnfb, xn, nullptr, nullptr);
    head_kernel<<<B_, 288>>>(xn, lastidx, headw, headb, (float*)d_out);
}

// round 10
// speedup vs baseline: 3.0940x; 1.4535x over previous
#include <cuda_runtime.h>
#include <cuda_fp16.h>
#include <math.h>
#include <stdint.h>

typedef __half f16;

// ---------------- problem constants ----------------
#define L_   6
#define D_   768
#define NH_  12
#define DH_  64
#define T_   512
#define B_   16
#define BT_  (B_ * T_)       // 8192
#define D3_  (3 * D_)        // 2304
#define D4_  (4 * D_)        // 3072

// ---------------- scratch ----------------
__device__ __align__(128) float g_x  [BT_ * D_];
__device__ __align__(128) float g_xn [BT_ * D_];
__device__ __align__(128) float g_qkv[BT_ * D3_];
__device__ __align__(128) f16   g_xh [BT_ * D_];
__device__ __align__(128) f16   g_yh [BT_ * D_];
__device__ __align__(128) f16   g_hh [BT_ * D4_];
__device__ __align__(128) float g_dm [B_ * D_];
__device__ char  g_mask[B_ * T_];
__device__ int   g_lastidx[B_];

__device__ __align__(128) f16 g_qkvT [L_ * D3_ * D_];
__device__ __align__(128) f16 g_projT[L_ * D_ * D_];
__device__ __align__(128) f16 g_fc1T [L_ * D4_ * D_];
__device__ __align__(128) f16 g_fc2T [L_ * D_ * D4_];

// ---------------- PTX helpers ----------------
__device__ __forceinline__ uint32_t smem_u32(const void* p) {
    uint32_t a;
    asm("{ .reg .u64 t; cvta.to.shared.u64 t, %1; cvt.u32.u64 %0, t; }" : "=r"(a) : "l"(p));
    return a;
}
__device__ __forceinline__ void cp16(uint32_t s, const void* g) {
    asm volatile("cp.async.cg.shared.global [%0], [%1], 16;" :: "r"(s), "l"(g) : "memory");
}
__device__ __forceinline__ void ldsm4(uint32_t* r, uint32_t addr) {
    asm volatile("ldmatrix.sync.aligned.m8n8.x4.shared.b16 {%0,%1,%2,%3}, [%4];"
                 : "=r"(r[0]), "=r"(r[1]), "=r"(r[2]), "=r"(r[3]) : "r"(addr));
}
__device__ __forceinline__ void mma16816(float* c, const uint32_t* a, const uint32_t* b) {
    asm volatile(
        "mma.sync.aligned.m16n8k16.row.col.f32.f16.f16.f32 "
        "{%0,%1,%2,%3}, {%4,%5,%6,%7}, {%8,%9}, {%0,%1,%2,%3};"
        : "+f"(c[0]), "+f"(c[1]), "+f"(c[2]), "+f"(c[3])
        : "r"(a[0]), "r"(a[1]), "r"(a[2]), "r"(a[3]), "r"(b[0]), "r"(b[1]));
}
__device__ __forceinline__ float gelu_exact(float v) {
    return 0.5f * v * (1.0f + erff(v * 0.70710678118654752440f));
}
__device__ __forceinline__ void split_f16(float v, f16& h, f16& l) {
    h = __float2half_rn(v);
    l = __float2half_rn(v - __half2float(h));
}
__device__ __forceinline__ uint32_t pack_h2(f16 a, f16 b) {
    __half2 t = __halves2half2(a, b);
    return *(uint32_t*)&t;
}

// ---------------- fused weight transpose + fp16 round ----------------
#define TQKV (L_ * 1728)
#define TPROJ (TQKV + L_ * 576)
#define TFC1 (TPROJ + L_ * 2304)
#define TFC2 (TFC1 + L_ * 2304)

__global__ void transpose_all(const float* __restrict__ qkvw, const float* __restrict__ projw,
                              const float* __restrict__ fc1w, const float* __restrict__ fc2w,
                              f16* __restrict__ qT, f16* __restrict__ pT,
                              f16* __restrict__ f1T, f16* __restrict__ f2T) {
    __shared__ float tile[32][33];
    int idx = blockIdx.x;
    const float* W; f16* Th; int K, N, rem;
    if (idx < TQKV) {
        int layer = idx / 1728; rem = idx % 1728;
        K = D_; N = D3_;
        W = qkvw + (size_t)layer * D_ * D3_;
        Th = qT + (size_t)layer * D3_ * D_;
    } else if (idx < TPROJ) {
        idx -= TQKV;
        int layer = idx / 576; rem = idx % 576;
        K = D_; N = D_;
        W = projw + (size_t)layer * D_ * D_;
        Th = pT + (size_t)layer * D_ * D_;
    } else if (idx < TFC1) {
        idx -= TPROJ;
        int layer = idx / 2304; rem = idx % 2304;
        K = D_; N = D4_;
        W = fc1w + (size_t)layer * D_ * D4_;
        Th = f1T + (size_t)layer * D4_ * D_;
    } else {
        idx -= TFC1;
        int layer = idx / 2304; rem = idx % 2304;
        K = D4_; N = D_;
        W = fc2w + (size_t)layer * D4_ * D_;
        Th = f2T + (size_t)layer * D_ * D4_;
    }
    int tilesN = N >> 5;
    int n0 = (rem % tilesN) << 5;
    int k0 = (rem / tilesN) << 5;
    int tx = threadIdx.x, ty = threadIdx.y;
    #pragma unroll
    for (int i = 0; i < 32; i += 8)
        tile[ty + i][tx] = W[(size_t)(k0 + ty + i) * N + n0 + tx];
    __syncthreads();
    #pragma unroll
    for (int i = 0; i < 32; i += 8) {
        float v = tile[tx][ty + i];
        Th[(size_t)(n0 + ty + i) * K + k0 + tx] = __float2half_rn(v);
    }
}

// ---------------- mask + last_idx ----------------
__global__ void mask_kernel(const int* __restrict__ cards,
                            char* __restrict__ mask, int* __restrict__ lastidx) {
    int b = blockIdx.x;
    int t = threadIdx.x;
    bool valid = cards[b * T_ + t] != 0;
    bool any = __syncthreads_or(valid);
    bool m = valid || (t == 0 && !any);
    mask[b * T_ + t] = m ? 1 : 0;
    int cnt = __syncthreads_count(m);
    if (t == 0) lastidx[b] = (cnt - 1) > 0 ? (cnt - 1) : 0;
}

// ---------------- deck means ----------------
__global__ void deckmean_kernel(const int* __restrict__ deck, const int* __restrict__ opp,
                                const float* __restrict__ tok, float* __restrict__ dm) {
    int b = blockIdx.x;
    int d = threadIdx.x;
    float s = 0.f;
    #pragma unroll
    for (int i = 0; i < 8; i++) {
        s += tok[(size_t)deck[b * 8 + i] * D_ + d];
        s += tok[(size_t)opp [b * 8 + i] * D_ + d];
    }
    dm[b * D_ + d] = s * 0.125f;
}

// ---------------- embedding sum ----------------
__global__ void embed_kernel(const int* __restrict__ cards, const int* __restrict__ players,
                             const float* __restrict__ tok, const float* __restrict__ pemb,
                             const float* __restrict__ pos, const float* __restrict__ dm,
                             float* __restrict__ x) {
    int bt = blockIdx.x;
    int b = bt >> 9;
    int t = bt & 511;
    int card = cards[bt];
    int pl = players[bt]; pl = pl < 0 ? 0 : (pl > 1 ? 1 : pl);
    const float* tr = tok  + (size_t)card * D_;
    const float* pr = pemb + (size_t)pl * D_;
    const float* qr = pos  + (size_t)t * D_;
    const float* mr = dm   + (size_t)b * D_;
    float* xr = x + (size_t)bt * D_;
    for (int d = threadIdx.x; d < D_; d += 256)
        xr[d] = tr[d] + pr[d] + mr[d] + qr[d];
}

// ---------------- layernorm -> fp16 (or fp32 for final) ----------------
template<bool TOH>
__global__ void ln_kernel(const float* __restrict__ x, const float* __restrict__ g,
                          const float* __restrict__ be, float* __restrict__ of,
                          f16* __restrict__ oh) {
    __shared__ float sh1[8], sh2[8];
    int r = blockIdx.x;
    size_t base = (size_t)r * D_;
    int t = threadIdx.x;
    float v0 = x[base + t], v1 = x[base + t + 256], v2 = x[base + t + 512];
    float s = v0 + v1 + v2;
    float q = v0 * v0 + v1 * v1 + v2 * v2;
    #pragma unroll
    for (int o2 = 16; o2; o2 >>= 1) {
        s += __shfl_xor_sync(0xffffffffu, s, o2);
        q += __shfl_xor_sync(0xffffffffu, q, o2);
    }
    if ((t & 31) == 0) { sh1[t >> 5] = s; sh2[t >> 5] = q; }
    __syncthreads();
    s = sh1[t & 7]; q = sh2[t & 7];
    #pragma unroll
    for (int o2 = 4; o2; o2 >>= 1) {
        s += __shfl_xor_sync(0xffffffffu, s, o2);
        q += __shfl_xor_sync(0xffffffffu, q, o2);
    }
    float mean = s * (1.0f / D_);
    float var  = q * (1.0f / D_) - mean * mean;
    float rstd = rsqrtf(var + 1e-5f);
    #pragma unroll
    for (int u = 0; u < 3; u++) {
        int d = t + u * 256;
        float v = (u == 0 ? v0 : (u == 1 ? v1 : v2));
        float o = (v - mean) * rstd * g[d] + be[d];
        if (TOH) oh[base + d] = __float2half_rn(o);
        else     of[base + d] = o;
    }
}

// ---------------- mma.sync fp16 GEMM (single pass), 128x256 tiles ----------------
#define ROWB 80
#define A_OFF 0
#define B_OFF (128 * ROWB)                 // 10240
#define STAGE_BYTES (B_OFF + 256 * ROWB)   // 30720
#define GEMM_SMEM (2 * STAGE_BYTES)        // 61440

template<int EPI>
__global__ __launch_bounds__(256, 1)
void gemm_mma(const f16* __restrict__ Ah, const f16* __restrict__ Bh,
              const float* __restrict__ bias, const float* __restrict__ res,
              float* __restrict__ outf, f16* __restrict__ outh,
              int K, int Nfull) {
    extern __shared__ char dsm[];
    uint32_t tiles = smem_u32(dsm);

    int tid = threadIdx.x;
    int wid = tid >> 5;
    int lane = tid & 31;
    int warp_m = wid & 1;
    int warp_n = wid >> 1;
    int m0 = blockIdx.y * 128;
    int n0 = blockIdx.x * 256;
    int nt = K >> 5;

    int aRow  = lane & 15;
    int aColB = (lane >> 4) << 4;
    int bRow  = (lane & 7) + ((lane & 16) >> 1);
    int bColB = (lane & 8) << 1;

    float acc[4][8][4];
    #pragma unroll
    for (int mt = 0; mt < 4; mt++)
        #pragma unroll
        for (int ntl = 0; ntl < 8; ntl++)
            #pragma unroll
            for (int r = 0; r < 4; r++) acc[mt][ntl][r] = 0.f;

    auto load_stage = [&](int kt, int st) {
        uint32_t sb = tiles + st * STAGE_BYTES;
        int k0 = kt << 5;
        #pragma unroll
        for (int i = 0; i < 2; i++) {                    // A: 128 rows x 4 chunks
            int id = tid + (i << 8);
            int r = id >> 2, c = id & 3;
            size_t go = (size_t)(m0 + r) * K + k0 + (c << 3);
            cp16(sb + A_OFF + r * ROWB + (c << 4), Ah + go);
        }
        #pragma unroll
        for (int i = 0; i < 4; i++) {                    // B: 256 rows x 4 chunks
            int id = tid + (i << 8);
            int r = id >> 2, c = id & 3;
            size_t go = (size_t)(n0 + r) * K + k0 + (c << 3);
            cp16(sb + B_OFF + r * ROWB + (c << 4), Bh + go);
        }
        asm volatile("cp.async.commit_group;" ::: "memory");
    };

    load_stage(0, 0);

    uint32_t aH[16], bH[16];

    for (int kt = 0; kt < nt; kt++) {
        int cur = kt & 1;
        if (kt + 1 < nt) {
            load_stage(kt + 1, cur ^ 1);
            asm volatile("cp.async.wait_group 1;" ::: "memory");
        } else {
            asm volatile("cp.async.wait_group 0;" ::: "memory");
        }
        __syncthreads();

        uint32_t sb = tiles + cur * STAGE_BYTES;
        uint32_t aBase = sb + (warp_m * 64 + aRow) * ROWB + aColB;
        uint32_t bBase = sb + B_OFF + (warp_n * 64 + bRow) * ROWB + bColB;

        #pragma unroll
        for (int ks = 0; ks < 2; ks++) {
            uint32_t kb = ks << 5;
            #pragma unroll
            for (int mt = 0; mt < 4; mt++)
                ldsm4(&aH[4 * mt], aBase + mt * (16 * ROWB) + kb);
            #pragma unroll
            for (int p = 0; p < 4; p++)
                ldsm4(&bH[4 * p], bBase + p * (16 * ROWB) + kb);
            #pragma unroll
            for (int mt = 0; mt < 4; mt++)
                #pragma unroll
                for (int ntl = 0; ntl < 8; ntl++)
                    mma16816(acc[mt][ntl], &aH[4 * mt], &bH[2 * ntl]);
        }
        __syncthreads();
    }

    int m_base = m0 + warp_m * 64 + (lane >> 2);
    int n_base = n0 + warp_n * 64 + ((lane & 3) << 1);
    #pragma unroll
    for (int mt = 0; mt < 4; mt++) {
        #pragma unroll
        for (int ntl = 0; ntl < 8; ntl++) {
            int n = n_base + ntl * 8;
            float b0 = bias[n], b1 = bias[n + 1];
            #pragma unroll
            for (int rr = 0; rr < 2; rr++) {
                int m = m_base + mt * 16 + rr * 8;
                size_t ob = (size_t)m * Nfull + n;
                float v0 = acc[mt][ntl][2 * rr]     + b0;
                float v1 = acc[mt][ntl][2 * rr + 1] + b1;
                if (EPI == 0) {
                    *(float2*)(outf + ob) = make_float2(v0, v1);
                } else if (EPI == 2) {
                    float2 rv = *(const float2*)(res + ob);
                    *(float2*)(outf + ob) = make_float2(v0 + rv.x, v1 + rv.y);
                } else {
                    float g0 = gelu_exact(v0), g1 = gelu_exact(v1);
                    *(__half2*)(outh + ob) =
                        __halves2half2(__float2half_rn(g0), __float2half_rn(g1));
                }
            }
        }
    }
}

// ---------------- tensor-core flash attention (fp16 hi/lo, fp32 softmax) -----------
#define QSTR 72
#define VSTR 40

__global__ __launch_bounds__(128)
void attn_kernel(const float* __restrict__ qkv, const char* __restrict__ mask,
                 f16* __restrict__ outh) {
    __shared__ f16 sQh[64 * QSTR], sQl[64 * QSTR];
    __shared__ f16 sKh[32 * QSTR], sKl[32 * QSTR];
    __shared__ f16 sVh[64 * VSTR], sVl[64 * VSTR];
    __shared__ char Ms[32];

    int qt = blockIdx.x, h = blockIdx.y, b = blockIdx.z;
    int tid = threadIdx.x;
    int wid = tid >> 5, lane = tid & 31;
    int grp = lane >> 2, qd = lane & 3;

    {
        int row = tid >> 1;
        int c0 = (tid & 1) * 32;
        const float* g = qkv + ((size_t)(b * T_ + qt * 64 + row)) * D3_ + h * DH_ + c0;
        #pragma unroll
        for (int u = 0; u < 8; u++) {
            float4 v = *(const float4*)(g + u * 4);
            v.x *= 0.125f; v.y *= 0.125f; v.z *= 0.125f; v.w *= 0.125f;
            f16 h0, l0, h1, l1, h2, l2, h3, l3;
            split_f16(v.x, h0, l0); split_f16(v.y, h1, l1);
            split_f16(v.z, h2, l2); split_f16(v.w, h3, l3);
            int o = row * QSTR + c0 + u * 4;
            *(__half2*)&sQh[o]     = __halves2half2(h0, h1);
            *(__half2*)&sQh[o + 2] = __halves2half2(h2, h3);
            *(__half2*)&sQl[o]     = __halves2half2(l0, l1);
            *(__half2*)&sQl[o + 2] = __halves2half2(l2, l3);
        }
    }

    float O[8][4];
    #pragma unroll
    for (int nf = 0; nf < 8; nf++)
        #pragma unroll
        for (int r = 0; r < 4; r++) O[nf][r] = 0.f;
    float m_a = -INFINITY, m_b = -INFINITY, l_a = 0.f, l_b = 0.f;

    uint32_t aAddrH = smem_u32(sQh) + (wid * 16 + (lane & 15)) * (QSTR * 2) + ((lane >> 4) << 4);
    uint32_t aAddrL = smem_u32(sQl) + (wid * 16 + (lane & 15)) * (QSTR * 2) + ((lane >> 4) << 4);
    int bRow  = (lane & 7) + ((lane & 16) >> 1);
    int bColB = (lane & 8) << 1;
    uint32_t kAddrH = smem_u32(sKh) + bRow * (QSTR * 2) + bColB;
    uint32_t kAddrL = smem_u32(sKl) + bRow * (QSTR * 2) + bColB;
    uint32_t vAddrH = smem_u32(sVh) + bRow * (VSTR * 2) + bColB;
    uint32_t vAddrL = smem_u32(sVl) + bRow * (VSTR * 2) + bColB;

    int q_a = qt * 64 + wid * 16 + grp;
    int q_b = q_a + 8;

    int ktmax = (qt + 1) * 2;
    for (int kt = 0; kt < ktmax; kt++) {
        __syncthreads();
        {
            int j  = tid >> 2;
            int d0 = (tid & 3) * 16;
            const float* gk = qkv + ((size_t)(b * T_ + kt * 32 + j)) * D3_ + D_ + h * DH_ + d0;
            const float* gv = gk + D_;
            #pragma unroll
            for (int u = 0; u < 4; u++) {
                float4 kv = *(const float4*)(gk + u * 4);
                f16 h0, l0, h1, l1, h2, l2, h3, l3;
                split_f16(kv.x, h0, l0); split_f16(kv.y, h1, l1);
                split_f16(kv.z, h2, l2); split_f16(kv.w, h3, l3);
                int o = j * QSTR + d0 + u * 4;
                *(__half2*)&sKh[o]     = __halves2half2(h0, h1);
                *(__half2*)&sKh[o + 2] = __halves2half2(h2, h3);
                *(__half2*)&sKl[o]     = __halves2half2(l0, l1);
                *(__half2*)&sKl[o + 2] = __halves2half2(l2, l3);
                float4 vv = *(const float4*)(gv + u * 4);
                f16 vh0, vl0, vh1, vl1, vh2, vl2, vh3, vl3;
                split_f16(vv.x, vh0, vl0); split_f16(vv.y, vh1, vl1);
                split_f16(vv.z, vh2, vl2); split_f16(vv.w, vh3, vl3);
                int d = d0 + u * 4;
                sVh[(d + 0) * VSTR + j] = vh0; sVl[(d + 0) * VSTR + j] = vl0;
                sVh[(d + 1) * VSTR + j] = vh1; sVl[(d + 1) * VSTR + j] = vl1;
                sVh[(d + 2) * VSTR + j] = vh2; sVl[(d + 2) * VSTR + j] = vl2;
                sVh[(d + 3) * VSTR + j] = vh3; sVl[(d + 3) * VSTR + j] = vl3;
            }
            if (tid < 32) Ms[tid] = mask[b * T_ + kt * 32 + tid];
        }
        __syncthreads();

        float S[4][4];
        #pragma unroll
        for (int f = 0; f < 4; f++)
            #pragma unroll
            for (int r = 0; r < 4; r++) S[f][r] = 0.f;
        #pragma unroll
        for (int kc = 0; kc < 4; kc++) {
            uint32_t qh[4], ql[4], kh[8], kl[8];
            ldsm4(qh, aAddrH + kc * 32);
            ldsm4(ql, aAddrL + kc * 32);
            ldsm4(&kh[0], kAddrH + kc * 32);
            ldsm4(&kh[4], kAddrH + 16 * (QSTR * 2) + kc * 32);
            ldsm4(&kl[0], kAddrL + kc * 32);
            ldsm4(&kl[4], kAddrL + 16 * (QSTR * 2) + kc * 32);
            #pragma unroll
            for (int f = 0; f < 4; f++) {
                mma16816(S[f], qh, &kh[2 * f]);
                mma16816(S[f], qh, &kl[2 * f]);
                mma16816(S[f], ql, &kh[2 * f]);
            }
        }

        float mt_a = -INFINITY, mt_b = -INFINITY;
        #pragma unroll
        for (int f = 0; f < 4; f++) {
            int ci = f * 8 + qd * 2;
            int gk0 = kt * 32 + ci, gk1 = gk0 + 1;
            bool ok0 = Ms[ci] != 0, ok1 = Ms[ci + 1] != 0;
            S[f][0] = (ok0 && gk0 <= q_a) ? S[f][0] : -INFINITY;
            S[f][1] = (ok1 && gk1 <= q_a) ? S[f][1] : -INFINITY;
            S[f][2] = (ok0 && gk0 <= q_b) ? S[f][2] : -INFINITY;
            S[f][3] = (ok1 && gk1 <= q_b) ? S[f][3] : -INFINITY;
            mt_a = fmaxf(mt_a, fmaxf(S[f][0], S[f][1]));
            mt_b = fmaxf(mt_b, fmaxf(S[f][2], S[f][3]));
        }
        mt_a = fmaxf(mt_a, __shfl_xor_sync(0xffffffffu, mt_a, 1));
        mt_a = fmaxf(mt_a, __shfl_xor_sync(0xffffffffu, mt_a, 2));
        mt_b = fmaxf(mt_b, __shfl_xor_sync(0xffffffffu, mt_b, 1));
        mt_b = fmaxf(mt_b, __shfl_xor_sync(0xffffffffu, mt_b, 2));
        float mn_a = fmaxf(m_a, mt_a), mn_b = fmaxf(m_b, mt_b);
        float al_a, al_b, ps_a = 0.f, ps_b = 0.f;
        if (mn_a == -INFINITY) {
            al_a = 1.f;
            #pragma unroll
            for (int f = 0; f < 4; f++) { S[f][0] = 0.f; S[f][1] = 0.f; }
        } else {
            al_a = expf(m_a - mn_a);
            #pragma unroll
            for (int f = 0; f < 4; f++) {
                S[f][0] = expf(S[f][0] - mn_a);
                S[f][1] = expf(S[f][1] - mn_a);
                ps_a += S[f][0] + S[f][1];
            }
        }
        if (mn_b == -INFINITY) {
            al_b = 1.f;
            #pragma unroll
            for (int f = 0; f < 4; f++) { S[f][2] = 0.f; S[f][3] = 0.f; }
        } else {
            al_b = expf(m_b - mn_b);
            #pragma unroll
            for (int f = 0; f < 4; f++) {
                S[f][2] = expf(S[f][2] - mn_b);
                S[f][3] = expf(S[f][3] - mn_b);
                ps_b += S[f][2] + S[f][3];
            }
        }
        ps_a += __shfl_xor_sync(0xffffffffu, ps_a, 1);
        ps_a += __shfl_xor_sync(0xffffffffu, ps_a, 2);
        ps_b += __shfl_xor_sync(0xffffffffu, ps_b, 1);
        ps_b += __shfl_xor_sync(0xffffffffu, ps_b, 2);
        l_a = l_a * al_a + ps_a;
        l_b = l_b * al_b + ps_b;
        m_a = mn_a; m_b = mn_b;
        #pragma unroll
        for (int nf = 0; nf < 8; nf++) {
            O[nf][0] *= al_a; O[nf][1] *= al_a;
            O[nf][2] *= al_b; O[nf][3] *= al_b;
        }

        #pragma unroll
        for (int kc = 0; kc < 2; kc++) {
            int f0 = 2 * kc, f1 = 2 * kc + 1;
            f16 h00, l00, h01, l01, h02, l02, h03, l03;
            f16 h10, l10, h11, l11, h12, l12, h13, l13;
            split_f16(S[f0][0], h00, l00); split_f16(S[f0][1], h01, l01);
            split_f16(S[f0][2], h02, l02); split_f16(S[f0][3], h03, l03);
            split_f16(S[f1][0], h10, l10); split_f16(S[f1][1], h11, l11);
            split_f16(S[f1][2], h12, l12); split_f16(S[f1][3], h13, l13);
            uint32_t pah[4], pal[4];
            pah[0] = pack_h2(h00, h01); pal[0] = pack_h2(l00, l01);
            pah[1] = pack_h2(h02, h03); pal[1] = pack_h2(l02, l03);
            pah[2] = pack_h2(h10, h11); pal[2] = pack_h2(l10, l11);
            pah[3] = pack_h2(h12, h13); pal[3] = pack_h2(l12, l13);
            uint32_t vh[16], vl[16];
            #pragma unroll
            for (int p4 = 0; p4 < 4; p4++) {
                ldsm4(&vh[4 * p4], vAddrH + p4 * 16 * (VSTR * 2) + kc * 32);
                ldsm4(&vl[4 * p4], vAddrL + p4 * 16 * (VSTR * 2) + kc * 32);
            }
            #pragma unroll
            for (int nf = 0; nf < 8; nf++) {
                mma16816(O[nf], pah, &vh[2 * nf]);
                mma16816(O[nf], pah, &vl[2 * nf]);
                mma16816(O[nf], pal, &vh[2 * nf]);
            }
        }
    }

    float rl_a = (l_a > 0.f) ? (1.f / l_a) : 0.f;
    float rl_b = (l_b > 0.f) ? (1.f / l_b) : 0.f;
    size_t rowA = (size_t)(b * T_) + qt * 64 + wid * 16 + grp;
    size_t rowB = rowA + 8;
    #pragma unroll
    for (int nf = 0; nf < 8; nf++) {
        int col = h * DH_ + nf * 8 + qd * 2;
        float v0 = O[nf][0] * rl_a, v1 = O[nf][1] * rl_a;
        float v2 = O[nf][2] * rl_b, v3 = O[nf][3] * rl_b;
        *(__half2*)(outh + rowA * D_ + col) =
            __halves2half2(__float2half_rn(v0), __float2half_rn(v1));
        *(__half2*)(outh + rowB * D_ + col) =
            __halves2half2(__float2half_rn(v2), __float2half_rn(v3));
    }
}

// ---------------- head ----------------
__global__ void head_kernel(const float* __restrict__ xn, const int* __restrict__ lastidx,
                            const float* __restrict__ hw, const float* __restrict__ hb,
                            float* __restrict__ out) {
    int b = blockIdx.x;
    int w = threadIdx.x >> 5;
    int lane = threadIdx.x & 31;
    const float* h = xn + ((size_t)(b * T_ + lastidx[b])) * D_;
    float s = 0.f;
    for (int d = lane; d < D_; d += 32) s += h[d] * hw[d * 9 + w];
    #pragma unroll
    for (int o = 16; o; o >>= 1) s += __shfl_down_sync(0xffffffffu, s, o);
    if (lane == 0) out[b * 9 + w] = s + hb[w];
}

// ---------------- orchestration ----------------
extern "C" void kernel_launch(void* const* d_in, const int* in_sizes, int n_in,
                              void* d_out, int out_size) {
    const int*   cards   = (const int*)  d_in[0];
    const int*   players = (const int*)  d_in[1];
    const int*   deck    = (const int*)  d_in[2];
    const int*   opp     = (const int*)  d_in[3];
    const float* tok     = (const float*)d_in[4];
    const float* pemb    = (const float*)d_in[5];
    const float* pos     = (const float*)d_in[6];
    const float* ln1s = (const float*)d_in[9];
    const float* ln1b = (const float*)d_in[10];
    const float* qkvw = (const float*)d_in[11];
    const float* qkvb = (const float*)d_in[12];
    const float* projw = (const float*)d_in[13];
    const float* projb = (const float*)d_in[14];
    const float* ln2s = (const float*)d_in[15];
    const float* ln2b = (const float*)d_in[16];
    const float* fc1w = (const float*)d_in[17];
    const float* fc1b = (const float*)d_in[18];
    const float* fc2w = (const float*)d_in[19];
    const float* fc2b = (const float*)d_in[20];
    const float* lnfs = (const float*)d_in[21];
    const float* lnfb = (const float*)d_in[22];
    const float* headw = (const float*)d_in[23];
    const float* headb = (const float*)d_in[24];

    float *x, *xn, *qkv, *dm;
    f16 *xh, *yh, *hh;
    f16 *qT, *pT, *f1T, *f2T;
    char* mask; int* lastidx;
    cudaGetSymbolAddress((void**)&x,    g_x);
    cudaGetSymbolAddress((void**)&xn,   g_xn);
    cudaGetSymbolAddress((void**)&qkv,  g_qkv);
    cudaGetSymbolAddress((void**)&dm,   g_dm);
    cudaGetSymbolAddress((void**)&xh,   g_xh);
    cudaGetSymbolAddress((void**)&yh,   g_yh);
    cudaGetSymbolAddress((void**)&hh,   g_hh);
    cudaGetSymbolAddress((void**)&qT,   g_qkvT);
    cudaGetSymbolAddress((void**)&pT,   g_projT);
    cudaGetSymbolAddress((void**)&f1T,  g_fc1T);
    cudaGetSymbolAddress((void**)&f2T,  g_fc2T);
    cudaGetSymbolAddress((void**)&mask, g_mask);
    cudaGetSymbolAddress((void**)&lastidx, g_lastidx);

    cudaFuncSetAttribute(gemm_mma<0>, cudaFuncAttributeMaxDynamicSharedMemorySize, GEMM_SMEM);
    cudaFuncSetAttribute(gemm_mma<1>, cudaFuncAttributeMaxDynamicSharedMemorySize, GEMM_SMEM);
    cudaFuncSetAttribute(gemm_mma<2>, cudaFuncAttributeMaxDynamicSharedMemorySize, GEMM_SMEM);

    dim3 tb(32, 8);
    transpose_all<<<TFC2, tb>>>(qkvw, projw, fc1w, fc2w, qT, pT, f1T, f2T);
    mask_kernel<<<B_, T_>>>(cards, mask, lastidx);
    deckmean_kernel<<<B_, D_>>>(deck, opp, tok, dm);
    embed_kernel<<<BT_, 256>>>(cards, players, tok, pemb, pos, dm, x);

    for (int i = 0; i < L_; i++) {
        ln_kernel<true><<<BT_, 256>>>(x, ln1s + i * D_, ln1b + i * D_, nullptr, xh);
        gemm_mma<0><<<dim3(D3_ / 256, BT_ / 128), 256, GEMM_SMEM>>>(
            xh, qT + (size_t)i * D3_ * D_,
            qkvb + i * D3_, nullptr, qkv, nullptr, D_, D3_);
        attn_kernel<<<dim3(T_ / 64, NH_, B_), 128>>>(qkv, mask, yh);
        gemm_mma<2><<<dim3(D_ / 256, BT_ / 128), 256, GEMM_SMEM>>>(
            yh, pT + (size_t)i * D_ * D_,
            projb + i * D_, x, x, nullptr, D_, D_);
        ln_kernel<true><<<BT_, 256>>>(x, ln2s + i * D_, ln2b + i * D_, nullptr, xh);
        gemm_mma<1><<<dim3(D4_ / 256, BT_ / 128), 256, GEMM_SMEM>>>(
            xh, f1T + (size_t)i * D4_ * D_,
            fc1b + i * D4_, nullptr, nullptr, hh, D_, D4_);
        gemm_mma<2><<<dim3(D_ / 256, BT_ / 128), 256, GEMM_SMEM>>>(
            hh, f2T + (size_t)i * D_ * D4_,
            fc2b + i * D_, x, x, nullptr, D4_, D_);
    }

    ln_kernel<false><<<BT_, 256>>>(x, lnfs, lnfb, xn, nullptr);
    head_kernel<<<B_, 288>>>(xn, lastidx, headw, headb, (float*)d_out);
}

// round 11
// speedup vs baseline: 3.4466x; 1.1140x over previous
#include <cuda_runtime.h>
#include <cuda_fp16.h>
#include <math.h>
#include <stdint.h>

typedef __half f16;

// ---------------- problem constants ----------------
#define L_   6
#define D_   768
#define NH_  12
#define DH_  64
#define T_   512
#define B_   16
#define BT_  (B_ * T_)       // 8192
#define D3_  (3 * D_)        // 2304
#define D4_  (4 * D_)        // 3072

// ---------------- scratch ----------------
__device__ __align__(128) float g_x  [BT_ * D_];
__device__ __align__(128) float g_xn [BT_ * D_];
__device__ __align__(128) float g_qkv[BT_ * D3_];
__device__ __align__(128) f16   g_xh [BT_ * D_];
__device__ __align__(128) f16   g_yh [BT_ * D_];
__device__ __align__(128) f16   g_hh [BT_ * D4_];
__device__ __align__(128) float g_dm [B_ * D_];
__device__ char  g_mask[B_ * T_];
__device__ int   g_lastidx[B_];

__device__ __align__(128) f16 g_qkvT [L_ * D3_ * D_];
__device__ __align__(128) f16 g_projT[L_ * D_ * D_];
__device__ __align__(128) f16 g_fc1T [L_ * D4_ * D_];
__device__ __align__(128) f16 g_fc2T [L_ * D_ * D4_];

// ---------------- PTX helpers ----------------
__device__ __forceinline__ uint32_t smem_u32(const void* p) {
    uint32_t a;
    asm("{ .reg .u64 t; cvta.to.shared.u64 t, %1; cvt.u32.u64 %0, t; }" : "=r"(a) : "l"(p));
    return a;
}
__device__ __forceinline__ void cp16(uint32_t s, const void* g) {
    asm volatile("cp.async.cg.shared.global [%0], [%1], 16;" :: "r"(s), "l"(g) : "memory");
}
__device__ __forceinline__ void ldsm4(uint32_t* r, uint32_t addr) {
    asm volatile("ldmatrix.sync.aligned.m8n8.x4.shared.b16 {%0,%1,%2,%3}, [%4];"
                 : "=r"(r[0]), "=r"(r[1]), "=r"(r[2]), "=r"(r[3]) : "r"(addr));
}
__device__ __forceinline__ void mma16816(float* c, const uint32_t* a, const uint32_t* b) {
    asm volatile(
        "mma.sync.aligned.m16n8k16.row.col.f32.f16.f16.f32 "
        "{%0,%1,%2,%3}, {%4,%5,%6,%7}, {%8,%9}, {%0,%1,%2,%3};"
        : "+f"(c[0]), "+f"(c[1]), "+f"(c[2]), "+f"(c[3])
        : "r"(a[0]), "r"(a[1]), "r"(a[2]), "r"(a[3]), "r"(b[0]), "r"(b[1]));
}
__device__ __forceinline__ float gelu_exact(float v) {
    return 0.5f * v * (1.0f + erff(v * 0.70710678118654752440f));
}
__device__ __forceinline__ uint32_t pack_h2(f16 a, f16 b) {
    __half2 t = __halves2half2(a, b);
    return *(uint32_t*)&t;
}

// ---------------- fused weight transpose + fp16 round ----------------
#define TQKV (L_ * 1728)
#define TPROJ (TQKV + L_ * 576)
#define TFC1 (TPROJ + L_ * 2304)
#define TFC2 (TFC1 + L_ * 2304)

__global__ void transpose_all(const float* __restrict__ qkvw, const float* __restrict__ projw,
                              const float* __restrict__ fc1w, const float* __restrict__ fc2w,
                              f16* __restrict__ qT, f16* __restrict__ pT,
                              f16* __restrict__ f1T, f16* __restrict__ f2T) {
    __shared__ float tile[32][33];
    int idx = blockIdx.x;
    const float* W; f16* Th; int K, N, rem;
    if (idx < TQKV) {
        int layer = idx / 1728; rem = idx % 1728;
        K = D_; N = D3_;
        W = qkvw + (size_t)layer * D_ * D3_;
        Th = qT + (size_t)layer * D3_ * D_;
    } else if (idx < TPROJ) {
        idx -= TQKV;
        int layer = idx / 576; rem = idx % 576;
        K = D_; N = D_;
        W = projw + (size_t)layer * D_ * D_;
        Th = pT + (size_t)layer * D_ * D_;
    } else if (idx < TFC1) {
        idx -= TPROJ;
        int layer = idx / 2304; rem = idx % 2304;
        K = D_; N = D4_;
        W = fc1w + (size_t)layer * D_ * D4_;
        Th = f1T + (size_t)layer * D4_ * D_;
    } else {
        idx -= TFC1;
        int layer = idx / 2304; rem = idx % 2304;
        K = D4_; N = D_;
        W = fc2w + (size_t)layer * D4_ * D_;
        Th = f2T + (size_t)layer * D_ * D4_;
    }
    int tilesN = N >> 5;
    int n0 = (rem % tilesN) << 5;
    int k0 = (rem / tilesN) << 5;
    int tx = threadIdx.x, ty = threadIdx.y;
    #pragma unroll
    for (int i = 0; i < 32; i += 8)
        tile[ty + i][tx] = W[(size_t)(k0 + ty + i) * N + n0 + tx];
    __syncthreads();
    #pragma unroll
    for (int i = 0; i < 32; i += 8) {
        float v = tile[tx][ty + i];
        Th[(size_t)(n0 + ty + i) * K + k0 + tx] = __float2half_rn(v);
    }
}

// ---------------- mask + last_idx ----------------
__global__ void mask_kernel(const int* __restrict__ cards,
                            char* __restrict__ mask, int* __restrict__ lastidx) {
    int b = blockIdx.x;
    int t = threadIdx.x;
    bool valid = cards[b * T_ + t] != 0;
    bool any = __syncthreads_or(valid);
    bool m = valid || (t == 0 && !any);
    mask[b * T_ + t] = m ? 1 : 0;
    int cnt = __syncthreads_count(m);
    if (t == 0) lastidx[b] = (cnt - 1) > 0 ? (cnt - 1) : 0;
}

// ---------------- deck means ----------------
__global__ void deckmean_kernel(const int* __restrict__ deck, const int* __restrict__ opp,
                                const float* __restrict__ tok, float* __restrict__ dm) {
    int b = blockIdx.x;
    int d = threadIdx.x;
    float s = 0.f;
    #pragma unroll
    for (int i = 0; i < 8; i++) {
        s += tok[(size_t)deck[b * 8 + i] * D_ + d];
        s += tok[(size_t)opp [b * 8 + i] * D_ + d];
    }
    dm[b * D_ + d] = s * 0.125f;
}

// ---------------- embedding sum ----------------
__global__ void embed_kernel(const int* __restrict__ cards, const int* __restrict__ players,
                             const float* __restrict__ tok, const float* __restrict__ pemb,
                             const float* __restrict__ pos, const float* __restrict__ dm,
                             float* __restrict__ x) {
    int bt = blockIdx.x;
    int b = bt >> 9;
    int t = bt & 511;
    int card = cards[bt];
    int pl = players[bt]; pl = pl < 0 ? 0 : (pl > 1 ? 1 : pl);
    const float* tr = tok  + (size_t)card * D_;
    const float* pr = pemb + (size_t)pl * D_;
    const float* qr = pos  + (size_t)t * D_;
    const float* mr = dm   + (size_t)b * D_;
    float* xr = x + (size_t)bt * D_;
    for (int d = threadIdx.x; d < D_; d += 256)
        xr[d] = tr[d] + pr[d] + mr[d] + qr[d];
}

// ---------------- layernorm -> fp16 (or fp32 for final) ----------------
template<bool TOH>
__global__ void ln_kernel(const float* __restrict__ x, const float* __restrict__ g,
                          const float* __restrict__ be, float* __restrict__ of,
                          f16* __restrict__ oh) {
    __shared__ float sh1[8], sh2[8];
    int r = blockIdx.x;
    size_t base = (size_t)r * D_;
    int t = threadIdx.x;
    float v0 = x[base + t], v1 = x[base + t + 256], v2 = x[base + t + 512];
    float s = v0 + v1 + v2;
    float q = v0 * v0 + v1 * v1 + v2 * v2;
    #pragma unroll
    for (int o2 = 16; o2; o2 >>= 1) {
        s += __shfl_xor_sync(0xffffffffu, s, o2);
        q += __shfl_xor_sync(0xffffffffu, q, o2);
    }
    if ((t & 31) == 0) { sh1[t >> 5] = s; sh2[t >> 5] = q; }
    __syncthreads();
    s = sh1[t & 7]; q = sh2[t & 7];
    #pragma unroll
    for (int o2 = 4; o2; o2 >>= 1) {
        s += __shfl_xor_sync(0xffffffffu, s, o2);
        q += __shfl_xor_sync(0xffffffffu, q, o2);
    }
    float mean = s * (1.0f / D_);
    float var  = q * (1.0f / D_) - mean * mean;
    float rstd = rsqrtf(var + 1e-5f);
    #pragma unroll
    for (int u = 0; u < 3; u++) {
        int d = t + u * 256;
        float v = (u == 0 ? v0 : (u == 1 ? v1 : v2));
        float o = (v - mean) * rstd * g[d] + be[d];
        if (TOH) oh[base + d] = __float2half_rn(o);
        else     of[base + d] = o;
    }
}

// ---------------- mma.sync fp16 GEMM, 128xBN tiles (BN = 256 or 128) ----------------
#define ROWB 80
template<int BN> struct GCfg {
    static constexpr int A_OFF = 0;
    static constexpr int B_OFF = 128 * ROWB;
    static constexpr int STAGE = (128 + BN) * ROWB;
    static constexpr int SMEM  = 2 * STAGE;
    static constexpr int NF    = BN / 32;       // n-frags per warp
    static constexpr int NPW   = BN / 4;        // n cols per warp
};

template<int EPI, int BN>
__global__ __launch_bounds__(256, 1)
void gemm_mma(const f16* __restrict__ Ah, const f16* __restrict__ Bh,
              const float* __restrict__ bias, const float* __restrict__ res,
              float* __restrict__ outf, f16* __restrict__ outh,
              int K, int Nfull) {
    using C = GCfg<BN>;
    extern __shared__ char dsm[];
    uint32_t tiles = smem_u32(dsm);

    int tid = threadIdx.x;
    int wid = tid >> 5;
    int lane = tid & 31;
    int warp_m = wid & 1;
    int warp_n = wid >> 1;
    int m0 = blockIdx.y * 128;
    int n0 = blockIdx.x * BN;
    int nt = K >> 5;

    int aRow  = lane & 15;
    int aColB = (lane >> 4) << 4;
    int bRow  = (lane & 7) + ((lane & 16) >> 1);
    int bColB = (lane & 8) << 1;

    float acc[4][C::NF][4];
    #pragma unroll
    for (int mt = 0; mt < 4; mt++)
        #pragma unroll
        for (int ntl = 0; ntl < C::NF; ntl++)
            #pragma unroll
            for (int r = 0; r < 4; r++) acc[mt][ntl][r] = 0.f;

    auto load_stage = [&](int kt, int st) {
        uint32_t sb = tiles + st * C::STAGE;
        int k0 = kt << 5;
        #pragma unroll
        for (int i = 0; i < 2; i++) {                    // A: 128 rows x 4 chunks
            int id = tid + (i << 8);
            int r = id >> 2, c = id & 3;
            size_t go = (size_t)(m0 + r) * K + k0 + (c << 3);
            cp16(sb + C::A_OFF + r * ROWB + (c << 4), Ah + go);
        }
        #pragma unroll
        for (int i = 0; i < BN / 64; i++) {              // B: BN rows x 4 chunks
            int id = tid + (i << 8);
            int r = id >> 2, c = id & 3;
            size_t go = (size_t)(n0 + r) * K + k0 + (c << 3);
            cp16(sb + C::B_OFF + r * ROWB + (c << 4), Bh + go);
        }
        asm volatile("cp.async.commit_group;" ::: "memory");
    };

    load_stage(0, 0);

    uint32_t aH[16], bH[2 * C::NF];

    for (int kt = 0; kt < nt; kt++) {
        int cur = kt & 1;
        if (kt + 1 < nt) {
            load_stage(kt + 1, cur ^ 1);
            asm volatile("cp.async.wait_group 1;" ::: "memory");
        } else {
            asm volatile("cp.async.wait_group 0;" ::: "memory");
        }
        __syncthreads();

        uint32_t sb = tiles + cur * C::STAGE;
        uint32_t aBase = sb + (warp_m * 64 + aRow) * ROWB + aColB;
        uint32_t bBase = sb + C::B_OFF + (warp_n * C::NPW + bRow) * ROWB + bColB;

        #pragma unroll
        for (int ks = 0; ks < 2; ks++) {
            uint32_t kb = ks << 5;
            #pragma unroll
            for (int mt = 0; mt < 4; mt++)
                ldsm4(&aH[4 * mt], aBase + mt * (16 * ROWB) + kb);
            #pragma unroll
            for (int p = 0; p < BN / 64; p++)
                ldsm4(&bH[4 * p], bBase + p * (16 * ROWB) + kb);
            #pragma unroll
            for (int mt = 0; mt < 4; mt++)
                #pragma unroll
                for (int ntl = 0; ntl < C::NF; ntl++)
                    mma16816(acc[mt][ntl], &aH[4 * mt], &bH[2 * ntl]);
        }
        __syncthreads();
    }

    int m_base = m0 + warp_m * 64 + (lane >> 2);
    int n_base = n0 + warp_n * C::NPW + ((lane & 3) << 1);
    #pragma unroll
    for (int mt = 0; mt < 4; mt++) {
        #pragma unroll
        for (int ntl = 0; ntl < C::NF; ntl++) {
            int n = n_base + ntl * 8;
            float b0 = bias[n], b1 = bias[n + 1];
            #pragma unroll
            for (int rr = 0; rr < 2; rr++) {
                int m = m_base + mt * 16 + rr * 8;
                size_t ob = (size_t)m * Nfull + n;
                float v0 = acc[mt][ntl][2 * rr]     + b0;
                float v1 = acc[mt][ntl][2 * rr + 1] + b1;
                if (EPI == 0) {
                    *(float2*)(outf + ob) = make_float2(v0, v1);
                } else if (EPI == 2) {
                    float2 rv = *(const float2*)(res + ob);
                    *(float2*)(outf + ob) = make_float2(v0 + rv.x, v1 + rv.y);
                } else {
                    float g0 = gelu_exact(v0), g1 = gelu_exact(v1);
                    *(__half2*)(outh + ob) =
                        __halves2half2(__float2half_rn(g0), __float2half_rn(g1));
                }
            }
        }
    }
}

// ---------------- tensor-core flash attention (single-pass fp16, fp32 softmax) -----
#define QSTR 72
#define VSTR 40

__global__ __launch_bounds__(128)
void attn_kernel(const float* __restrict__ qkv, const char* __restrict__ mask,
                 f16* __restrict__ outh) {
    __shared__ f16 sQ[64 * QSTR];
    __shared__ f16 sK[32 * QSTR];
    __shared__ f16 sV[64 * VSTR];    // V^T: [dim][key]
    __shared__ char Ms[32];

    int qt = blockIdx.x, h = blockIdx.y, b = blockIdx.z;
    int tid = threadIdx.x;
    int wid = tid >> 5, lane = tid & 31;
    int grp = lane >> 2, qd = lane & 3;

    // ---- load Q (64x64), scale by 1/8, fp16 ----
    {
        int row = tid >> 1;
        int c0 = (tid & 1) * 32;
        const float* g = qkv + ((size_t)(b * T_ + qt * 64 + row)) * D3_ + h * DH_ + c0;
        #pragma unroll
        for (int u = 0; u < 8; u++) {
            float4 v = *(const float4*)(g + u * 4);
            int o = row * QSTR + c0 + u * 4;
            *(__half2*)&sQ[o] = __halves2half2(
                __float2half_rn(v.x * 0.125f), __float2half_rn(v.y * 0.125f));
            *(__half2*)&sQ[o + 2] = __halves2half2(
                __float2half_rn(v.z * 0.125f), __float2half_rn(v.w * 0.125f));
        }
    }

    float O[8][4];
    #pragma unroll
    for (int nf = 0; nf < 8; nf++)
        #pragma unroll
        for (int r = 0; r < 4; r++) O[nf][r] = 0.f;
    float m_a = -INFINITY, m_b = -INFINITY, l_a = 0.f, l_b = 0.f;

    uint32_t aAddr = smem_u32(sQ) + (wid * 16 + (lane & 15)) * (QSTR * 2) + ((lane >> 4) << 4);
    int bRow  = (lane & 7) + ((lane & 16) >> 1);
    int bColB = (lane & 8) << 1;
    uint32_t kAddr = smem_u32(sK) + bRow * (QSTR * 2) + bColB;
    uint32_t vAddr = smem_u32(sV) + bRow * (VSTR * 2) + bColB;

    int q_a = qt * 64 + wid * 16 + grp;
    int q_b = q_a + 8;

    int ktmax = (qt + 1) * 2;
    for (int kt = 0; kt < ktmax; kt++) {
        __syncthreads();
        // ---- fill K (row-major) and V^T, fp16 ----
        {
            int j  = tid >> 2;
            int d0 = (tid & 3) * 16;
            const float* gk = qkv + ((size_t)(b * T_ + kt * 32 + j)) * D3_ + D_ + h * DH_ + d0;
            const float* gv = gk + D_;
            #pragma unroll
            for (int u = 0; u < 4; u++) {
                float4 kv = *(const float4*)(gk + u * 4);
                int o = j * QSTR + d0 + u * 4;
                *(__half2*)&sK[o] = __halves2half2(__float2half_rn(kv.x), __float2half_rn(kv.y));
                *(__half2*)&sK[o + 2] = __halves2half2(__float2half_rn(kv.z), __float2half_rn(kv.w));
                float4 vv = *(const float4*)(gv + u * 4);
                int d = d0 + u * 4;
                sV[(d + 0) * VSTR + j] = __float2half_rn(vv.x);
                sV[(d + 1) * VSTR + j] = __float2half_rn(vv.y);
                sV[(d + 2) * VSTR + j] = __float2half_rn(vv.z);
                sV[(d + 3) * VSTR + j] = __float2half_rn(vv.w);
            }
            if (tid < 32) Ms[tid] = mask[b * T_ + kt * 32 + tid];
        }
        __syncthreads();

        // ---- S = Q K^T (m16 x n32, k64) ----
        float S[4][4];
        #pragma unroll
        for (int f = 0; f < 4; f++)
            #pragma unroll
            for (int r = 0; r < 4; r++) S[f][r] = 0.f;
        #pragma unroll
        for (int kc = 0; kc < 4; kc++) {
            uint32_t q[4], kf[8];
            ldsm4(q, aAddr + kc * 32);
            ldsm4(&kf[0], kAddr + kc * 32);
            ldsm4(&kf[4], kAddr + 16 * (QSTR * 2) + kc * 32);
            #pragma unroll
            for (int f = 0; f < 4; f++)
                mma16816(S[f], q, &kf[2 * f]);
        }

        // ---- mask + online softmax ----
        float mt_a = -INFINITY, mt_b = -INFINITY;
        #pragma unroll
        for (int f = 0; f < 4; f++) {
            int ci = f * 8 + qd * 2;
            int gk0 = kt * 32 + ci, gk1 = gk0 + 1;
            bool ok0 = Ms[ci] != 0, ok1 = Ms[ci + 1] != 0;
            S[f][0] = (ok0 && gk0 <= q_a) ? S[f][0] : -INFINITY;
            S[f][1] = (ok1 && gk1 <= q_a) ? S[f][1] : -INFINITY;
            S[f][2] = (ok0 && gk0 <= q_b) ? S[f][2] : -INFINITY;
            S[f][3] = (ok1 && gk1 <= q_b) ? S[f][3] : -INFINITY;
            mt_a = fmaxf(mt_a, fmaxf(S[f][0], S[f][1]));
            mt_b = fmaxf(mt_b, fmaxf(S[f][2], S[f][3]));
        }
        mt_a = fmaxf(mt_a, __shfl_xor_sync(0xffffffffu, mt_a, 1));
        mt_a = fmaxf(mt_a, __shfl_xor_sync(0xffffffffu, mt_a, 2));
        mt_b = fmaxf(mt_b, __shfl_xor_sync(0xffffffffu, mt_b, 1));
        mt_b = fmaxf(mt_b, __shfl_xor_sync(0xffffffffu, mt_b, 2));
        float mn_a = fmaxf(m_a, mt_a), mn_b = fmaxf(m_b, mt_b);
        float al_a, al_b, ps_a = 0.f, ps_b = 0.f;
        if (mn_a == -INFINITY) {
            al_a = 1.f;
            #pragma unroll
            for (int f = 0; f < 4; f++) { S[f][0] = 0.f; S[f][1] = 0.f; }
        } else {
            al_a = expf(m_a - mn_a);
            #pragma unroll
            for (int f = 0; f < 4; f++) {
                S[f][0] = expf(S[f][0] - mn_a);
                S[f][1] = expf(S[f][1] - mn_a);
                ps_a += S[f][0] + S[f][1];
            }
        }
        if (mn_b == -INFINITY) {
            al_b = 1.f;
            #pragma unroll
            for (int f = 0; f < 4; f++) { S[f][2] = 0.f; S[f][3] = 0.f; }
        } else {
            al_b = expf(m_b - mn_b);
            #pragma unroll
            for (int f = 0; f < 4; f++) {
                S[f][2] = expf(S[f][2] - mn_b);
                S[f][3] = expf(S[f][3] - mn_b);
                ps_b += S[f][2] + S[f][3];
            }
        }
        ps_a += __shfl_xor_sync(0xffffffffu, ps_a, 1);
        ps_a += __shfl_xor_sync(0xffffffffu, ps_a, 2);
        ps_b += __shfl_xor_sync(0xffffffffu, ps_b, 1);
        ps_b += __shfl_xor_sync(0xffffffffu, ps_b, 2);
        l_a = l_a * al_a + ps_a;
        l_b = l_b * al_b + ps_b;
        m_a = mn_a; m_b = mn_b;
        #pragma unroll
        for (int nf = 0; nf < 8; nf++) {
            O[nf][0] *= al_a; O[nf][1] *= al_a;
            O[nf][2] *= al_b; O[nf][3] *= al_b;
        }

        // ---- O += P V  (P in registers -> A-frags, fp16) ----
        #pragma unroll
        for (int kc = 0; kc < 2; kc++) {
            int f0 = 2 * kc, f1 = 2 * kc + 1;
            uint32_t pa[4];
            pa[0] = pack_h2(__float2half_rn(S[f0][0]), __float2half_rn(S[f0][1]));
            pa[1] = pack_h2(__float2half_rn(S[f0][2]), __float2half_rn(S[f0][3]));
            pa[2] = pack_h2(__float2half_rn(S[f1][0]), __float2half_rn(S[f1][1]));
            pa[3] = pack_h2(__float2half_rn(S[f1][2]), __float2half_rn(S[f1][3]));
            uint32_t vf[16];
            #pragma unroll
            for (int p4 = 0; p4 < 4; p4++)
                ldsm4(&vf[4 * p4], vAddr + p4 * 16 * (VSTR * 2) + kc * 32);
            #pragma unroll
            for (int nf = 0; nf < 8; nf++)
                mma16816(O[nf], pa, &vf[2 * nf]);
        }
    }

    // ---- normalize + write fp16 ----
    float rl_a = (l_a > 0.f) ? (1.f / l_a) : 0.f;
    float rl_b = (l_b > 0.f) ? (1.f / l_b) : 0.f;
    size_t rowA = (size_t)(b * T_) + qt * 64 + wid * 16 + grp;
    size_t rowB = rowA + 8;
    #pragma unroll
    for (int nf = 0; nf < 8; nf++) {
        int col = h * DH_ + nf * 8 + qd * 2;
        *(__half2*)(outh + rowA * D_ + col) = __halves2half2(
            __float2half_rn(O[nf][0] * rl_a), __float2half_rn(O[nf][1] * rl_a));
        *(__half2*)(outh + rowB * D_ + col) = __halves2half2(
            __float2half_rn(O[nf][2] * rl_b), __float2half_rn(O[nf][3] * rl_b));
    }
}

// ---------------- head ----------------
__global__ void head_kernel(const float* __restrict__ xn, const int* __restrict__ lastidx,
                            const float* __restrict__ hw, const float* __restrict__ hb,
                            float* __restrict__ out) {
    int b = blockIdx.x;
    int w = threadIdx.x >> 5;
    int lane = threadIdx.x & 31;
    const float* h = xn + ((size_t)(b * T_ + lastidx[b])) * D_;
    float s = 0.f;
    for (int d = lane; d < D_; d += 32) s += h[d] * hw[d * 9 + w];
    #pragma unroll
    for (int o = 16; o; o >>= 1) s += __shfl_down_sync(0xffffffffu, s, o);
    if (lane == 0) out[b * 9 + w] = s + hb[w];
}

// ---------------- orchestration ----------------
extern "C" void kernel_launch(void* const* d_in, const int* in_sizes, int n_in,
                              void* d_out, int out_size) {
    const int*   cards   = (const int*)  d_in[0];
    const int*   players = (const int*)  d_in[1];
    const int*   deck    = (const int*)  d_in[2];
    const int*   opp     = (const int*)  d_in[3];
    const float* tok     = (const float*)d_in[4];
    const float* pemb    = (const float*)d_in[5];
    const float* pos     = (const float*)d_in[6];
    const float* ln1s = (const float*)d_in[9];
    const float* ln1b = (const float*)d_in[10];
    const float* qkvw = (const float*)d_in[11];
    const float* qkvb = (const float*)d_in[12];
    const float* projw = (const float*)d_in[13];
    const float* projb = (const float*)d_in[14];
    const float* ln2s = (const float*)d_in[15];
    const float* ln2b = (const float*)d_in[16];
    const float* fc1w = (const float*)d_in[17];
    const float* fc1b = (const float*)d_in[18];
    const float* fc2w = (const float*)d_in[19];
    const float* fc2b = (const float*)d_in[20];
    const float* lnfs = (const float*)d_in[21];
    const float* lnfb = (const float*)d_in[22];
    const float* headw = (const float*)d_in[23];
    const float* headb = (const float*)d_in[24];

    float *x, *xn, *qkv, *dm;
    f16 *xh, *yh, *hh;
    f16 *qT, *pT, *f1T, *f2T;
    char* mask; int* lastidx;
    cudaGetSymbolAddress((void**)&x,    g_x);
    cudaGetSymbolAddress((void**)&xn,   g_xn);
    cudaGetSymbolAddress((void**)&qkv,  g_qkv);
    cudaGetSymbolAddress((void**)&dm,   g_dm);
    cudaGetSymbolAddress((void**)&xh,   g_xh);
    cudaGetSymbolAddress((void**)&yh,   g_yh);
    cudaGetSymbolAddress((void**)&hh,   g_hh);
    cudaGetSymbolAddress((void**)&qT,   g_qkvT);
    cudaGetSymbolAddress((void**)&pT,   g_projT);
    cudaGetSymbolAddress((void**)&f1T,  g_fc1T);
    cudaGetSymbolAddress((void**)&f2T,  g_fc2T);
    cudaGetSymbolAddress((void**)&mask, g_mask);
    cudaGetSymbolAddress((void**)&lastidx, g_lastidx);

    cudaFuncSetAttribute((const void*)gemm_mma<0, 256>,
                         cudaFuncAttributeMaxDynamicSharedMemorySize, GCfg<256>::SMEM);
    cudaFuncSetAttribute((const void*)gemm_mma<1, 256>,
                         cudaFuncAttributeMaxDynamicSharedMemorySize, GCfg<256>::SMEM);
    cudaFuncSetAttribute((const void*)gemm_mma<2, 128>,
                         cudaFuncAttributeMaxDynamicSharedMemorySize, GCfg<128>::SMEM);

    dim3 tb(32, 8);
    transpose_all<<<TFC2, tb>>>(qkvw, projw, fc1w, fc2w, qT, pT, f1T, f2T);
    mask_kernel<<<B_, T_>>>(cards, mask, lastidx);
    deckmean_kernel<<<B_, D_>>>(deck, opp, tok, dm);
    embed_kernel<<<BT_, 256>>>(cards, players, tok, pemb, pos, dm, x);

    for (int i = 0; i < L_; i++) {
        ln_kernel<true><<<BT_, 256>>>(x, ln1s + i * D_, ln1b + i * D_, nullptr, xh);
        gemm_mma<0, 256><<<dim3(D3_ / 256, BT_ / 128), 256, GCfg<256>::SMEM>>>(
            xh, qT + (size_t)i * D3_ * D_,
            qkvb + i * D3_, nullptr, qkv, nullptr, D_, D3_);
        attn_kernel<<<dim3(T_ / 64, NH_, B_), 128>>>(qkv, mask, yh);
        gemm_mma<2, 128><<<dim3(D_ / 128, BT_ / 128), 256, GCfg<128>::SMEM>>>(
            yh, pT + (size_t)i * D_ * D_,
            projb + i * D_, x, x, nullptr, D_, D_);
        ln_kernel<true><<<BT_, 256>>>(x, ln2s + i * D_, ln2b + i * D_, nullptr, xh);
        gemm_mma<1, 256><<<dim3(D4_ / 256, BT_ / 128), 256, GCfg<256>::SMEM>>>(
            xh, f1T + (size_t)i * D4_ * D_,
            fc1b + i * D4_, nullptr, nullptr, hh, D_, D4_);
        gemm_mma<2, 128><<<dim3(D_ / 128, BT_ / 128), 256, GCfg<128>::SMEM>>>(
            hh, f2T + (size_t)i * D_ * D4_,
            fc2b + i * D_, x, x, nullptr, D4_, D_);
    }

    ln_kernel<false><<<BT_, 256>>>(x, lnfs, lnfb, xn, nullptr);
    head_kernel<<<B_, 288>>>(xn, lastidx, headw, headb, (float*)d_out);
}

// round 12
// speedup vs baseline: 3.5147x; 1.0198x over previous
#include <cuda_runtime.h>
#include <cuda_fp16.h>
#include <math.h>
#include <stdint.h>

typedef __half f16;

// ---------------- problem constants ----------------
#define L_   6
#define D_   768
#define NH_  12
#define DH_  64
#define T_   512
#define B_   16
#define BT_  (B_ * T_)       // 8192
#define D3_  (3 * D_)        // 2304
#define D4_  (4 * D_)        // 3072

// ---------------- scratch ----------------
__device__ __align__(128) float g_x  [BT_ * D_];
__device__ __align__(128) float g_xn [BT_ * D_];
__device__ __align__(128) f16   g_qkv[BT_ * D3_];   // fp16 now
__device__ __align__(128) f16   g_xh [BT_ * D_];
__device__ __align__(128) f16   g_yh [BT_ * D_];
__device__ __align__(128) f16   g_hh [BT_ * D4_];
__device__ __align__(128) float g_dm [B_ * D_];
__device__ char  g_mask[B_ * T_];
__device__ int   g_lastidx[B_];

__device__ __align__(128) f16 g_qkvT [L_ * D3_ * D_];
__device__ __align__(128) f16 g_projT[L_ * D_ * D_];
__device__ __align__(128) f16 g_fc1T [L_ * D4_ * D_];
__device__ __align__(128) f16 g_fc2T [L_ * D_ * D4_];

// ---------------- PTX helpers ----------------
__device__ __forceinline__ uint32_t smem_u32(const void* p) {
    uint32_t a;
    asm("{ .reg .u64 t; cvta.to.shared.u64 t, %1; cvt.u32.u64 %0, t; }" : "=r"(a) : "l"(p));
    return a;
}
__device__ __forceinline__ void cp16(uint32_t s, const void* g) {
    asm volatile("cp.async.cg.shared.global [%0], [%1], 16;" :: "r"(s), "l"(g) : "memory");
}
__device__ __forceinline__ void ldsm4(uint32_t* r, uint32_t addr) {
    asm volatile("ldmatrix.sync.aligned.m8n8.x4.shared.b16 {%0,%1,%2,%3}, [%4];"
                 : "=r"(r[0]), "=r"(r[1]), "=r"(r[2]), "=r"(r[3]) : "r"(addr));
}
__device__ __forceinline__ void mma16816(float* c, const uint32_t* a, const uint32_t* b) {
    asm volatile(
        "mma.sync.aligned.m16n8k16.row.col.f32.f16.f16.f32 "
        "{%0,%1,%2,%3}, {%4,%5,%6,%7}, {%8,%9}, {%0,%1,%2,%3};"
        : "+f"(c[0]), "+f"(c[1]), "+f"(c[2]), "+f"(c[3])
        : "r"(a[0]), "r"(a[1]), "r"(a[2]), "r"(a[3]), "r"(b[0]), "r"(b[1]));
}
__device__ __forceinline__ float gelu_exact(float v) {
    return 0.5f * v * (1.0f + erff(v * 0.70710678118654752440f));
}
__device__ __forceinline__ uint32_t pack_h2(f16 a, f16 b) {
    __half2 t = __halves2half2(a, b);
    return *(uint32_t*)&t;
}

// ---------------- fused weight transpose + fp16 round ----------------
#define TQKV (L_ * 1728)
#define TPROJ (TQKV + L_ * 576)
#define TFC1 (TPROJ + L_ * 2304)
#define TFC2 (TFC1 + L_ * 2304)

__global__ void transpose_all(const float* __restrict__ qkvw, const float* __restrict__ projw,
                              const float* __restrict__ fc1w, const float* __restrict__ fc2w,
                              f16* __restrict__ qT, f16* __restrict__ pT,
                              f16* __restrict__ f1T, f16* __restrict__ f2T) {
    __shared__ float tile[32][33];
    int idx = blockIdx.x;
    const float* W; f16* Th; int K, N, rem;
    if (idx < TQKV) {
        int layer = idx / 1728; rem = idx % 1728;
        K = D_; N = D3_;
        W = qkvw + (size_t)layer * D_ * D3_;
        Th = qT + (size_t)layer * D3_ * D_;
    } else if (idx < TPROJ) {
        idx -= TQKV;
        int layer = idx / 576; rem = idx % 576;
        K = D_; N = D_;
        W = projw + (size_t)layer * D_ * D_;
        Th = pT + (size_t)layer * D_ * D_;
    } else if (idx < TFC1) {
        idx -= TPROJ;
        int layer = idx / 2304; rem = idx % 2304;
        K = D_; N = D4_;
        W = fc1w + (size_t)layer * D_ * D4_;
        Th = f1T + (size_t)layer * D4_ * D_;
    } else {
        idx -= TFC1;
        int layer = idx / 2304; rem = idx % 2304;
        K = D4_; N = D_;
        W = fc2w + (size_t)layer * D4_ * D_;
        Th = f2T + (size_t)layer * D_ * D4_;
    }
    int tilesN = N >> 5;
    int n0 = (rem % tilesN) << 5;
    int k0 = (rem / tilesN) << 5;
    int tx = threadIdx.x, ty = threadIdx.y;
    #pragma unroll
    for (int i = 0; i < 32; i += 8)
        tile[ty + i][tx] = W[(size_t)(k0 + ty + i) * N + n0 + tx];
    __syncthreads();
    #pragma unroll
    for (int i = 0; i < 32; i += 8) {
        float v = tile[tx][ty + i];
        Th[(size_t)(n0 + ty + i) * K + k0 + tx] = __float2half_rn(v);
    }
}

// ---------------- mask + last_idx ----------------
__global__ void mask_kernel(const int* __restrict__ cards,
                            char* __restrict__ mask, int* __restrict__ lastidx) {
    int b = blockIdx.x;
    int t = threadIdx.x;
    bool valid = cards[b * T_ + t] != 0;
    bool any = __syncthreads_or(valid);
    bool m = valid || (t == 0 && !any);
    mask[b * T_ + t] = m ? 1 : 0;
    int cnt = __syncthreads_count(m);
    if (t == 0) lastidx[b] = (cnt - 1) > 0 ? (cnt - 1) : 0;
}

// ---------------- deck means ----------------
__global__ void deckmean_kernel(const int* __restrict__ deck, const int* __restrict__ opp,
                                const float* __restrict__ tok, float* __restrict__ dm) {
    int b = blockIdx.x;
    int d = threadIdx.x;
    float s = 0.f;
    #pragma unroll
    for (int i = 0; i < 8; i++) {
        s += tok[(size_t)deck[b * 8 + i] * D_ + d];
        s += tok[(size_t)opp [b * 8 + i] * D_ + d];
    }
    dm[b * D_ + d] = s * 0.125f;
}

// ---------------- embedding sum ----------------
__global__ void embed_kernel(const int* __restrict__ cards, const int* __restrict__ players,
                             const float* __restrict__ tok, const float* __restrict__ pemb,
                             const float* __restrict__ pos, const float* __restrict__ dm,
                             float* __restrict__ x) {
    int bt = blockIdx.x;
    int b = bt >> 9;
    int t = bt & 511;
    int card = cards[bt];
    int pl = players[bt]; pl = pl < 0 ? 0 : (pl > 1 ? 1 : pl);
    const float* tr = tok  + (size_t)card * D_;
    const float* pr = pemb + (size_t)pl * D_;
    const float* qr = pos  + (size_t)t * D_;
    const float* mr = dm   + (size_t)b * D_;
    float* xr = x + (size_t)bt * D_;
    for (int d = threadIdx.x; d < D_; d += 256)
        xr[d] = tr[d] + pr[d] + mr[d] + qr[d];
}

// ---------------- layernorm -> fp16 (or fp32 for final) ----------------
template<bool TOH>
__global__ void ln_kernel(const float* __restrict__ x, const float* __restrict__ g,
                          const float* __restrict__ be, float* __restrict__ of,
                          f16* __restrict__ oh) {
    __shared__ float sh1[8], sh2[8];
    int r = blockIdx.x;
    size_t base = (size_t)r * D_;
    int t = threadIdx.x;
    float v0 = x[base + t], v1 = x[base + t + 256], v2 = x[base + t + 512];
    float s = v0 + v1 + v2;
    float q = v0 * v0 + v1 * v1 + v2 * v2;
    #pragma unroll
    for (int o2 = 16; o2; o2 >>= 1) {
        s += __shfl_xor_sync(0xffffffffu, s, o2);
        q += __shfl_xor_sync(0xffffffffu, q, o2);
    }
    if ((t & 31) == 0) { sh1[t >> 5] = s; sh2[t >> 5] = q; }
    __syncthreads();
    s = sh1[t & 7]; q = sh2[t & 7];
    #pragma unroll
    for (int o2 = 4; o2; o2 >>= 1) {
        s += __shfl_xor_sync(0xffffffffu, s, o2);
        q += __shfl_xor_sync(0xffffffffu, q, o2);
    }
    float mean = s * (1.0f / D_);
    float var  = q * (1.0f / D_) - mean * mean;
    float rstd = rsqrtf(var + 1e-5f);
    #pragma unroll
    for (int u = 0; u < 3; u++) {
        int d = t + u * 256;
        float v = (u == 0 ? v0 : (u == 1 ? v1 : v2));
        float o = (v - mean) * rstd * g[d] + be[d];
        if (TOH) oh[base + d] = __float2half_rn(o);
        else     of[base + d] = o;
    }
}

// ---------------- mma.sync fp16 GEMM, 128xBN tiles ----------------
// EPI: 0 = bias -> f16; 1 = bias+gelu -> f16; 2 = bias+residual -> fp32
#define ROWB 80
template<int BN> struct GCfg {
    static constexpr int A_OFF = 0;
    static constexpr int B_OFF = 128 * ROWB;
    static constexpr int STAGE = (128 + BN) * ROWB;
    static constexpr int SMEM  = 2 * STAGE;
    static constexpr int NF    = BN / 32;
    static constexpr int NPW   = BN / 4;
};

template<int EPI, int BN>
__global__ __launch_bounds__(256, 1)
void gemm_mma(const f16* __restrict__ Ah, const f16* __restrict__ Bh,
              const float* __restrict__ bias, const float* __restrict__ res,
              float* __restrict__ outf, f16* __restrict__ outh,
              int K, int Nfull) {
    using C = GCfg<BN>;
    extern __shared__ char dsm[];
    uint32_t tiles = smem_u32(dsm);

    int tid = threadIdx.x;
    int wid = tid >> 5;
    int lane = tid & 31;
    int warp_m = wid & 1;
    int warp_n = wid >> 1;
    int m0 = blockIdx.y * 128;
    int n0 = blockIdx.x * BN;
    int nt = K >> 5;

    int aRow  = lane & 15;
    int aColB = (lane >> 4) << 4;
    int bRow  = (lane & 7) + ((lane & 16) >> 1);
    int bColB = (lane & 8) << 1;

    float acc[4][C::NF][4];
    #pragma unroll
    for (int mt = 0; mt < 4; mt++)
        #pragma unroll
        for (int ntl = 0; ntl < C::NF; ntl++)
            #pragma unroll
            for (int r = 0; r < 4; r++) acc[mt][ntl][r] = 0.f;

    auto load_stage = [&](int kt, int st) {
        uint32_t sb = tiles + st * C::STAGE;
        int k0 = kt << 5;
        #pragma unroll
        for (int i = 0; i < 2; i++) {
            int id = tid + (i << 8);
            int r = id >> 2, c = id & 3;
            size_t go = (size_t)(m0 + r) * K + k0 + (c << 3);
            cp16(sb + C::A_OFF + r * ROWB + (c << 4), Ah + go);
        }
        #pragma unroll
        for (int i = 0; i < BN / 64; i++) {
            int id = tid + (i << 8);
            int r = id >> 2, c = id & 3;
            size_t go = (size_t)(n0 + r) * K + k0 + (c << 3);
            cp16(sb + C::B_OFF + r * ROWB + (c << 4), Bh + go);
        }
        asm volatile("cp.async.commit_group;" ::: "memory");
    };

    load_stage(0, 0);

    uint32_t aH[16], bH[2 * C::NF];

    for (int kt = 0; kt < nt; kt++) {
        int cur = kt & 1;
        if (kt + 1 < nt) {
            load_stage(kt + 1, cur ^ 1);
            asm volatile("cp.async.wait_group 1;" ::: "memory");
        } else {
            asm volatile("cp.async.wait_group 0;" ::: "memory");
        }
        __syncthreads();

        uint32_t sb = tiles + cur * C::STAGE;
        uint32_t aBase = sb + (warp_m * 64 + aRow) * ROWB + aColB;
        uint32_t bBase = sb + C::B_OFF + (warp_n * C::NPW + bRow) * ROWB + bColB;

        #pragma unroll
        for (int ks = 0; ks < 2; ks++) {
            uint32_t kb = ks << 5;
            #pragma unroll
            for (int mt = 0; mt < 4; mt++)
                ldsm4(&aH[4 * mt], aBase + mt * (16 * ROWB) + kb);
            #pragma unroll
            for (int p = 0; p < BN / 64; p++)
                ldsm4(&bH[4 * p], bBase + p * (16 * ROWB) + kb);
            #pragma unroll
            for (int mt = 0; mt < 4; mt++)
                #pragma unroll
                for (int ntl = 0; ntl < C::NF; ntl++)
                    mma16816(acc[mt][ntl], &aH[4 * mt], &bH[2 * ntl]);
        }
        __syncthreads();
    }

    int m_base = m0 + warp_m * 64 + (lane >> 2);
    int n_base = n0 + warp_n * C::NPW + ((lane & 3) << 1);
    #pragma unroll
    for (int mt = 0; mt < 4; mt++) {
        #pragma unroll
        for (int ntl = 0; ntl < C::NF; ntl++) {
            int n = n_base + ntl * 8;
            float b0 = bias[n], b1 = bias[n + 1];
            #pragma unroll
            for (int rr = 0; rr < 2; rr++) {
                int m = m_base + mt * 16 + rr * 8;
                size_t ob = (size_t)m * Nfull + n;
                float v0 = acc[mt][ntl][2 * rr]     + b0;
                float v1 = acc[mt][ntl][2 * rr + 1] + b1;
                if (EPI == 0) {
                    *(__half2*)(outh + ob) =
                        __halves2half2(__float2half_rn(v0), __float2half_rn(v1));
                } else if (EPI == 2) {
                    float2 rv = *(const float2*)(res + ob);
                    *(float2*)(outf + ob) = make_float2(v0 + rv.x, v1 + rv.y);
                } else {
                    float g0 = gelu_exact(v0), g1 = gelu_exact(v1);
                    *(__half2*)(outh + ob) =
                        __halves2half2(__float2half_rn(g0), __float2half_rn(g1));
                }
            }
        }
    }
}

// ---------------- tensor-core flash attention (fp16 qkv in, fp32 softmax) ----------
#define QSTR 72
#define VSTR 40

__global__ __launch_bounds__(128)
void attn_kernel(const f16* __restrict__ qkv, const char* __restrict__ mask,
                 f16* __restrict__ outh) {
    __shared__ f16 sQ[64 * QSTR];
    __shared__ f16 sK[32 * QSTR];
    __shared__ f16 sV[64 * VSTR];    // V^T: [dim][key]
    __shared__ char Ms[32];

    int qt = blockIdx.x, h = blockIdx.y, b = blockIdx.z;
    int tid = threadIdx.x;
    int wid = tid >> 5, lane = tid & 31;
    int grp = lane >> 2, qd = lane & 3;

    // ---- load Q (64x64 f16), scale by 1/8 (exact in fp16) ----
    {
        int row = tid >> 1;
        int c0 = (tid & 1) * 32;
        const f16* g = qkv + ((size_t)(b * T_ + qt * 64 + row)) * D3_ + h * DH_ + c0;
        __half2 sc = __half2half2(__float2half(0.125f));
        #pragma unroll
        for (int u = 0; u < 16; u++) {
            __half2 v = *(const __half2*)(g + 2 * u);
            *(__half2*)&sQ[row * QSTR + c0 + 2 * u] = __hmul2(v, sc);
        }
    }

    float O[8][4];
    #pragma unroll
    for (int nf = 0; nf < 8; nf++)
        #pragma unroll
        for (int r = 0; r < 4; r++) O[nf][r] = 0.f;
    float m_a = -INFINITY, m_b = -INFINITY, l_a = 0.f, l_b = 0.f;

    uint32_t aAddr = smem_u32(sQ) + (wid * 16 + (lane & 15)) * (QSTR * 2) + ((lane >> 4) << 4);
    int bRow  = (lane & 7) + ((lane & 16) >> 1);
    int bColB = (lane & 8) << 1;
    uint32_t kAddr = smem_u32(sK) + bRow * (QSTR * 2) + bColB;
    uint32_t vAddr = smem_u32(sV) + bRow * (VSTR * 2) + bColB;

    int q_a = qt * 64 + wid * 16 + grp;
    int q_b = q_a + 8;

    int ktmax = (qt + 1) * 2;
    for (int kt = 0; kt < ktmax; kt++) {
        __syncthreads();
        // ---- fill K (row-major copy) and V^T ----
        {
            int j  = tid >> 2;
            int d0 = (tid & 3) * 16;
            const f16* gk = qkv + ((size_t)(b * T_ + kt * 32 + j)) * D3_ + D_ + h * DH_ + d0;
            const f16* gv = gk + D_;
            #pragma unroll
            for (int u = 0; u < 2; u++)
                *(uint4*)&sK[j * QSTR + d0 + u * 8] = *(const uint4*)(gk + u * 8);
            #pragma unroll
            for (int u = 0; u < 8; u++) {
                __half2 v = *(const __half2*)(gv + 2 * u);
                int d = d0 + 2 * u;
                sV[(d + 0) * VSTR + j] = __low2half(v);
                sV[(d + 1) * VSTR + j] = __high2half(v);
            }
            if (tid < 32) Ms[tid] = mask[b * T_ + kt * 32 + tid];
        }
        __syncthreads();

        // ---- S = Q K^T (m16 x n32, k64) ----
        float S[4][4];
        #pragma unroll
        for (int f = 0; f < 4; f++)
            #pragma unroll
            for (int r = 0; r < 4; r++) S[f][r] = 0.f;
        #pragma unroll
        for (int kc = 0; kc < 4; kc++) {
            uint32_t q[4], kf[8];
            ldsm4(q, aAddr + kc * 32);
            ldsm4(&kf[0], kAddr + kc * 32);
            ldsm4(&kf[4], kAddr + 16 * (QSTR * 2) + kc * 32);
            #pragma unroll
            for (int f = 0; f < 4; f++)
                mma16816(S[f], q, &kf[2 * f]);
        }

        // ---- mask + online softmax ----
        float mt_a = -INFINITY, mt_b = -INFINITY;
        #pragma unroll
        for (int f = 0; f < 4; f++) {
            int ci = f * 8 + qd * 2;
            int gk0 = kt * 32 + ci, gk1 = gk0 + 1;
            bool ok0 = Ms[ci] != 0, ok1 = Ms[ci + 1] != 0;
            S[f][0] = (ok0 && gk0 <= q_a) ? S[f][0] : -INFINITY;
            S[f][1] = (ok1 && gk1 <= q_a) ? S[f][1] : -INFINITY;
            S[f][2] = (ok0 && gk0 <= q_b) ? S[f][2] : -INFINITY;
            S[f][3] = (ok1 && gk1 <= q_b) ? S[f][3] : -INFINITY;
            mt_a = fmaxf(mt_a, fmaxf(S[f][0], S[f][1]));
            mt_b = fmaxf(mt_b, fmaxf(S[f][2], S[f][3]));
        }
        mt_a = fmaxf(mt_a, __shfl_xor_sync(0xffffffffu, mt_a, 1));
        mt_a = fmaxf(mt_a, __shfl_xor_sync(0xffffffffu, mt_a, 2));
        mt_b = fmaxf(mt_b, __shfl_xor_sync(0xffffffffu, mt_b, 1));
        mt_b = fmaxf(mt_b, __shfl_xor_sync(0xffffffffu, mt_b, 2));
        float mn_a = fmaxf(m_a, mt_a), mn_b = fmaxf(m_b, mt_b);
        float al_a, al_b, ps_a = 0.f, ps_b = 0.f;
        if (mn_a == -INFINITY) {
            al_a = 1.f;
            #pragma unroll
            for (int f = 0; f < 4; f++) { S[f][0] = 0.f; S[f][1] = 0.f; }
        } else {
            al_a = expf(m_a - mn_a);
            #pragma unroll
            for (int f = 0; f < 4; f++) {
                S[f][0] = expf(S[f][0] - mn_a);
                S[f][1] = expf(S[f][1] - mn_a);
                ps_a += S[f][0] + S[f][1];
            }
        }
        if (mn_b == -INFINITY) {
            al_b = 1.f;
            #pragma unroll
            for (int f = 0; f < 4; f++) { S[f][2] = 0.f; S[f][3] = 0.f; }
        } else {
            al_b = expf(m_b - mn_b);
            #pragma unroll
            for (int f = 0; f < 4; f++) {
                S[f][2] = expf(S[f][2] - mn_b);
                S[f][3] = expf(S[f][3] - mn_b);
                ps_b += S[f][2] + S[f][3];
            }
        }
        ps_a += __shfl_xor_sync(0xffffffffu, ps_a, 1);
        ps_a += __shfl_xor_sync(0xffffffffu, ps_a, 2);
        ps_b += __shfl_xor_sync(0xffffffffu, ps_b, 1);
        ps_b += __shfl_xor_sync(0xffffffffu, ps_b, 2);
        l_a = l_a * al_a + ps_a;
        l_b = l_b * al_b + ps_b;
        m_a = mn_a; m_b = mn_b;
        #pragma unroll
        for (int nf = 0; nf < 8; nf++) {
            O[nf][0] *= al_a; O[nf][1] *= al_a;
            O[nf][2] *= al_b; O[nf][3] *= al_b;
        }

        // ---- O += P V ----
        #pragma unroll
        for (int kc = 0; kc < 2; kc++) {
            int f0 = 2 * kc, f1 = 2 * kc + 1;
            uint32_t pa[4];
            pa[0] = pack_h2(__float2half_rn(S[f0][0]), __float2half_rn(S[f0][1]));
            pa[1] = pack_h2(__float2half_rn(S[f0][2]), __float2half_rn(S[f0][3]));
            pa[2] = pack_h2(__float2half_rn(S[f1][0]), __float2half_rn(S[f1][1]));
            pa[3] = pack_h2(__float2half_rn(S[f1][2]), __float2half_rn(S[f1][3]));
            uint32_t vf[16];
            #pragma unroll
            for (int p4 = 0; p4 < 4; p4++)
                ldsm4(&vf[4 * p4], vAddr + p4 * 16 * (VSTR * 2) + kc * 32);
            #pragma unroll
            for (int nf = 0; nf < 8; nf++)
                mma16816(O[nf], pa, &vf[2 * nf]);
        }
    }

    float rl_a = (l_a > 0.f) ? (1.f / l_a) : 0.f;
    float rl_b = (l_b > 0.f) ? (1.f / l_b) : 0.f;
    size_t rowA = (size_t)(b * T_) + qt * 64 + wid * 16 + grp;
    size_t rowB = rowA + 8;
    #pragma unroll
    for (int nf = 0; nf < 8; nf++) {
        int col = h * DH_ + nf * 8 + qd * 2;
        *(__half2*)(outh + rowA * D_ + col) = __halves2half2(
            __float2half_rn(O[nf][0] * rl_a), __float2half_rn(O[nf][1] * rl_a));
        *(__half2*)(outh + rowB * D_ + col) = __halves2half2(
            __float2half_rn(O[nf][2] * rl_b), __float2half_rn(O[nf][3] * rl_b));
    }
}

// ---------------- head ----------------
__global__ void head_kernel(const float* __restrict__ xn, const int* __restrict__ lastidx,
                            const float* __restrict__ hw, const float* __restrict__ hb,
                            float* __restrict__ out) {
    int b = blockIdx.x;
    int w = threadIdx.x >> 5;
    int lane = threadIdx.x & 31;
    const float* h = xn + ((size_t)(b * T_ + lastidx[b])) * D_;
    float s = 0.f;
    for (int d = lane; d < D_; d += 32) s += h[d] * hw[d * 9 + w];
    #pragma unroll
    for (int o = 16; o; o >>= 1) s += __shfl_down_sync(0xffffffffu, s, o);
    if (lane == 0) out[b * 9 + w] = s + hb[w];
}

// ---------------- orchestration ----------------
extern "C" void kernel_launch(void* const* d_in, const int* in_sizes, int n_in,
                              void* d_out, int out_size) {
    const int*   cards   = (const int*)  d_in[0];
    const int*   players = (const int*)  d_in[1];
    const int*   deck    = (const int*)  d_in[2];
    const int*   opp     = (const int*)  d_in[3];
    const float* tok     = (const float*)d_in[4];
    const float* pemb    = (const float*)d_in[5];
    const float* pos     = (const float*)d_in[6];
    const float* ln1s = (const float*)d_in[9];
    const float* ln1b = (const float*)d_in[10];
    const float* qkvw = (const float*)d_in[11];
    const float* qkvb = (const float*)d_in[12];
    const float* projw = (const float*)d_in[13];
    const float* projb = (const float*)d_in[14];
    const float* ln2s = (const float*)d_in[15];
    const float* ln2b = (const float*)d_in[16];
    const float* fc1w = (const float*)d_in[17];
    const float* fc1b = (const float*)d_in[18];
    const float* fc2w = (const float*)d_in[19];
    const float* fc2b = (const float*)d_in[20];
    const float* lnfs = (const float*)d_in[21];
    const float* lnfb = (const float*)d_in[22];
    const float* headw = (const float*)d_in[23];
    const float* headb = (const float*)d_in[24];

    float *x, *xn, *dm;
    f16 *qkv, *xh, *yh, *hh;
    f16 *qT, *pT, *f1T, *f2T;
    char* mask; int* lastidx;
    cudaGetSymbolAddress((void**)&x,    g_x);
    cudaGetSymbolAddress((void**)&xn,   g_xn);
    cudaGetSymbolAddress((void**)&qkv,  g_qkv);
    cudaGetSymbolAddress((void**)&dm,   g_dm);
    cudaGetSymbolAddress((void**)&xh,   g_xh);
    cudaGetSymbolAddress((void**)&yh,   g_yh);
    cudaGetSymbolAddress((void**)&hh,   g_hh);
    cudaGetSymbolAddress((void**)&qT,   g_qkvT);
    cudaGetSymbolAddress((void**)&pT,   g_projT);
    cudaGetSymbolAddress((void**)&f1T,  g_fc1T);
    cudaGetSymbolAddress((void**)&f2T,  g_fc2T);
    cudaGetSymbolAddress((void**)&mask, g_mask);
    cudaGetSymbolAddress((void**)&lastidx, g_lastidx);

    cudaFuncSetAttribute((const void*)gemm_mma<0, 256>,
                         cudaFuncAttributeMaxDynamicSharedMemorySize, GCfg<256>::SMEM);
    cudaFuncSetAttribute((const void*)gemm_mma<1, 128>,
                         cudaFuncAttributeMaxDynamicSharedMemorySize, GCfg<128>::SMEM);
    cudaFuncSetAttribute((const void*)gemm_mma<2, 128>,
                         cudaFuncAttributeMaxDynamicSharedMemorySize, GCfg<128>::SMEM);

    dim3 tb(32, 8);
    transpose_all<<<TFC2, tb>>>(qkvw, projw, fc1w, fc2w, qT, pT, f1T, f2T);
    mask_kernel<<<B_, T_>>>(cards, mask, lastidx);
    deckmean_kernel<<<B_, D_>>>(deck, opp, tok, dm);
    embed_kernel<<<BT_, 256>>>(cards, players, tok, pemb, pos, dm, x);

    for (int i = 0; i < L_; i++) {
        ln_kernel<true><<<BT_, 256>>>(x, ln1s + i * D_, ln1b + i * D_, nullptr, xh);
        gemm_mma<0, 256><<<dim3(D3_ / 256, BT_ / 128), 256, GCfg<256>::SMEM>>>(
            xh, qT + (size_t)i * D3_ * D_,
            qkvb + i * D3_, nullptr, nullptr, qkv, D_, D3_);
        attn_kernel<<<dim3(T_ / 64, NH_, B_), 128>>>(qkv, mask, yh);
        gemm_mma<2, 128><<<dim3(D_ / 128, BT_ / 128), 256, GCfg<128>::SMEM>>>(
            yh, pT + (size_t)i * D_ * D_,
            projb + i * D_, x, x, nullptr, D_, D_);
        ln_kernel<true><<<BT_, 256>>>(x, ln2s + i * D_, ln2b + i * D_, nullptr, xh);
        gemm_mma<1, 128><<<dim3(D4_ / 128, BT_ / 128), 256, GCfg<128>::SMEM>>>(
            xh, f1T + (size_t)i * D4_ * D_,
            fc1b + i * D4_, nullptr, nullptr, hh, D_, D4_);
        gemm_mma<2, 128><<<dim3(D_ / 128, BT_ / 128), 256, GCfg<128>::SMEM>>>(
            hh, f2T + (size_t)i * D_ * D4_,
            fc2b + i * D_, x, x, nullptr, D4_, D_);
    }

    ln_kernel<false><<<BT_, 256>>>(x, lnfs, lnfb, xn, nullptr);
    head_kernel<<<B_, 288>>>(xn, lastidx, headw, headb, (float*)d_out);
}

// round 13
// speedup vs baseline: 4.0533x; 1.1532x over previous
#include <cuda_runtime.h>
#include <cuda_fp16.h>
#include <math.h>
#include <stdint.h>

typedef __half f16;

// ---------------- problem constants ----------------
#define L_   6
#define D_   768
#define NH_  12
#define DH_  64
#define T_   512
#define B_   16
#define BT_  (B_ * T_)       // 8192
#define D3_  (3 * D_)        // 2304
#define D4_  (4 * D_)        // 3072

// ---------------- scratch ----------------
__device__ __align__(128) float g_x  [BT_ * D_];
__device__ __align__(128) float g_xn [BT_ * D_];
__device__ __align__(128) f16   g_qkv[BT_ * D3_];
__device__ __align__(128) f16   g_xh [BT_ * D_];
__device__ __align__(128) f16   g_yh [BT_ * D_];
__device__ __align__(128) f16   g_hh [BT_ * D4_];
__device__ __align__(128) float g_dm [B_ * D_];
__device__ char  g_mask[B_ * T_];
__device__ int   g_lastidx[B_];

__device__ __align__(128) f16 g_qkvT [L_ * D3_ * D_];
__device__ __align__(128) f16 g_projT[L_ * D_ * D_];
__device__ __align__(128) f16 g_fc1T [L_ * D4_ * D_];
__device__ __align__(128) f16 g_fc2T [L_ * D_ * D4_];

// ---------------- PTX helpers ----------------
__device__ __forceinline__ uint32_t smem_u32(const void* p) {
    uint32_t a;
    asm("{ .reg .u64 t; cvta.to.shared.u64 t, %1; cvt.u32.u64 %0, t; }" : "=r"(a) : "l"(p));
    return a;
}
__device__ __forceinline__ void cp16(uint32_t s, const void* g) {
    asm volatile("cp.async.cg.shared.global [%0], [%1], 16;" :: "r"(s), "l"(g) : "memory");
}
__device__ __forceinline__ void ldsm4(uint32_t* r, uint32_t addr) {
    asm volatile("ldmatrix.sync.aligned.m8n8.x4.shared.b16 {%0,%1,%2,%3}, [%4];"
                 : "=r"(r[0]), "=r"(r[1]), "=r"(r[2]), "=r"(r[3]) : "r"(addr));
}
__device__ __forceinline__ void mma16816(float* c, const uint32_t* a, const uint32_t* b) {
    asm volatile(
        "mma.sync.aligned.m16n8k16.row.col.f32.f16.f16.f32 "
        "{%0,%1,%2,%3}, {%4,%5,%6,%7}, {%8,%9}, {%0,%1,%2,%3};"
        : "+f"(c[0]), "+f"(c[1]), "+f"(c[2]), "+f"(c[3])
        : "r"(a[0]), "r"(a[1]), "r"(a[2]), "r"(a[3]), "r"(b[0]), "r"(b[1]));
}
__device__ __forceinline__ float gelu_exact(float v) {
    return 0.5f * v * (1.0f + erff(v * 0.70710678118654752440f));
}
__device__ __forceinline__ uint32_t pack_h2(f16 a, f16 b) {
    __half2 t = __halves2half2(a, b);
    return *(uint32_t*)&t;
}

// ---------------- fused weight transpose + fp16 round ----------------
#define TQKV (L_ * 1728)
#define TPROJ (TQKV + L_ * 576)
#define TFC1 (TPROJ + L_ * 2304)
#define TFC2 (TFC1 + L_ * 2304)

__global__ void transpose_all(const float* __restrict__ qkvw, const float* __restrict__ projw,
                              const float* __restrict__ fc1w, const float* __restrict__ fc2w,
                              f16* __restrict__ qT, f16* __restrict__ pT,
                              f16* __restrict__ f1T, f16* __restrict__ f2T) {
    __shared__ float tile[32][33];
    int idx = blockIdx.x;
    const float* W; f16* Th; int K, N, rem;
    if (idx < TQKV) {
        int layer = idx / 1728; rem = idx % 1728;
        K = D_; N = D3_;
        W = qkvw + (size_t)layer * D_ * D3_;
        Th = qT + (size_t)layer * D3_ * D_;
    } else if (idx < TPROJ) {
        idx -= TQKV;
        int layer = idx / 576; rem = idx % 576;
        K = D_; N = D_;
        W = projw + (size_t)layer * D_ * D_;
        Th = pT + (size_t)layer * D_ * D_;
    } else if (idx < TFC1) {
        idx -= TPROJ;
        int layer = idx / 2304; rem = idx % 2304;
        K = D_; N = D4_;
        W = fc1w + (size_t)layer * D_ * D4_;
        Th = f1T + (size_t)layer * D4_ * D_;
    } else {
        idx -= TFC1;
        int layer = idx / 2304; rem = idx % 2304;
        K = D4_; N = D_;
        W = fc2w + (size_t)layer * D4_ * D_;
        Th = f2T + (size_t)layer * D_ * D4_;
    }
    int tilesN = N >> 5;
    int n0 = (rem % tilesN) << 5;
    int k0 = (rem / tilesN) << 5;
    int tx = threadIdx.x, ty = threadIdx.y;
    #pragma unroll
    for (int i = 0; i < 32; i += 8)
        tile[ty + i][tx] = W[(size_t)(k0 + ty + i) * N + n0 + tx];
    __syncthreads();
    #pragma unroll
    for (int i = 0; i < 32; i += 8) {
        float v = tile[tx][ty + i];
        Th[(size_t)(n0 + ty + i) * K + k0 + tx] = __float2half_rn(v);
    }
}

// ---------------- mask + last_idx ----------------
__global__ void mask_kernel(const int* __restrict__ cards,
                            char* __restrict__ mask, int* __restrict__ lastidx) {
    int b = blockIdx.x;
    int t = threadIdx.x;
    bool valid = cards[b * T_ + t] != 0;
    bool any = __syncthreads_or(valid);
    bool m = valid || (t == 0 && !any);
    mask[b * T_ + t] = m ? 1 : 0;
    int cnt = __syncthreads_count(m);
    if (t == 0) lastidx[b] = (cnt - 1) > 0 ? (cnt - 1) : 0;
}

// ---------------- deck means ----------------
__global__ void deckmean_kernel(const int* __restrict__ deck, const int* __restrict__ opp,
                                const float* __restrict__ tok, float* __restrict__ dm) {
    int b = blockIdx.x;
    int d = threadIdx.x;
    float s = 0.f;
    #pragma unroll
    for (int i = 0; i < 8; i++) {
        s += tok[(size_t)deck[b * 8 + i] * D_ + d];
        s += tok[(size_t)opp [b * 8 + i] * D_ + d];
    }
    dm[b * D_ + d] = s * 0.125f;
}

// ---------------- embedding sum ----------------
__global__ void embed_kernel(const int* __restrict__ cards, const int* __restrict__ players,
                             const float* __restrict__ tok, const float* __restrict__ pemb,
                             const float* __restrict__ pos, const float* __restrict__ dm,
                             float* __restrict__ x) {
    int bt = blockIdx.x;
    int b = bt >> 9;
    int t = bt & 511;
    int card = cards[bt];
    int pl = players[bt]; pl = pl < 0 ? 0 : (pl > 1 ? 1 : pl);
    const float* tr = tok  + (size_t)card * D_;
    const float* pr = pemb + (size_t)pl * D_;
    const float* qr = pos  + (size_t)t * D_;
    const float* mr = dm   + (size_t)b * D_;
    float* xr = x + (size_t)bt * D_;
    for (int d = threadIdx.x; d < D_; d += 256)
        xr[d] = tr[d] + pr[d] + mr[d] + qr[d];
}

// ---------------- layernorm (float4), 256 thr / row, 192 active loaders ------------
template<bool TOH>
__global__ void ln_kernel(const float* __restrict__ x, const float* __restrict__ g,
                          const float* __restrict__ be, float* __restrict__ of,
                          f16* __restrict__ oh) {
    __shared__ float sh1[8], sh2[8];
    int r = blockIdx.x;
    size_t base = (size_t)r * D_;
    int t = threadIdx.x;
    float4 v = make_float4(0.f, 0.f, 0.f, 0.f);
    if (t < 192) v = *(const float4*)(x + base + 4 * t);
    float s = v.x + v.y + v.z + v.w;
    float q = v.x * v.x + v.y * v.y + v.z * v.z + v.w * v.w;
    #pragma unroll
    for (int o2 = 16; o2; o2 >>= 1) {
        s += __shfl_xor_sync(0xffffffffu, s, o2);
        q += __shfl_xor_sync(0xffffffffu, q, o2);
    }
    if ((t & 31) == 0) { sh1[t >> 5] = s; sh2[t >> 5] = q; }
    __syncthreads();
    s = sh1[t & 7]; q = sh2[t & 7];
    #pragma unroll
    for (int o2 = 4; o2; o2 >>= 1) {
        s += __shfl_xor_sync(0xffffffffu, s, o2);
        q += __shfl_xor_sync(0xffffffffu, q, o2);
    }
    float mean = s * (1.0f / D_);
    float var  = q * (1.0f / D_) - mean * mean;
    float rstd = rsqrtf(var + 1e-5f);
    if (t < 192) {
        int d = 4 * t;
        float4 gv = *(const float4*)(g + d);
        float4 bv = *(const float4*)(be + d);
        float o0 = (v.x - mean) * rstd * gv.x + bv.x;
        float o1 = (v.y - mean) * rstd * gv.y + bv.y;
        float o2_ = (v.z - mean) * rstd * gv.z + bv.z;
        float o3 = (v.w - mean) * rstd * gv.w + bv.w;
        if (TOH) {
            __half2 h0 = __halves2half2(__float2half_rn(o0), __float2half_rn(o1));
            __half2 h1 = __halves2half2(__float2half_rn(o2_), __float2half_rn(o3));
            uint2 pk; pk.x = *(uint32_t*)&h0; pk.y = *(uint32_t*)&h1;
            *(uint2*)(oh + base + d) = pk;
        } else {
            *(float4*)(of + base + d) = make_float4(o0, o1, o2_, o3);
        }
    }
}

// ---------------- mma.sync fp16 GEMM, 128xBN tiles, 4-stage ring, 1 sync/kt --------
// EPI: 0 = bias -> f16; 1 = bias+gelu -> f16; 2 = bias+residual -> fp32
#define ROWB 80
template<int BN> struct GCfg {
    static constexpr int A_OFF = 0;
    static constexpr int B_OFF = 128 * ROWB;
    static constexpr int STAGE = (128 + BN) * ROWB;
    static constexpr int SMEM  = 4 * STAGE;
    static constexpr int NF    = BN / 32;
    static constexpr int NPW   = BN / 4;
};

template<int EPI, int BN>
__global__ __launch_bounds__(256, 1)
void gemm_mma(const f16* __restrict__ Ah, const f16* __restrict__ Bh,
              const float* __restrict__ bias, const float* __restrict__ res,
              float* __restrict__ outf, f16* __restrict__ outh,
              int K, int Nfull) {
    using C = GCfg<BN>;
    extern __shared__ char dsm[];
    uint32_t tiles = smem_u32(dsm);

    int tid = threadIdx.x;
    int wid = tid >> 5;
    int lane = tid & 31;
    int warp_m = wid & 1;
    int warp_n = wid >> 1;
    int m0 = blockIdx.y * 128;
    int n0 = blockIdx.x * BN;
    int nt = K >> 5;

    int aRow  = lane & 15;
    int aColB = (lane >> 4) << 4;
    int bRow  = (lane & 7) + ((lane & 16) >> 1);
    int bColB = (lane & 8) << 1;

    float acc[4][C::NF][4];
    #pragma unroll
    for (int mt = 0; mt < 4; mt++)
        #pragma unroll
        for (int ntl = 0; ntl < C::NF; ntl++)
            #pragma unroll
            for (int r = 0; r < 4; r++) acc[mt][ntl][r] = 0.f;

    auto load_stage = [&](int kt, int st) {
        uint32_t sb = tiles + st * C::STAGE;
        int k0 = kt << 5;
        #pragma unroll
        for (int i = 0; i < 2; i++) {
            int id = tid + (i << 8);
            int r = id >> 2, c = id & 3;
            size_t go = (size_t)(m0 + r) * K + k0 + (c << 3);
            cp16(sb + C::A_OFF + r * ROWB + (c << 4), Ah + go);
        }
        #pragma unroll
        for (int i = 0; i < BN / 64; i++) {
            int id = tid + (i << 8);
            int r = id >> 2, c = id & 3;
            size_t go = (size_t)(n0 + r) * K + k0 + (c << 3);
            cp16(sb + C::B_OFF + r * ROWB + (c << 4), Bh + go);
        }
        asm volatile("cp.async.commit_group;" ::: "memory");
    };

    // prefetch distance 2: stages kt, kt+1 in flight before iter kt
    load_stage(0, 0);
    load_stage(1, 1);

    uint32_t aH[16], bH[2 * C::NF];

    for (int kt = 0; kt < nt; kt++) {
        int cur = kt & 3;
        // issue load for kt+2 into stage (kt+2)&3 (last read at iter kt-2; all warps
        // passed sync(kt-1), so every reader of that stage is done -> safe)
        if (kt + 2 < nt) {
            load_stage(kt + 2, (kt + 2) & 3);
            asm volatile("cp.async.wait_group 2;" ::: "memory");   // group kt done
        } else if (kt + 1 < nt) {
            asm volatile("cp.async.wait_group 1;" ::: "memory");
        } else {
            asm volatile("cp.async.wait_group 0;" ::: "memory");
        }
        __syncthreads();   // single barrier: publishes group-kt data + orders stage reuse

        uint32_t sb = tiles + cur * C::STAGE;
        uint32_t aBase = sb + (warp_m * 64 + aRow) * ROWB + aColB;
        uint32_t bBase = sb + C::B_OFF + (warp_n * C::NPW + bRow) * ROWB + bColB;

        #pragma unroll
        for (int ks = 0; ks < 2; ks++) {
            uint32_t kb = ks << 5;
            #pragma unroll
            for (int mt = 0; mt < 4; mt++)
                ldsm4(&aH[4 * mt], aBase + mt * (16 * ROWB) + kb);
            #pragma unroll
            for (int p = 0; p < BN / 64; p++)
                ldsm4(&bH[4 * p], bBase + p * (16 * ROWB) + kb);
            #pragma unroll
            for (int mt = 0; mt < 4; mt++)
                #pragma unroll
                for (int ntl = 0; ntl < C::NF; ntl++)
                    mma16816(acc[mt][ntl], &aH[4 * mt], &bH[2 * ntl]);
        }
    }

    int m_base = m0 + warp_m * 64 + (lane >> 2);
    int n_base = n0 + warp_n * C::NPW + ((lane & 3) << 1);
    #pragma unroll
    for (int mt = 0; mt < 4; mt++) {
        #pragma unroll
        for (int ntl = 0; ntl < C::NF; ntl++) {
            int n = n_base + ntl * 8;
            float b0 = bias[n], b1 = bias[n + 1];
            #pragma unroll
            for (int rr = 0; rr < 2; rr++) {
                int m = m_base + mt * 16 + rr * 8;
                size_t ob = (size_t)m * Nfull + n;
                float v0 = acc[mt][ntl][2 * rr]     + b0;
                float v1 = acc[mt][ntl][2 * rr + 1] + b1;
                if (EPI == 0) {
                    *(__half2*)(outh + ob) =
                        __halves2half2(__float2half_rn(v0), __float2half_rn(v1));
                } else if (EPI == 2) {
                    float2 rv = *(const float2*)(res + ob);
                    *(float2*)(outf + ob) = make_float2(v0 + rv.x, v1 + rv.y);
                } else {
                    float g0 = gelu_exact(v0), g1 = gelu_exact(v1);
                    *(__half2*)(outh + ob) =
                        __halves2half2(__float2half_rn(g0), __float2half_rn(g1));
                }
            }
        }
    }
}

// ---------------- tensor-core flash attention (fp16 qkv in, fp32 softmax) ----------
#define QSTR 72
#define VSTR 40

__global__ __launch_bounds__(128)
void attn_kernel(const f16* __restrict__ qkv, const char* __restrict__ mask,
                 f16* __restrict__ outh) {
    __shared__ f16 sQ[64 * QSTR];
    __shared__ f16 sK[32 * QSTR];
    __shared__ f16 sV[64 * VSTR];    // V^T: [dim][key]
    __shared__ char Ms[32];

    int qt = blockIdx.x, h = blockIdx.y, b = blockIdx.z;
    int tid = threadIdx.x;
    int wid = tid >> 5, lane = tid & 31;
    int grp = lane >> 2, qd = lane & 3;

    {
        int row = tid >> 1;
        int c0 = (tid & 1) * 32;
        const f16* g = qkv + ((size_t)(b * T_ + qt * 64 + row)) * D3_ + h * DH_ + c0;
        __half2 sc = __half2half2(__float2half(0.125f));
        #pragma unroll
        for (int u = 0; u < 16; u++) {
            __half2 v = *(const __half2*)(g + 2 * u);
            *(__half2*)&sQ[row * QSTR + c0 + 2 * u] = __hmul2(v, sc);
        }
    }

    float O[8][4];
    #pragma unroll
    for (int nf = 0; nf < 8; nf++)
        #pragma unroll
        for (int r = 0; r < 4; r++) O[nf][r] = 0.f;
    float m_a = -INFINITY, m_b = -INFINITY, l_a = 0.f, l_b = 0.f;

    uint32_t aAddr = smem_u32(sQ) + (wid * 16 + (lane & 15)) * (QSTR * 2) + ((lane >> 4) << 4);
    int bRow  = (lane & 7) + ((lane & 16) >> 1);
    int bColB = (lane & 8) << 1;
    uint32_t kAddr = smem_u32(sK) + bRow * (QSTR * 2) + bColB;
    uint32_t vAddr = smem_u32(sV) + bRow * (VSTR * 2) + bColB;

    int q_a = qt * 64 + wid * 16 + grp;
    int q_b = q_a + 8;

    int ktmax = (qt + 1) * 2;
    for (int kt = 0; kt < ktmax; kt++) {
        __syncthreads();
        {
            int j  = tid >> 2;
            int d0 = (tid & 3) * 16;
            const f16* gk = qkv + ((size_t)(b * T_ + kt * 32 + j)) * D3_ + D_ + h * DH_ + d0;
            const f16* gv = gk + D_;
            #pragma unroll
            for (int u = 0; u < 2; u++)
                *(uint4*)&sK[j * QSTR + d0 + u * 8] = *(const uint4*)(gk + u * 8);
            #pragma unroll
            for (int u = 0; u < 8; u++) {
                __half2 v = *(const __half2*)(gv + 2 * u);
                int d = d0 + 2 * u;
                sV[(d + 0) * VSTR + j] = __low2half(v);
                sV[(d + 1) * VSTR + j] = __high2half(v);
            }
            if (tid < 32) Ms[tid] = mask[b * T_ + kt * 32 + tid];
        }
        __syncthreads();

        float S[4][4];
        #pragma unroll
        for (int f = 0; f < 4; f++)
            #pragma unroll
            for (int r = 0; r < 4; r++) S[f][r] = 0.f;
        #pragma unroll
        for (int kc = 0; kc < 4; kc++) {
            uint32_t q[4], kf[8];
            ldsm4(q, aAddr + kc * 32);
            ldsm4(&kf[0], kAddr + kc * 32);
            ldsm4(&kf[4], kAddr + 16 * (QSTR * 2) + kc * 32);
            #pragma unroll
            for (int f = 0; f < 4; f++)
                mma16816(S[f], q, &kf[2 * f]);
        }

        float mt_a = -INFINITY, mt_b = -INFINITY;
        #pragma unroll
        for (int f = 0; f < 4; f++) {
            int ci = f * 8 + qd * 2;
            int gk0 = kt * 32 + ci, gk1 = gk0 + 1;
            bool ok0 = Ms[ci] != 0, ok1 = Ms[ci + 1] != 0;
            S[f][0] = (ok0 && gk0 <= q_a) ? S[f][0] : -INFINITY;
            S[f][1] = (ok1 && gk1 <= q_a) ? S[f][1] : -INFINITY;
            S[f][2] = (ok0 && gk0 <= q_b) ? S[f][2] : -INFINITY;
            S[f][3] = (ok1 && gk1 <= q_b) ? S[f][3] : -INFINITY;
            mt_a = fmaxf(mt_a, fmaxf(S[f][0], S[f][1]));
            mt_b = fmaxf(mt_b, fmaxf(S[f][2], S[f][3]));
        }
        mt_a = fmaxf(mt_a, __shfl_xor_sync(0xffffffffu, mt_a, 1));
        mt_a = fmaxf(mt_a, __shfl_xor_sync(0xffffffffu, mt_a, 2));
        mt_b = fmaxf(mt_b, __shfl_xor_sync(0xffffffffu, mt_b, 1));
        mt_b = fmaxf(mt_b, __shfl_xor_sync(0xffffffffu, mt_b, 2));
        float mn_a = fmaxf(m_a, mt_a), mn_b = fmaxf(m_b, mt_b);
        float al_a, al_b, ps_a = 0.f, ps_b = 0.f;
        if (mn_a == -INFINITY) {
            al_a = 1.f;
            #pragma unroll
            for (int f = 0; f < 4; f++) { S[f][0] = 0.f; S[f][1] = 0.f; }
        } else {
            al_a = expf(m_a - mn_a);
            #pragma unroll
            for (int f = 0; f < 4; f++) {
                S[f][0] = expf(S[f][0] - mn_a);
                S[f][1] = expf(S[f][1] - mn_a);
                ps_a += S[f][0] + S[f][1];
            }
        }
        if (mn_b == -INFINITY) {
            al_b = 1.f;
            #pragma unroll
            for (int f = 0; f < 4; f++) { S[f][2] = 0.f; S[f][3] = 0.f; }
        } else {
            al_b = expf(m_b - mn_b);
            #pragma unroll
            for (int f = 0; f < 4; f++) {
                S[f][2] = expf(S[f][2] - mn_b);
                S[f][3] = expf(S[f][3] - mn_b);
                ps_b += S[f][2] + S[f][3];
            }
        }
        ps_a += __shfl_xor_sync(0xffffffffu, ps_a, 1);
        ps_a += __shfl_xor_sync(0xffffffffu, ps_a, 2);
        ps_b += __shfl_xor_sync(0xffffffffu, ps_b, 1);
        ps_b += __shfl_xor_sync(0xffffffffu, ps_b, 2);
        l_a = l_a * al_a + ps_a;
        l_b = l_b * al_b + ps_b;
        m_a = mn_a; m_b = mn_b;
        #pragma unroll
        for (int nf = 0; nf < 8; nf++) {
            O[nf][0] *= al_a; O[nf][1] *= al_a;
            O[nf][2] *= al_b; O[nf][3] *= al_b;
        }

        #pragma unroll
        for (int kc = 0; kc < 2; kc++) {
            int f0 = 2 * kc, f1 = 2 * kc + 1;
            uint32_t pa[4];
            pa[0] = pack_h2(__float2half_rn(S[f0][0]), __float2half_rn(S[f0][1]));
            pa[1] = pack_h2(__float2half_rn(S[f0][2]), __float2half_rn(S[f0][3]));
            pa[2] = pack_h2(__float2half_rn(S[f1][0]), __float2half_rn(S[f1][1]));
            pa[3] = pack_h2(__float2half_rn(S[f1][2]), __float2half_rn(S[f1][3]));
            uint32_t vf[16];
            #pragma unroll
            for (int p4 = 0; p4 < 4; p4++)
                ldsm4(&vf[4 * p4], vAddr + p4 * 16 * (VSTR * 2) + kc * 32);
            #pragma unroll
            for (int nf = 0; nf < 8; nf++)
                mma16816(O[nf], pa, &vf[2 * nf]);
        }
    }

    float rl_a = (l_a > 0.f) ? (1.f / l_a) : 0.f;
    float rl_b = (l_b > 0.f) ? (1.f / l_b) : 0.f;
    size_t rowA = (size_t)(b * T_) + qt * 64 + wid * 16 + grp;
    size_t rowB = rowA + 8;
    #pragma unroll
    for (int nf = 0; nf < 8; nf++) {
        int col = h * DH_ + nf * 8 + qd * 2;
        *(__half2*)(outh + rowA * D_ + col) = __halves2half2(
            __float2half_rn(O[nf][0] * rl_a), __float2half_rn(O[nf][1] * rl_a));
        *(__half2*)(outh + rowB * D_ + col) = __halves2half2(
            __float2half_rn(O[nf][2] * rl_b), __float2half_rn(O[nf][3] * rl_b));
    }
}

// ---------------- head ----------------
__global__ void head_kernel(const float* __restrict__ xn, const int* __restrict__ lastidx,
                            const float* __restrict__ hw, const float* __restrict__ hb,
                            float* __restrict__ out) {
    int b = blockIdx.x;
    int w = threadIdx.x >> 5;
    int lane = threadIdx.x & 31;
    const float* h = xn + ((size_t)(b * T_ + lastidx[b])) * D_;
    float s = 0.f;
    for (int d = lane; d < D_; d += 32) s += h[d] * hw[d * 9 + w];
    #pragma unroll
    for (int o = 16; o; o >>= 1) s += __shfl_down_sync(0xffffffffu, s, o);
    if (lane == 0) out[b * 9 + w] = s + hb[w];
}

// ---------------- orchestration ----------------
extern "C" void kernel_launch(void* const* d_in, const int* in_sizes, int n_in,
                              void* d_out, int out_size) {
    const int*   cards   = (const int*)  d_in[0];
    const int*   players = (const int*)  d_in[1];
    const int*   deck    = (const int*)  d_in[2];
    const int*   opp     = (const int*)  d_in[3];
    const float* tok     = (const float*)d_in[4];
    const float* pemb    = (const float*)d_in[5];
    const float* pos     = (const float*)d_in[6];
    const float* ln1s = (const float*)d_in[9];
    const float* ln1b = (const float*)d_in[10];
    const float* qkvw = (const float*)d_in[11];
    const float* qkvb = (const float*)d_in[12];
    const float* projw = (const float*)d_in[13];
    const float* projb = (const float*)d_in[14];
    const float* ln2s = (const float*)d_in[15];
    const float* ln2b = (const float*)d_in[16];
    const float* fc1w = (const float*)d_in[17];
    const float* fc1b = (const float*)d_in[18];
    const float* fc2w = (const float*)d_in[19];
    const float* fc2b = (const float*)d_in[20];
    const float* lnfs = (const float*)d_in[21];
    const float* lnfb = (const float*)d_in[22];
    const float* headw = (const float*)d_in[23];
    const float* headb = (const float*)d_in[24];

    float *x, *xn, *dm;
    f16 *qkv, *xh, *yh, *hh;
    f16 *qT, *pT, *f1T, *f2T;
    char* mask; int* lastidx;
    cudaGetSymbolAddress((void**)&x,    g_x);
    cudaGetSymbolAddress((void**)&xn,   g_xn);
    cudaGetSymbolAddress((void**)&qkv,  g_qkv);
    cudaGetSymbolAddress((void**)&dm,   g_dm);
    cudaGetSymbolAddress((void**)&xh,   g_xh);
    cudaGetSymbolAddress((void**)&yh,   g_yh);
    cudaGetSymbolAddress((void**)&hh,   g_hh);
    cudaGetSymbolAddress((void**)&qT,   g_qkvT);
    cudaGetSymbolAddress((void**)&pT,   g_projT);
    cudaGetSymbolAddress((void**)&f1T,  g_fc1T);
    cudaGetSymbolAddress((void**)&f2T,  g_fc2T);
    cudaGetSymbolAddress((void**)&mask, g_mask);
    cudaGetSymbolAddress((void**)&lastidx, g_lastidx);

    cudaFuncSetAttribute((const void*)gemm_mma<0, 256>,
                         cudaFuncAttributeMaxDynamicSharedMemorySize, GCfg<256>::SMEM);
    cudaFuncSetAttribute((const void*)gemm_mma<1, 128>,
                         cudaFuncAttributeMaxDynamicSharedMemorySize, GCfg<128>::SMEM);
    cudaFuncSetAttribute((const void*)gemm_mma<2, 128>,
                         cudaFuncAttributeMaxDynamicSharedMemorySize, GCfg<128>::SMEM);

    dim3 tb(32, 8);
    transpose_all<<<TFC2, tb>>>(qkvw, projw, fc1w, fc2w, qT, pT, f1T, f2T);
    mask_kernel<<<B_, T_>>>(cards, mask, lastidx);
    deckmean_kernel<<<B_, D_>>>(deck, opp, tok, dm);
    embed_kernel<<<BT_, 256>>>(cards, players, tok, pemb, pos, dm, x);

    for (int i = 0; i < L_; i++) {
        ln_kernel<true><<<BT_, 256>>>(x, ln1s + i * D_, ln1b + i * D_, nullptr, xh);
        gemm_mma<0, 256><<<dim3(D3_ / 256, BT_ / 128), 256, GCfg<256>::SMEM>>>(
            xh, qT + (size_t)i * D3_ * D_,
            qkvb + i * D3_, nullptr, nullptr, qkv, D_, D3_);
        attn_kernel<<<dim3(T_ / 64, NH_, B_), 128>>>(qkv, mask, yh);
        gemm_mma<2, 128><<<dim3(D_ / 128, BT_ / 128), 256, GCfg<128>::SMEM>>>(
            yh, pT + (size_t)i * D_ * D_,
            projb + i * D_, x, x, nullptr, D_, D_);
        ln_kernel<true><<<BT_, 256>>>(x, ln2s + i * D_, ln2b + i * D_, nullptr, xh);
        gemm_mma<1, 128><<<dim3(D4_ / 128, BT_ / 128), 256, GCfg<128>::SMEM>>>(
            xh, f1T + (size_t)i * D4_ * D_,
            fc1b + i * D4_, nullptr, nullptr, hh, D_, D4_);
        gemm_mma<2, 128><<<dim3(D_ / 128, BT_ / 128), 256, GCfg<128>::SMEM>>>(
            hh, f2T + (size_t)i * D_ * D4_,
            fc2b + i * D_, x, x, nullptr, D4_, D_);
    }

    ln_kernel<false><<<BT_, 256>>>(x, lnfs, lnfb, xn, nullptr);
    head_kernel<<<B_, 288>>>(xn, lastidx, headw, headb, (float*)d_out);
}